// round 8
// baseline (speedup 1.0000x reference)
#include <cuda_runtime.h>
#include <cuda_bf16.h>
#include <cstdint>

// ---------------- problem constants ----------------
#define B_   64
#define V_   2048
#define K_   128
#define H_   128
#define N_   (B_*V_)
#define E_   1048576
#define CF_  47
#define L_   3
#define EPSF 1e-5f
#define SPLITV 4

// ---------------- scratch ----------------
__device__ float g_Y1[(size_t)E_*H_];
__device__ float g_Y2[(size_t)E_*2*H_];
__device__ float g_H [(size_t)N_*H_];
__device__ float g_HS[(size_t)B_*K_*H_];
__device__ float g_Ya[(size_t)N_*H_];
__device__ float g_Yb[(size_t)N_*H_];
__device__ float g_sum[256], g_sumsq[256], g_scale[256], g_shift[256];
__device__ __nv_bfloat16 w1s_hi[64*128],        w1s_lo[64*128];
__device__ __nv_bfloat16 w2s_hi[128*256],       w2s_lo[128*256];
__device__ __nv_bfloat16 pw1s_hi[3*256*128],    pw1s_lo[3*256*128];
__device__ __nv_bfloat16 pw2s_hi[3*128*128],    pw2s_lo[3*128*128];
__device__ __nv_bfloat16 wo1s_hi[128*128],      wo1s_lo[128*128];
__device__ __nv_bfloat16 g_evhi[(size_t)B_*V_*K_], g_evlo[(size_t)B_*V_*K_];
__device__ __nv_bfloat16 g_eihi[(size_t)B_*V_*K_], g_eilo[(size_t)B_*V_*K_];
__device__ __nv_bfloat16 g_hhi [(size_t)N_*H_],    g_hlo [(size_t)N_*H_];
__device__ __nv_bfloat16 g_Thi [(size_t)B_*K_*H_], g_Tlo [(size_t)B_*K_*H_];

// ---------------- helpers ----------------
__device__ __forceinline__ float siluf(float x){ return x * (1.f/(1.f+__expf(-x))); }
__device__ __forceinline__ float softplusf(float x){ return x > 20.f ? x : log1pf(__expf(x)); }
__device__ __forceinline__ void red_add_v4(float* a, float x, float y, float z, float w){
    asm volatile("red.global.add.v4.f32 [%0], {%1,%2,%3,%4};"
                 :: "l"(a), "f"(x), "f"(y), "f"(z), "f"(w) : "memory");
}
__device__ __forceinline__ void red_add_v2(float* a, float x, float y){
    asm volatile("red.global.add.v2.f32 [%0], {%1,%2};" :: "l"(a), "f"(x), "f"(y) : "memory");
}
__device__ __forceinline__ uint32_t smem_u32(const void* p){
    uint32_t a;
    asm("{ .reg .u64 t; cvta.to.shared.u64 t, %1; cvt.u32.u64 %0, t; }" : "=r"(a) : "l"(p));
    return a;
}
__device__ __forceinline__ void cpasync16(uint32_t s, const void* g){
    asm volatile("cp.async.ca.shared.global [%0], [%1], 16;" :: "r"(s), "l"(g));
}
#define CP_COMMIT() asm volatile("cp.async.commit_group;")
#define CP_WAIT0()  asm volatile("cp.async.wait_group 0;")

__device__ __forceinline__ void ldsm4(uint32_t* r, uint32_t addr){
    asm volatile("ldmatrix.sync.aligned.m8n8.x4.shared.b16 {%0,%1,%2,%3}, [%4];"
        : "=r"(r[0]),"=r"(r[1]),"=r"(r[2]),"=r"(r[3]) : "r"(addr));
}
__device__ __forceinline__ void ldsm4t(uint32_t* r, uint32_t addr){
    asm volatile("ldmatrix.sync.aligned.m8n8.x4.trans.shared.b16 {%0,%1,%2,%3}, [%4];"
        : "=r"(r[0]),"=r"(r[1]),"=r"(r[2]),"=r"(r[3]) : "r"(addr));
}
__device__ __forceinline__ void mma16816(float* d, const uint32_t* a, uint32_t b0, uint32_t b1){
    asm volatile("mma.sync.aligned.m16n8k16.row.col.f32.bf16.bf16.f32 "
        "{%0,%1,%2,%3}, {%4,%5,%6,%7}, {%8,%9}, {%0,%1,%2,%3};"
        : "+f"(d[0]),"+f"(d[1]),"+f"(d[2]),"+f"(d[3])
        : "r"(a[0]),"r"(a[1]),"r"(a[2]),"r"(a[3]), "r"(b0),"r"(b1));
}

__device__ __forceinline__ void split8(const float* f, uint4& hi, uint4& lo){
    unsigned h[4], l[4];
    #pragma unroll
    for (int p=0;p<4;p++){
        float2 a = make_float2(f[2*p], f[2*p+1]);
        __nv_bfloat162 bh = __float22bfloat162_rn(a);
        float hx = __bfloat162float(bh.x), hy = __bfloat162float(bh.y);
        float2 rz = make_float2(a.x - hx, a.y - hy);
        __nv_bfloat162 bl = __float22bfloat162_rn(rz);
        h[p] = *reinterpret_cast<unsigned*>(&bh);
        l[p] = *reinterpret_cast<unsigned*>(&bl);
    }
    hi = make_uint4(h[0],h[1],h[2],h[3]);
    lo = make_uint4(l[0],l[1],l[2],l[3]);
}
__device__ __forceinline__ void split1(float v, __nv_bfloat16& hi, __nv_bfloat16& lo){
    hi = __float2bfloat16_rn(v);
    lo = __float2bfloat16_rn(v - __bfloat162float(hi));
}
__device__ __forceinline__ void split2_store(__nv_bfloat16* phi, __nv_bfloat16* plo,
                                             float v0, float v1){
    __nv_bfloat162 h2 = __float22bfloat162_rn(make_float2(v0, v1));
    __nv_bfloat162 l2 = __float22bfloat162_rn(make_float2(
        v0-__bfloat162float(h2.x), v1-__bfloat162float(h2.y)));
    *reinterpret_cast<__nv_bfloat162*>(phi) = h2;
    *reinterpret_cast<__nv_bfloat162*>(plo) = l2;
}

__global__ void zero_kernel(float* __restrict__ p, size_t n){
    size_t i = (size_t)blockIdx.x*blockDim.x + threadIdx.x;
    if (i < n) p[i] = 0.f;
}
__global__ void zero_stats(){ g_sum[threadIdx.x]=0.f; g_sumsq[threadIdx.x]=0.f; }

// ---------------- prep: split kernels ----------------
__global__ void split_mat(const float* __restrict__ src, __nv_bfloat16* __restrict__ hi,
                          __nv_bfloat16* __restrict__ lo, size_t n){
    size_t i = (size_t)blockIdx.x*256 + threadIdx.x;
    if (i < n){ __nv_bfloat16 h, l; split1(src[i], h, l); hi[i]=h; lo[i]=l; }
}
__global__ void split_w1(const float* __restrict__ w1){
    int i = blockIdx.x*256 + threadIdx.x;
    int k = i >> 7, n = i & 127;
    float v = (k < CF_) ? w1[k*128 + n] : 0.f;
    __nv_bfloat16 h, l; split1(v, h, l);
    w1s_hi[i]=h; w1s_lo[i]=l;
}
__global__ void split_eigs_k(const float* __restrict__ eigs){
    size_t i = (size_t)blockIdx.x*256 + threadIdx.x;
    size_t b = i >> 18, rem = i & 0x3FFFF;
    const float* base = eigs + (b*(size_t)(2*V_+1) + 1)*K_;
    __nv_bfloat16 h, l;
    split1(base[rem], h, l);                 g_evhi[i]=h; g_evlo[i]=l;
    split1(base[(size_t)V_*K_ + rem], h, l); g_eihi[i]=h; g_eilo[i]=l;
}

// ================= pipelined HMMA split-bf16 GEMM (128-col) =================
// ASRC 0: A fp32 plain, guarded scalar loads
// ASRC 1: A fp32, silu(A*scale+shift)
// ASRC 3: A pre-split bf16
// ASRC 5: dual concat: kc<4 -> (Ahi/Alo @ Bhi/Blo); kc>=4 -> (evecs[batch] @ B2[batch])
// ASRC 6: A fp32 * exp(-eig[row]*t[col])  (coeff-fused T-gemm)
#define APITCH 80
#define BPITCH 272
#define SMBUF  37888
template<int ASRC, bool STATS, bool OUTSPLIT>
__global__ void __launch_bounds__(256,2) gemm5(
    const float* __restrict__ Af,
    const __nv_bfloat16* __restrict__ Ahi, const __nv_bfloat16* __restrict__ Alo,
    const __nv_bfloat16* __restrict__ A2hi, const __nv_bfloat16* __restrict__ A2lo,
    const __nv_bfloat16* __restrict__ Bhi, const __nv_bfloat16* __restrict__ Blo,
    const __nv_bfloat16* __restrict__ B2hi, const __nv_bfloat16* __restrict__ B2lo,
    const float* __restrict__ bias, float* __restrict__ C,
    __nv_bfloat16* __restrict__ Chi, __nv_bfloat16* __restrict__ Clo,
    int Kd, int Nd, int lda,
    size_t sAs, size_t sBs, size_t sC,
    const float* __restrict__ eigsp, const float* __restrict__ ptp, int lidx)
{
    extern __shared__ __align__(16) uint8_t smem[];
    const uint32_t sb = smem_u32(smem);
    const int tid = threadIdx.x;
    const int lane = tid & 31, wid = tid >> 5;
    const int warpm = wid & 3, warpn = wid >> 2;
    const int brow = blockIdx.y * 128;
    const int bcol = blockIdx.x * 128;
    const int bz   = blockIdx.z;
    Ahi += sAs*bz; Alo += sAs*bz; Bhi += sBs*bz; Blo += sBs*bz;
    if (ASRC == 6) Af += (size_t)K_*H_*bz;
    if (C)   C   += sC*bz;
    if (Chi){ Chi += sC*bz; Clo += sC*bz; }
    const int bb = brow >> 11;
    const size_t a2base = (size_t)bb*V_*K_ + (size_t)(brow & 2047)*K_;
    const size_t b2base = (size_t)bb*K_*H_;

    const int nch = (Kd + 31) >> 5;

    const int ar = tid >> 1, akh = (tid & 1) * 16;
    const int bkr = tid >> 3, bns = (tid & 7) * 16;

    auto stageB = [&](int kc, int buf){
        const __nv_bfloat16 *shi, *slo; size_t so;
        if (ASRC == 5 && kc >= 4){
            const int gk = (kc & 3)*32 + bkr;
            shi = B2hi + b2base; slo = B2lo + b2base;
            so = (size_t)gk*128 + bns;
        } else {
            const int gk = kc*32 + bkr;
            shi = Bhi; slo = Blo;
            so = (size_t)gk*Nd + bcol + bns;
        }
        const uint32_t dst = sb + buf*SMBUF + 20480 + bkr*BPITCH + bns*2;
        cpasync16(dst,             shi + so);
        cpasync16(dst + 16,        shi + so + 8);
        cpasync16(dst + 8704,      slo + so);
        cpasync16(dst + 8704 + 16, slo + so + 8);
    };
    auto stageA_async = [&](int kc, int buf){
        const __nv_bfloat16 *hi, *lo; size_t so;
        if (ASRC == 5){
            if (kc < 4){ hi = Ahi; lo = Alo; so = (size_t)(brow+ar)*128 + kc*32 + akh; }
            else { hi = A2hi + a2base; lo = A2lo + a2base;
                   so = (size_t)ar*K_ + (kc & 3)*32 + akh; }
        } else {
            hi = Ahi; lo = Alo;
            so = (size_t)(brow + ar)*lda + kc*32 + akh;
        }
        const uint32_t dst = sb + buf*SMBUF + ar*APITCH + akh*2;
        cpasync16(dst,              hi + so);
        cpasync16(dst + 16,         hi + so + 8);
        cpasync16(dst + 10240,      lo + so);
        cpasync16(dst + 10240 + 16, lo + so + 8);
    };
    auto loadA_f32 = [&](int kc, float* av){
        if (ASRC == 1 || ASRC == 6){
            const float* S = Af + (size_t)(brow+ar)*lda + kc*32 + akh;
            #pragma unroll
            for (int q=0;q<4;q++) *reinterpret_cast<float4*>(&av[q*4]) =
                *reinterpret_cast<const float4*>(S + q*4);
        } else {
            #pragma unroll
            for (int j=0;j<16;j++){
                const int k = kc*32 + akh + j;
                av[j] = (k < Kd) ? Af[(size_t)(brow+ar)*lda + k] : 0.f;
            }
        }
    };
    auto storeA_f32 = [&](int kc, int buf, float* av){
        if (ASRC == 1){
            #pragma unroll
            for (int j=0;j<16;j++){
                const int k = kc*32 + akh + j;
                av[j] = siluf(av[j]*g_scale[k] + g_shift[k]);
            }
        }
        if (ASRC == 6){
            const float eig_a = eigsp[(size_t)bz*(2*V_+1)*K_ + brow + ar];
            #pragma unroll
            for (int j=0;j<16;j++){
                const int k = kc*32 + akh + j;
                av[j] *= __expf(-eig_a * fmaxf(ptp[lidx*H_ + k], 1e-6f));
            }
        }
        uint4 h0,l0,h1,l1;
        split8(&av[0], h0, l0);
        split8(&av[8], h1, l1);
        uint8_t* base = smem + buf*SMBUF + ar*APITCH + akh*2;
        *reinterpret_cast<uint4*>(base)              = h0;
        *reinterpret_cast<uint4*>(base + 16)         = h1;
        *reinterpret_cast<uint4*>(base + 10240)      = l0;
        *reinterpret_cast<uint4*>(base + 10240 + 16) = l1;
    };

    constexpr bool A_F32 = (ASRC == 0) || (ASRC == 1) || (ASRC == 6);

    float d[2][8][4];
    #pragma unroll
    for (int i=0;i<2;i++)
        #pragma unroll
        for (int j=0;j<8;j++)
            #pragma unroll
            for (int q=0;q<4;q++) d[i][j][q] = 0.f;

    float av[16];
    stageB(0, 0);
    if (A_F32){ loadA_f32(0, av); storeA_f32(0, 0, av); }
    else       stageA_async(0, 0);
    CP_COMMIT();
    CP_WAIT0();
    __syncthreads();

    for (int kc = 0; kc < nch; kc++){
        const int cur = kc & 1, nxt = cur ^ 1;
        const bool more = (kc + 1 < nch);
        if (more){
            stageB(kc+1, nxt);
            if (!A_F32) stageA_async(kc+1, nxt);
            CP_COMMIT();
            if (A_F32) loadA_f32(kc+1, av);
        }
        const uint32_t aHi = sb + cur*SMBUF;
        const uint32_t aLo = aHi + 10240;
        const uint32_t bHi = aHi + 20480;
        const uint32_t bLo = aHi + 29184;
        #pragma unroll
        for (int ks=0; ks<2; ks++){
            if (kc*32 + ks*16 < Kd){    // skip all-zero K16 steps (GEMM1 tail)
                uint32_t ah[2][4], al[2][4];
                #pragma unroll
                for (int mb=0; mb<2; mb++){
                    const uint32_t ao = (uint32_t)(warpm*32 + mb*16 + (lane & 15))*APITCH
                                      + ks*32 + ((lane >> 4)*16);
                    ldsm4(ah[mb], aHi + ao);
                    ldsm4(al[mb], aLo + ao);
                }
                #pragma unroll
                for (int np=0; np<4; np++){
                    const int n0 = warpn*64 + np*16;
                    const uint32_t bo = (uint32_t)(ks*16 + (lane & 15))*BPITCH
                                      + (uint32_t)n0*2 + ((lane >> 4)*16);
                    uint32_t bh[4], bl[4];
                    ldsm4t(bh, bHi + bo);
                    ldsm4t(bl, bLo + bo);
                    #pragma unroll
                    for (int mb=0; mb<2; mb++){
                        mma16816(d[mb][np*2  ], ah[mb], bh[0], bh[1]);
                        mma16816(d[mb][np*2  ], al[mb], bh[0], bh[1]);
                        mma16816(d[mb][np*2  ], ah[mb], bl[0], bl[1]);
                        mma16816(d[mb][np*2+1], ah[mb], bh[2], bh[3]);
                        mma16816(d[mb][np*2+1], al[mb], bh[2], bh[3]);
                        mma16816(d[mb][np*2+1], ah[mb], bl[2], bl[3]);
                    }
                }
            }
        }
        if (more){
            if (A_F32) storeA_f32(kc+1, nxt, av);
            CP_WAIT0();
        }
        __syncthreads();
    }

    #pragma unroll
    for (int mb=0; mb<2; mb++){
        #pragma unroll
        for (int nb=0; nb<8; nb++){
            const int m = brow + warpm*32 + mb*16 + (lane >> 2);
            const int n = bcol + warpn*64 + nb*8 + (lane & 3)*2;
            float b0 = 0.f, b1 = 0.f;
            if (bias){ b0 = bias[n]; b1 = bias[n+1]; }
            d[mb][nb][0] += b0; d[mb][nb][1] += b1;
            d[mb][nb][2] += b0; d[mb][nb][3] += b1;
            if (OUTSPLIT){
                split2_store(Chi + (size_t)m*Nd + n, Clo + (size_t)m*Nd + n,
                             d[mb][nb][0], d[mb][nb][1]);
                split2_store(Chi + (size_t)(m+8)*Nd + n, Clo + (size_t)(m+8)*Nd + n,
                             d[mb][nb][2], d[mb][nb][3]);
            } else {
                *reinterpret_cast<float2*>(C + (size_t)m*Nd + n) =
                    make_float2(d[mb][nb][0], d[mb][nb][1]);
                *reinterpret_cast<float2*>(C + (size_t)(m+8)*Nd + n) =
                    make_float2(d[mb][nb][2], d[mb][nb][3]);
            }
        }
    }

    if (STATS){
        float* sred = reinterpret_cast<float*>(smem + 2*SMBUF);
        sred[tid] = 0.f;
        __syncthreads();
        float s[16], q[16];
        #pragma unroll
        for (int i=0;i<16;i++){ s[i]=0.f; q[i]=0.f; }
        #pragma unroll
        for (int mb=0; mb<2; mb++)
            #pragma unroll
            for (int nb=0; nb<8; nb++){
                s[nb*2+0] += d[mb][nb][0] + d[mb][nb][2];
                s[nb*2+1] += d[mb][nb][1] + d[mb][nb][3];
                q[nb*2+0] += d[mb][nb][0]*d[mb][nb][0] + d[mb][nb][2]*d[mb][nb][2];
                q[nb*2+1] += d[mb][nb][1]*d[mb][nb][1] + d[mb][nb][3]*d[mb][nb][3];
            }
        #pragma unroll
        for (int off=4; off<32; off<<=1){
            #pragma unroll
            for (int i=0;i<16;i++){
                s[i] += __shfl_xor_sync(0xFFFFFFFFu, s[i], off);
                q[i] += __shfl_xor_sync(0xFFFFFFFFu, q[i], off);
            }
        }
        if (lane < 4){
            #pragma unroll
            for (int i=0;i<16;i++){
                const int col = warpn*64 + (i>>1)*8 + (lane & 3)*2 + (i & 1);
                atomicAdd(&sred[col], s[i]);
                atomicAdd(&sred[128+col], q[i]);
            }
        }
        __syncthreads();
        if (tid < 128){
            atomicAdd(&g_sum  [bcol + tid], sred[tid]);
            atomicAdd(&g_sumsq[bcol + tid], sred[128 + tid]);
        }
    }
}

// ================= GEMM2: 128x256 single-block tile =================
// Y2 = silu(bn(Y1)) @ w2 + b2, stats fused. One block per 128 rows, all 256 cols.
#define B2PITCH 528
#define SM2BUF  54272   // Ahi 10240 | Alo 10240 | Bhi 16896 | Blo 16896
__global__ void __launch_bounds__(256,1) gemm2big(
    const float* __restrict__ Af,
    const __nv_bfloat16* __restrict__ Bhi, const __nv_bfloat16* __restrict__ Blo,
    const float* __restrict__ bias, float* __restrict__ C)
{
    extern __shared__ __align__(16) uint8_t smem[];
    const uint32_t sb = smem_u32(smem);
    const int tid = threadIdx.x;
    const int lane = tid & 31, wid = tid >> 5;
    const int warpm = wid & 3, warpn = wid >> 2;
    const int brow = blockIdx.y * 128;
    const int ar = tid >> 1, akh = (tid & 1) * 16;
    const int bkr = tid >> 3, bns = (tid & 7) * 32;

    auto stageB = [&](int kc, int buf){
        const int gk = kc*32 + bkr;
        const uint32_t dst = sb + buf*SM2BUF + 20480 + bkr*B2PITCH + bns*2;
        const size_t so = (size_t)gk*256 + bns;
        #pragma unroll
        for (int q=0;q<4;q++){
            cpasync16(dst + q*16,         Bhi + so + q*8);
            cpasync16(dst + 16896 + q*16, Blo + so + q*8);
        }
    };
    auto loadA = [&](int kc, float* av){
        const float* S = Af + (size_t)(brow+ar)*128 + kc*32 + akh;
        #pragma unroll
        for (int q=0;q<4;q++) *reinterpret_cast<float4*>(&av[q*4]) =
            *reinterpret_cast<const float4*>(S + q*4);
    };
    auto storeA = [&](int kc, int buf, float* av){
        #pragma unroll
        for (int j=0;j<16;j++){
            const int k = kc*32 + akh + j;
            av[j] = siluf(av[j]*g_scale[k] + g_shift[k]);
        }
        uint4 h0,l0,h1,l1;
        split8(&av[0], h0, l0);
        split8(&av[8], h1, l1);
        uint8_t* base = smem + buf*SM2BUF + ar*APITCH + akh*2;
        *reinterpret_cast<uint4*>(base)              = h0;
        *reinterpret_cast<uint4*>(base + 16)         = h1;
        *reinterpret_cast<uint4*>(base + 10240)      = l0;
        *reinterpret_cast<uint4*>(base + 10240 + 16) = l1;
    };

    float d[2][16][4];
    #pragma unroll
    for (int i=0;i<2;i++)
        #pragma unroll
        for (int j=0;j<16;j++)
            #pragma unroll
            for (int q=0;q<4;q++) d[i][j][q] = 0.f;

    float av[16];
    stageB(0, 0); loadA(0, av); storeA(0, 0, av);
    CP_COMMIT(); CP_WAIT0();
    __syncthreads();

    for (int kc = 0; kc < 4; kc++){
        const int cur = kc & 1, nxt = cur ^ 1;
        const bool more = (kc < 3);
        if (more){ stageB(kc+1, nxt); CP_COMMIT(); loadA(kc+1, av); }
        const uint32_t aHi = sb + cur*SM2BUF;
        const uint32_t aLo = aHi + 10240;
        const uint32_t bHi = aHi + 20480;
        const uint32_t bLo = aHi + 37376;
        #pragma unroll
        for (int ks=0; ks<2; ks++){
            uint32_t ah[2][4], al[2][4];
            #pragma unroll
            for (int mb=0; mb<2; mb++){
                const uint32_t ao = (uint32_t)(warpm*32 + mb*16 + (lane & 15))*APITCH
                                  + ks*32 + ((lane >> 4)*16);
                ldsm4(ah[mb], aHi + ao);
                ldsm4(al[mb], aLo + ao);
            }
            #pragma unroll
            for (int np=0; np<8; np++){
                const int n0 = warpn*128 + np*16;
                const uint32_t bo = (uint32_t)(ks*16 + (lane & 15))*B2PITCH
                                  + (uint32_t)n0*2 + ((lane >> 4)*16);
                uint32_t bh[4], bl[4];
                ldsm4t(bh, bHi + bo);
                ldsm4t(bl, bLo + bo);
                #pragma unroll
                for (int mb=0; mb<2; mb++){
                    mma16816(d[mb][np*2  ], ah[mb], bh[0], bh[1]);
                    mma16816(d[mb][np*2  ], al[mb], bh[0], bh[1]);
                    mma16816(d[mb][np*2  ], ah[mb], bl[0], bl[1]);
                    mma16816(d[mb][np*2+1], ah[mb], bh[2], bh[3]);
                    mma16816(d[mb][np*2+1], al[mb], bh[2], bh[3]);
                    mma16816(d[mb][np*2+1], ah[mb], bl[2], bl[3]);
                }
            }
        }
        if (more){ storeA(kc+1, nxt, av); CP_WAIT0(); }
        __syncthreads();
    }

    // ---- epilogue: bias + store ----
    #pragma unroll
    for (int mb=0; mb<2; mb++){
        #pragma unroll
        for (int nb=0; nb<16; nb++){
            const int m = brow + warpm*32 + mb*16 + (lane >> 2);
            const int n = warpn*128 + nb*8 + (lane & 3)*2;
            const float b0 = bias[n], b1 = bias[n+1];
            d[mb][nb][0] += b0; d[mb][nb][1] += b1;
            d[mb][nb][2] += b0; d[mb][nb][3] += b1;
            *reinterpret_cast<float2*>(C + (size_t)m*256 + n) =
                make_float2(d[mb][nb][0], d[mb][nb][1]);
            *reinterpret_cast<float2*>(C + (size_t)(m+8)*256 + n) =
                make_float2(d[mb][nb][2], d[mb][nb][3]);
        }
    }

    // ---- fused 256-col stats ----
    float* sred = reinterpret_cast<float*>(smem + 2*SM2BUF);
    if (tid < 256){ sred[tid] = 0.f; sred[256+tid] = 0.f; }
    __syncthreads();
    float s[32], q[32];
    #pragma unroll
    for (int i=0;i<32;i++){ s[i]=0.f; q[i]=0.f; }
    #pragma unroll
    for (int mb=0; mb<2; mb++)
        #pragma unroll
        for (int nb=0; nb<16; nb++){
            s[nb*2+0] += d[mb][nb][0] + d[mb][nb][2];
            s[nb*2+1] += d[mb][nb][1] + d[mb][nb][3];
            q[nb*2+0] += d[mb][nb][0]*d[mb][nb][0] + d[mb][nb][2]*d[mb][nb][2];
            q[nb*2+1] += d[mb][nb][1]*d[mb][nb][1] + d[mb][nb][3]*d[mb][nb][3];
        }
    #pragma unroll
    for (int off=4; off<32; off<<=1){
        #pragma unroll
        for (int i=0;i<32;i++){
            s[i] += __shfl_xor_sync(0xFFFFFFFFu, s[i], off);
            q[i] += __shfl_xor_sync(0xFFFFFFFFu, q[i], off);
        }
    }
    if (lane < 4){
        #pragma unroll
        for (int i=0;i<32;i++){
            const int col = warpn*128 + (i>>1)*8 + (lane & 3)*2 + (i & 1);
            atomicAdd(&sred[col], s[i]);
            atomicAdd(&sred[256+col], q[i]);
        }
    }
    __syncthreads();
    if (tid < 256){
        atomicAdd(&g_sum  [tid], sred[tid]);
        atomicAdd(&g_sumsq[tid], sred[256 + tid]);
    }
}

// ================= spectral forward (256 blocks, red.add into fp32 HS) =================
#define SSMBUF 34816
__global__ void __launch_bounds__(256,2) spec5(float* __restrict__ HS)
{
    extern __shared__ __align__(16) uint8_t smem[];
    const uint32_t sb = smem_u32(smem);
    const int b   = blockIdx.z;
    const int seg = blockIdx.x;
    const __nv_bfloat16* Ahi = g_eihi + (size_t)b*V_*K_;
    const __nv_bfloat16* Alo = g_eilo + (size_t)b*V_*K_;
    const __nv_bfloat16* Bhi = g_hhi  + (size_t)b*V_*H_;
    const __nv_bfloat16* Blo = g_hlo  + (size_t)b*V_*H_;

    const int tid = threadIdx.x;
    const int lane = tid & 31, wid = tid >> 5;
    const int warpm = wid & 3, warpn = wid >> 2;
    const int vr = tid >> 3, cs = (tid & 7) * 16;
    const int v0 = seg * (V_/SPLITV);
    const int nch = V_/SPLITV/32;   // 16

    auto stage = [&](int vc, int buf){
        const int v = v0 + vc*32 + vr;
        const size_t soA = (size_t)v*K_ + cs;
        const size_t soB = (size_t)v*H_ + cs;
        const uint32_t base = sb + buf*SSMBUF + vr*BPITCH + cs*2;
        cpasync16(base,              Ahi + soA);
        cpasync16(base + 16,         Ahi + soA + 8);
        cpasync16(base + 8704,       Alo + soA);
        cpasync16(base + 8704 + 16,  Alo + soA + 8);
        cpasync16(base + 17408,      Bhi + soB);
        cpasync16(base + 17408 + 16, Bhi + soB + 8);
        cpasync16(base + 26112,      Blo + soB);
        cpasync16(base + 26112 + 16, Blo + soB + 8);
    };

    float d[2][8][4];
    #pragma unroll
    for (int i=0;i<2;i++)
        #pragma unroll
        for (int j=0;j<8;j++)
            #pragma unroll
            for (int q=0;q<4;q++) d[i][j][q] = 0.f;

    stage(0, 0);
    CP_COMMIT();
    CP_WAIT0();
    __syncthreads();

    for (int vc = 0; vc < nch; vc++){
        const int cur = vc & 1, nxt = cur ^ 1;
        const bool more = (vc + 1 < nch);
        if (more){ stage(vc+1, nxt); CP_COMMIT(); }

        const uint32_t aHi = sb + cur*SSMBUF;
        const uint32_t aLo = aHi + 8704;
        const uint32_t bHi = aHi + 17408;
        const uint32_t bLo = aHi + 26112;
        #pragma unroll
        for (int ks=0; ks<2; ks++){
            uint32_t ah[2][4], al[2][4];
            #pragma unroll
            for (int mb=0; mb<2; mb++){
                const uint32_t ao = (uint32_t)(ks*16 + (lane & 7) + ((lane >> 4)*8))*BPITCH
                                  + (uint32_t)(warpm*32 + mb*16)*2 + (((lane >> 3) & 1)*16);
                ldsm4t(ah[mb], aHi + ao);
                ldsm4t(al[mb], aLo + ao);
            }
            #pragma unroll
            for (int np=0; np<4; np++){
                const int n0 = warpn*64 + np*16;
                const uint32_t bo = (uint32_t)(ks*16 + (lane & 15))*BPITCH
                                  + (uint32_t)n0*2 + ((lane >> 4)*16);
                uint32_t bh[4], bl[4];
                ldsm4t(bh, bHi + bo);
                ldsm4t(bl, bLo + bo);
                #pragma unroll
                for (int mb=0; mb<2; mb++){
                    mma16816(d[mb][np*2  ], ah[mb], bh[0], bh[1]);
                    mma16816(d[mb][np*2  ], al[mb], bh[0], bh[1]);
                    mma16816(d[mb][np*2  ], ah[mb], bl[0], bl[1]);
                    mma16816(d[mb][np*2+1], ah[mb], bh[2], bh[3]);
                    mma16816(d[mb][np*2+1], al[mb], bh[2], bh[3]);
                    mma16816(d[mb][np*2+1], ah[mb], bl[2], bl[3]);
                }
            }
        }
        if (more) CP_WAIT0();
        __syncthreads();
    }

    float* Cb = HS + (size_t)b*K_*H_;
    #pragma unroll
    for (int mb=0; mb<2; mb++)
        #pragma unroll
        for (int nb=0; nb<8; nb++){
            const int m = warpm*32 + mb*16 + (lane >> 2);
            const int n = warpn*64 + nb*8 + (lane & 3)*2;
            red_add_v2(Cb + (size_t)m*H_ + n,     d[mb][nb][0], d[mb][nb][1]);
            red_add_v2(Cb + (size_t)(m+8)*H_ + n, d[mb][nb][2], d[mb][nb][3]);
        }
}

// finalize BN coeffs; zeroes stats for next accumulation
__global__ void finalize_bn(const float* __restrict__ g, const float* __restrict__ be, float Rinv){
    const int c = threadIdx.x;
    const float m   = g_sum[c]*Rinv;
    const float var = g_sumsq[c]*Rinv - m*m;
    const float sc  = g[c] * rsqrtf(var + EPSF);
    g_scale[c] = sc;
    g_shift[c] = be[c] - m*sc;
    g_sum[c] = 0.f;
    g_sumsq[c] = 0.f;
}

// ---------------- message + scatter-add ----------------
__global__ void msg_scatter(const float* __restrict__ Y2, const int* __restrict__ vid,
                            float* __restrict__ Hout)
{
    const int sub = threadIdx.x >> 5;
    const int c4  = (threadIdx.x & 31) * 4;
    const int e0  = blockIdx.x * 32 + sub * 8;
    const float s0=g_scale[c4],   s1=g_scale[c4+1],   s2=g_scale[c4+2],   s3=g_scale[c4+3];
    const float t0=g_shift[c4],   t1=g_shift[c4+1],   t2=g_shift[c4+2],   t3=g_shift[c4+3];
    const float u0=g_scale[128+c4],u1=g_scale[129+c4],u2=g_scale[130+c4],u3=g_scale[131+c4];
    const float w0=g_shift[128+c4],w1=g_shift[129+c4],w2=g_shift[130+c4],w3=g_shift[131+c4];
    #pragma unroll
    for (int i=0;i<8;i++){
        const int e = e0 + i;
        float4 f = *reinterpret_cast<const float4*>(Y2 + (size_t)e*256 + c4);
        float4 c = *reinterpret_cast<const float4*>(Y2 + (size_t)e*256 + 128 + c4);
        float m0 = (1.f/(1.f+__expf(-(f.x*s0+t0)))) * softplusf(c.x*u0+w0);
        float m1 = (1.f/(1.f+__expf(-(f.y*s1+t1)))) * softplusf(c.y*u1+w1);
        float m2 = (1.f/(1.f+__expf(-(f.z*s2+t2)))) * softplusf(c.z*u2+w2);
        float m3 = (1.f/(1.f+__expf(-(f.w*s3+t3)))) * softplusf(c.w*u3+w3);
        const int v = vid[e];
        red_add_v4(Hout + (size_t)v*128 + c4, m0, m1, m2, m3);
    }
}

// h += bn(Y); also emit split H
__global__ void h_update_split(float* __restrict__ H, const float* __restrict__ Y){
    const size_t i = (size_t)blockIdx.x*256 + threadIdx.x;
    const int c = (int)(i & 127);
    const float v = H[i] + Y[i]*g_scale[c] + g_shift[c];
    H[i] = v;
    __nv_bfloat16 hi, lo; split1(v, hi, lo);
    g_hhi[i] = hi; g_hlo[i] = lo;
}
__global__ void split_H(const float* __restrict__ H){
    const size_t i = (size_t)blockIdx.x*256 + threadIdx.x;
    __nv_bfloat16 hi, lo; split1(H[i], hi, lo);
    g_hhi[i] = hi; g_hlo[i] = lo;
}

// out[b] += mean_v( silu(bn(Yo)) . wo2 + bo2 )
__global__ void out_reduce(const float* __restrict__ Yo, const float* __restrict__ wo2,
                           const float* __restrict__ bo2, float* __restrict__ out)
{
    const int warp = threadIdx.x >> 5, lane = threadIdx.x & 31;
    const long n = (long)blockIdx.x*8 + warp;
    float s = 0.f;
    #pragma unroll
    for (int j=0;j<4;j++){
        const int h = lane + j*32;
        float x = Yo[(size_t)n*128 + h]*g_scale[h] + g_shift[h];
        x = siluf(x);
        s += x * wo2[h];
    }
    #pragma unroll
    for (int o=16;o>0;o>>=1) s += __shfl_xor_sync(0xFFFFFFFFu, s, o);
    if (lane == 0){
        const int b = (int)(n >> 11);
        atomicAdd(&out[b], (s + bo2[0]) * (1.f/(float)V_));
    }
}

// ---------------- launcher ----------------
extern "C" void kernel_launch(void* const* d_in, const int* in_sizes, int n_in,
                              void* d_out, int out_size)
{
    const float* chem = (const float*)d_in[0];
    const int*   vid  = (const int*  )d_in[1];
    const float* eigs = (const float*)d_in[2];
    const float* w1   = (const float*)d_in[3];
    const float* b1   = (const float*)d_in[4];
    const float* g1   = (const float*)d_in[5];
    const float* be1  = (const float*)d_in[6];
    const float* w2   = (const float*)d_in[7];
    const float* b2   = (const float*)d_in[8];
    const float* g2   = (const float*)d_in[9];
    const float* be2  = (const float*)d_in[10];
    const float* ptim = (const float*)d_in[11];
    const float* pw1  = (const float*)d_in[12];
    const float* pb1  = (const float*)d_in[13];
    const float* pg1  = (const float*)d_in[14];
    const float* pbe1 = (const float*)d_in[15];
    const float* pw2  = (const float*)d_in[16];
    const float* pb2  = (const float*)d_in[17];
    const float* pg2  = (const float*)d_in[18];
    const float* pbe2 = (const float*)d_in[19];
    const float* wo1  = (const float*)d_in[20];
    const float* bo1  = (const float*)d_in[21];
    const float* go1  = (const float*)d_in[22];
    const float* beo1 = (const float*)d_in[23];
    const float* wo2  = (const float*)d_in[24];
    const float* bo2  = (const float*)d_in[25];
    float* outp = (float*)d_out;

    void* p;
    float *pY1,*pY2,*pH,*pHS,*pYa,*pYb;
    __nv_bfloat16 *pw1hi,*pw1lo,*pw2hi,*pw2lo,*ppw1hi,*ppw1lo,*ppw2hi,*ppw2lo,*pwo1hi,*pwo1lo;
    __nv_bfloat16 *pevhi,*pevlo,*phhi,*phlo,*pThi,*pTlo;
    cudaGetSymbolAddress(&p, g_Y1); pY1=(float*)p;
    cudaGetSymbolAddress(&p, g_Y2); pY2=(float*)p;
    cudaGetSymbolAddress(&p, g_H ); pH =(float*)p;
    cudaGetSymbolAddress(&p, g_HS); pHS=(float*)p;
    cudaGetSymbolAddress(&p, g_Ya); pYa=(float*)p;
    cudaGetSymbolAddress(&p, g_Yb); pYb=(float*)p;
    cudaGetSymbolAddress(&p, w1s_hi); pw1hi=(__nv_bfloat16*)p;
    cudaGetSymbolAddress(&p, w1s_lo); pw1lo=(__nv_bfloat16*)p;
    cudaGetSymbolAddress(&p, w2s_hi); pw2hi=(__nv_bfloat16*)p;
    cudaGetSymbolAddress(&p, w2s_lo); pw2lo=(__nv_bfloat16*)p;
    cudaGetSymbolAddress(&p, pw1s_hi); ppw1hi=(__nv_bfloat16*)p;
    cudaGetSymbolAddress(&p, pw1s_lo); ppw1lo=(__nv_bfloat16*)p;
    cudaGetSymbolAddress(&p, pw2s_hi); ppw2hi=(__nv_bfloat16*)p;
    cudaGetSymbolAddress(&p, pw2s_lo); ppw2lo=(__nv_bfloat16*)p;
    cudaGetSymbolAddress(&p, wo1s_hi); pwo1hi=(__nv_bfloat16*)p;
    cudaGetSymbolAddress(&p, wo1s_lo); pwo1lo=(__nv_bfloat16*)p;
    cudaGetSymbolAddress(&p, g_evhi); pevhi=(__nv_bfloat16*)p;
    cudaGetSymbolAddress(&p, g_evlo); pevlo=(__nv_bfloat16*)p;
    cudaGetSymbolAddress(&p, g_hhi ); phhi=(__nv_bfloat16*)p;
    cudaGetSymbolAddress(&p, g_hlo ); phlo=(__nv_bfloat16*)p;
    cudaGetSymbolAddress(&p, g_Thi ); pThi=(__nv_bfloat16*)p;
    cudaGetSymbolAddress(&p, g_Tlo ); pTlo=(__nv_bfloat16*)p;

    const int GSM  = 2*SMBUF + 1024;
    const int SSM  = 2*SSMBUF;
    const int G2SM = 2*SM2BUF + 2048;   // 110592
    cudaFuncSetAttribute(gemm5<0,true ,false>, cudaFuncAttributeMaxDynamicSharedMemorySize, GSM);
    cudaFuncSetAttribute(gemm5<1,true ,false>, cudaFuncAttributeMaxDynamicSharedMemorySize, GSM);
    cudaFuncSetAttribute(gemm5<6,false,true >, cudaFuncAttributeMaxDynamicSharedMemorySize, GSM);
    cudaFuncSetAttribute(gemm5<5,true ,false>, cudaFuncAttributeMaxDynamicSharedMemorySize, GSM);
    cudaFuncSetAttribute(gemm5<3,true ,false>, cudaFuncAttributeMaxDynamicSharedMemorySize, GSM);
    cudaFuncSetAttribute(gemm2big, cudaFuncAttributeMaxDynamicSharedMemorySize, G2SM);
    cudaFuncSetAttribute(spec5, cudaFuncAttributeMaxDynamicSharedMemorySize, SSM);

    // launches 1-5 (keeps GEMM1 as launch #6 for ncu -s 5 -c 1)
    split_w1<<<64*128/256, 256>>>(w1);
    zero_kernel<<<1, 64>>>(outp, 64);
    zero_stats<<<1,256>>>();
    split_mat<<<(128*256+255)/256, 256>>>(w2, pw2hi, pw2lo, 128*256);
    split_eigs_k<<<(unsigned)(((size_t)B_*V_*K_)/256), 256>>>(eigs);

    // ---- chem MLP stage 1 (launch #6 — profiled) ----
    gemm5<0,true,false><<<dim3(1, E_/128, 1), 256, GSM>>>(
        chem, nullptr, nullptr, nullptr, nullptr, pw1hi, pw1lo, nullptr, nullptr,
        b1, pY1, nullptr, nullptr, CF_, 128, CF_, 0, 0, 0, nullptr, nullptr, 0);
    finalize_bn<<<1,128>>>(g1, be1, 1.f/(float)E_);

    // remaining prep
    split_mat<<<(3*256*128+255)/256, 256>>>(pw1, ppw1hi, ppw1lo, 3*256*128);
    split_mat<<<(3*128*128+255)/256, 256>>>(pw2, ppw2hi, ppw2lo, 3*128*128);
    split_mat<<<(128*128+255)/256, 256>>>(wo1, pwo1hi, pwo1lo, 128*128);

    // ---- stage 2: one 256-col block per 128 rows ----
    gemm2big<<<dim3(1, E_/128, 1), 256, G2SM>>>(pY1, pw2hi, pw2lo, b2, pY2);
    finalize_bn<<<1,256>>>(g2, be2, 1.f/(float)E_);

    // ---- message + segment_sum ----
    zero_kernel<<<(unsigned)(((size_t)N_*H_)/256), 256>>>(pH, (size_t)N_*H_);
    msg_scatter<<<E_/32, 128>>>(pY2, vid, pH);
    split_H<<<(unsigned)(((size_t)N_*H_)/256), 256>>>(pH);

    // ---- propagation layers ----
    for (int l = 0; l < L_; l++){
        zero_kernel<<<(B_*K_*H_+255)/256, 256>>>(pHS, (size_t)B_*K_*H_);
        spec5<<<dim3(SPLITV, 1, B_), 256, SSM>>>(pHS);
        // T[b] = (coeff .* HS[b]) @ W1b   (coeff fused into A loader)
        gemm5<6,false,true><<<dim3(1, 1, B_), 256, GSM>>>(
            pHS, nullptr, nullptr, nullptr, nullptr,
            ppw1hi + (size_t)l*256*128 + 128*128, ppw1lo + (size_t)l*256*128 + 128*128,
            nullptr, nullptr, nullptr, nullptr, pThi, pTlo,
            128, 128, 128, 0, 0, (size_t)K_*H_, eigs, ptim, l);
        // zMLP1: Ya = h @ W1a + evecs @ T[b] + pb1[l]
        gemm5<5,true,false><<<dim3(1, N_/128, 1), 256, GSM>>>(
            nullptr, phhi, phlo, pevhi, pevlo,
            ppw1hi + (size_t)l*256*128, ppw1lo + (size_t)l*256*128, pThi, pTlo,
            pb1 + l*H_, pYa, nullptr, nullptr, 256, 128, 128, 0, 0, 0, nullptr, nullptr, 0);
        finalize_bn<<<1,128>>>(pg1 + l*H_, pbe1 + l*H_, 1.f/(float)N_);
        // zMLP2: Yb = silu(bn(Ya)) @ pw2[l] + pb2[l]
        gemm5<1,true,false><<<dim3(1, N_/128, 1), 256, GSM>>>(
            pYa, nullptr, nullptr, nullptr, nullptr,
            ppw2hi + (size_t)l*128*128, ppw2lo + (size_t)l*128*128, nullptr, nullptr,
            pb2 + l*H_, pYb, nullptr, nullptr, 128, 128, 128, 0, 0, 0, nullptr, nullptr, 0);
        finalize_bn<<<1,128>>>(pg2 + l*H_, pbe2 + l*H_, 1.f/(float)N_);
        h_update_split<<<(unsigned)(((size_t)N_*H_)/256), 256>>>(pH, pYb);
    }

    // ---- output head ----
    gemm5<3,true,false><<<dim3(1, N_/128, 1), 256, GSM>>>(
        nullptr, phhi, phlo, nullptr, nullptr, pwo1hi, pwo1lo, nullptr, nullptr,
        bo1, pYa, nullptr, nullptr, 128, 128, 128, 0, 0, 0, nullptr, nullptr, 0);
    finalize_bn<<<1,128>>>(go1, beo1, 1.f/(float)N_);
    out_reduce<<<N_/8, 256>>>(pYa, wo2, bo2, outp);
}

// round 9
// speedup vs baseline: 1.0284x; 1.0284x over previous
#include <cuda_runtime.h>
#include <cuda_bf16.h>
#include <cstdint>

// ---------------- problem constants ----------------
#define B_   64
#define V_   2048
#define K_   128
#define H_   128
#define N_   (B_*V_)
#define E_   1048576
#define CF_  47
#define L_   3
#define EPSF 1e-5f
#define SPLITV 4

// ---------------- scratch ----------------
__device__ float g_Y1[(size_t)E_*H_];
__device__ float g_Y2[(size_t)E_*2*H_];
__device__ float g_H [(size_t)N_*H_];
__device__ float g_HS[(size_t)B_*K_*H_];
__device__ float g_Ya[(size_t)N_*H_];
__device__ float g_Yb[(size_t)N_*H_];
__device__ float g_sum[256], g_sumsq[256], g_scale[256], g_shift[256];
__device__ __nv_bfloat16 w1s_hi[64*128],        w1s_lo[64*128];
__device__ __nv_bfloat16 w2s_hi[128*256],       w2s_lo[128*256];
__device__ __nv_bfloat16 pw1s_hi[3*256*128],    pw1s_lo[3*256*128];
__device__ __nv_bfloat16 pw2s_hi[3*128*128],    pw2s_lo[3*128*128];
__device__ __nv_bfloat16 wo1s_hi[128*128],      wo1s_lo[128*128];
__device__ __nv_bfloat16 g_evhi[(size_t)B_*V_*K_], g_evlo[(size_t)B_*V_*K_];
__device__ __nv_bfloat16 g_eihi[(size_t)B_*V_*K_], g_eilo[(size_t)B_*V_*K_];
__device__ __nv_bfloat16 g_hhi [(size_t)N_*H_],    g_hlo [(size_t)N_*H_];
__device__ __nv_bfloat16 g_Thi [(size_t)B_*K_*H_], g_Tlo [(size_t)B_*K_*H_];

// ---------------- helpers ----------------
__device__ __forceinline__ float siluf(float x){ return x * (1.f/(1.f+__expf(-x))); }
__device__ __forceinline__ float softplusf(float x){ return x > 20.f ? x : log1pf(__expf(x)); }
__device__ __forceinline__ void red_add_v4(float* a, float x, float y, float z, float w){
    asm volatile("red.global.add.v4.f32 [%0], {%1,%2,%3,%4};"
                 :: "l"(a), "f"(x), "f"(y), "f"(z), "f"(w) : "memory");
}
__device__ __forceinline__ void red_add_v2(float* a, float x, float y){
    asm volatile("red.global.add.v2.f32 [%0], {%1,%2};" :: "l"(a), "f"(x), "f"(y) : "memory");
}
__device__ __forceinline__ uint32_t smem_u32(const void* p){
    uint32_t a;
    asm("{ .reg .u64 t; cvta.to.shared.u64 t, %1; cvt.u32.u64 %0, t; }" : "=r"(a) : "l"(p));
    return a;
}
__device__ __forceinline__ void cpasync16(uint32_t s, const void* g){
    asm volatile("cp.async.ca.shared.global [%0], [%1], 16;" :: "r"(s), "l"(g));
}
#define CP_COMMIT() asm volatile("cp.async.commit_group;")
#define CP_WAIT0()  asm volatile("cp.async.wait_group 0;")

__device__ __forceinline__ void ldsm4(uint32_t* r, uint32_t addr){
    asm volatile("ldmatrix.sync.aligned.m8n8.x4.shared.b16 {%0,%1,%2,%3}, [%4];"
        : "=r"(r[0]),"=r"(r[1]),"=r"(r[2]),"=r"(r[3]) : "r"(addr));
}
__device__ __forceinline__ void ldsm4t(uint32_t* r, uint32_t addr){
    asm volatile("ldmatrix.sync.aligned.m8n8.x4.trans.shared.b16 {%0,%1,%2,%3}, [%4];"
        : "=r"(r[0]),"=r"(r[1]),"=r"(r[2]),"=r"(r[3]) : "r"(addr));
}
__device__ __forceinline__ void mma16816(float* d, const uint32_t* a, uint32_t b0, uint32_t b1){
    asm volatile("mma.sync.aligned.m16n8k16.row.col.f32.bf16.bf16.f32 "
        "{%0,%1,%2,%3}, {%4,%5,%6,%7}, {%8,%9}, {%0,%1,%2,%3};"
        : "+f"(d[0]),"+f"(d[1]),"+f"(d[2]),"+f"(d[3])
        : "r"(a[0]),"r"(a[1]),"r"(a[2]),"r"(a[3]), "r"(b0),"r"(b1));
}

__device__ __forceinline__ void split8(const float* f, uint4& hi, uint4& lo){
    unsigned h[4], l[4];
    #pragma unroll
    for (int p=0;p<4;p++){
        float2 a = make_float2(f[2*p], f[2*p+1]);
        __nv_bfloat162 bh = __float22bfloat162_rn(a);
        float hx = __bfloat162float(bh.x), hy = __bfloat162float(bh.y);
        float2 rz = make_float2(a.x - hx, a.y - hy);
        __nv_bfloat162 bl = __float22bfloat162_rn(rz);
        h[p] = *reinterpret_cast<unsigned*>(&bh);
        l[p] = *reinterpret_cast<unsigned*>(&bl);
    }
    hi = make_uint4(h[0],h[1],h[2],h[3]);
    lo = make_uint4(l[0],l[1],l[2],l[3]);
}
__device__ __forceinline__ void split1(float v, __nv_bfloat16& hi, __nv_bfloat16& lo){
    hi = __float2bfloat16_rn(v);
    lo = __float2bfloat16_rn(v - __bfloat162float(hi));
}
__device__ __forceinline__ void split2_store(__nv_bfloat16* phi, __nv_bfloat16* plo,
                                             float v0, float v1){
    __nv_bfloat162 h2 = __float22bfloat162_rn(make_float2(v0, v1));
    __nv_bfloat162 l2 = __float22bfloat162_rn(make_float2(
        v0-__bfloat162float(h2.x), v1-__bfloat162float(h2.y)));
    *reinterpret_cast<__nv_bfloat162*>(phi) = h2;
    *reinterpret_cast<__nv_bfloat162*>(plo) = l2;
}

__global__ void zero_kernel(float* __restrict__ p, size_t n){
    size_t i = (size_t)blockIdx.x*blockDim.x + threadIdx.x;
    if (i < n) p[i] = 0.f;
}
__global__ void zero_stats(){ g_sum[threadIdx.x]=0.f; g_sumsq[threadIdx.x]=0.f; }

// ---------------- prep: split kernels ----------------
__global__ void split_mat(const float* __restrict__ src, __nv_bfloat16* __restrict__ hi,
                          __nv_bfloat16* __restrict__ lo, size_t n){
    size_t i = (size_t)blockIdx.x*256 + threadIdx.x;
    if (i < n){ __nv_bfloat16 h, l; split1(src[i], h, l); hi[i]=h; lo[i]=l; }
}
__global__ void split_w1(const float* __restrict__ w1){
    int i = blockIdx.x*256 + threadIdx.x;
    int k = i >> 7, n = i & 127;
    float v = (k < CF_) ? w1[k*128 + n] : 0.f;
    __nv_bfloat16 h, l; split1(v, h, l);
    w1s_hi[i]=h; w1s_lo[i]=l;
}
__global__ void split_eigs_k(const float* __restrict__ eigs){
    size_t i = (size_t)blockIdx.x*256 + threadIdx.x;
    size_t b = i >> 18, rem = i & 0x3FFFF;
    const float* base = eigs + (b*(size_t)(2*V_+1) + 1)*K_;
    __nv_bfloat16 h, l;
    split1(base[rem], h, l);                 g_evhi[i]=h; g_evlo[i]=l;
    split1(base[(size_t)V_*K_ + rem], h, l); g_eihi[i]=h; g_eilo[i]=l;
}

// ================= pipelined HMMA split-bf16 GEMM =================
// ASRC 0: A fp32 plain, guarded scalar loads (GEMM1, Kd=47; skips all-zero k16 steps)
// ASRC 1: A fp32, silu(A*scale+shift)
// ASRC 3: A pre-split bf16
// ASRC 5: dual concat: kc<4 -> (Ahi/Alo @ Bhi/Blo); kc>=4 -> (evecs[batch] @ B2[batch])
// ASRC 6: A fp32 * exp(-eig[row]*t[col])  (coeff-fused T-gemm)
#define APITCH 80
#define BPITCH 272
#define SMBUF  37888
template<int ASRC, bool STATS, bool OUTSPLIT>
__global__ void __launch_bounds__(256,2) gemm5(
    const float* __restrict__ Af,
    const __nv_bfloat16* __restrict__ Ahi, const __nv_bfloat16* __restrict__ Alo,
    const __nv_bfloat16* __restrict__ A2hi, const __nv_bfloat16* __restrict__ A2lo,
    const __nv_bfloat16* __restrict__ Bhi, const __nv_bfloat16* __restrict__ Blo,
    const __nv_bfloat16* __restrict__ B2hi, const __nv_bfloat16* __restrict__ B2lo,
    const float* __restrict__ bias, float* __restrict__ C,
    __nv_bfloat16* __restrict__ Chi, __nv_bfloat16* __restrict__ Clo,
    int Kd, int Nd, int lda,
    size_t sAs, size_t sBs, size_t sC,
    const float* __restrict__ eigsp, const float* __restrict__ ptp, int lidx)
{
    extern __shared__ __align__(16) uint8_t smem[];
    const uint32_t sb = smem_u32(smem);
    const int tid = threadIdx.x;
    const int lane = tid & 31, wid = tid >> 5;
    const int warpm = wid & 3, warpn = wid >> 2;
    const int brow = blockIdx.y * 128;
    const int bcol = blockIdx.x * 128;
    const int bz   = blockIdx.z;
    Ahi += sAs*bz; Alo += sAs*bz; Bhi += sBs*bz; Blo += sBs*bz;
    if (ASRC == 6) Af += (size_t)K_*H_*bz;
    if (C)   C   += sC*bz;
    if (Chi){ Chi += sC*bz; Clo += sC*bz; }
    const int bb = brow >> 11;
    const size_t a2base = (size_t)bb*V_*K_ + (size_t)(brow & 2047)*K_;
    const size_t b2base = (size_t)bb*K_*H_;

    const int nch = (Kd + 31) >> 5;

    const int ar = tid >> 1, akh = (tid & 1) * 16;
    const int bkr = tid >> 3, bns = (tid & 7) * 16;

    auto stageB = [&](int kc, int buf){
        const __nv_bfloat16 *shi, *slo; size_t so;
        if (ASRC == 5 && kc >= 4){
            const int gk = (kc & 3)*32 + bkr;
            shi = B2hi + b2base; slo = B2lo + b2base;
            so = (size_t)gk*128 + bns;
        } else {
            const int gk = kc*32 + bkr;
            shi = Bhi; slo = Blo;
            so = (size_t)gk*Nd + bcol + bns;
        }
        const uint32_t dst = sb + buf*SMBUF + 20480 + bkr*BPITCH + bns*2;
        cpasync16(dst,             shi + so);
        cpasync16(dst + 16,        shi + so + 8);
        cpasync16(dst + 8704,      slo + so);
        cpasync16(dst + 8704 + 16, slo + so + 8);
    };
    auto stageA_async = [&](int kc, int buf){
        const __nv_bfloat16 *hi, *lo; size_t so;
        if (ASRC == 5){
            if (kc < 4){ hi = Ahi; lo = Alo; so = (size_t)(brow+ar)*128 + kc*32 + akh; }
            else { hi = A2hi + a2base; lo = A2lo + a2base;
                   so = (size_t)ar*K_ + (kc & 3)*32 + akh; }
        } else {
            hi = Ahi; lo = Alo;
            so = (size_t)(brow + ar)*lda + kc*32 + akh;
        }
        const uint32_t dst = sb + buf*SMBUF + ar*APITCH + akh*2;
        cpasync16(dst,              hi + so);
        cpasync16(dst + 16,         hi + so + 8);
        cpasync16(dst + 10240,      lo + so);
        cpasync16(dst + 10240 + 16, lo + so + 8);
    };
    auto loadA_f32 = [&](int kc, float* av){
        if (ASRC == 1 || ASRC == 6){
            const float* S = Af + (size_t)(brow+ar)*lda + kc*32 + akh;
            #pragma unroll
            for (int q=0;q<4;q++) *reinterpret_cast<float4*>(&av[q*4]) =
                *reinterpret_cast<const float4*>(S + q*4);
        } else {
            #pragma unroll
            for (int j=0;j<16;j++){
                const int k = kc*32 + akh + j;
                av[j] = (k < Kd) ? Af[(size_t)(brow+ar)*lda + k] : 0.f;
            }
        }
    };
    auto storeA_f32 = [&](int kc, int buf, float* av){
        if (ASRC == 1){
            #pragma unroll
            for (int j=0;j<16;j++){
                const int k = kc*32 + akh + j;
                av[j] = siluf(av[j]*g_scale[k] + g_shift[k]);
            }
        }
        if (ASRC == 6){
            const float eig_a = eigsp[(size_t)bz*(2*V_+1)*K_ + brow + ar];
            #pragma unroll
            for (int j=0;j<16;j++){
                const int k = kc*32 + akh + j;
                av[j] *= __expf(-eig_a * fmaxf(ptp[lidx*H_ + k], 1e-6f));
            }
        }
        uint4 h0,l0,h1,l1;
        split8(&av[0], h0, l0);
        split8(&av[8], h1, l1);
        uint8_t* base = smem + buf*SMBUF + ar*APITCH + akh*2;
        *reinterpret_cast<uint4*>(base)              = h0;
        *reinterpret_cast<uint4*>(base + 16)         = h1;
        *reinterpret_cast<uint4*>(base + 10240)      = l0;
        *reinterpret_cast<uint4*>(base + 10240 + 16) = l1;
    };

    constexpr bool A_F32 = (ASRC == 0) || (ASRC == 1) || (ASRC == 6);

    float d[2][8][4];
    #pragma unroll
    for (int i=0;i<2;i++)
        #pragma unroll
        for (int j=0;j<8;j++)
            #pragma unroll
            for (int q=0;q<4;q++) d[i][j][q] = 0.f;

    float av[16];
    stageB(0, 0);
    if (A_F32){ loadA_f32(0, av); storeA_f32(0, 0, av); }
    else       stageA_async(0, 0);
    CP_COMMIT();
    CP_WAIT0();
    __syncthreads();

    for (int kc = 0; kc < nch; kc++){
        const int cur = kc & 1, nxt = cur ^ 1;
        const bool more = (kc + 1 < nch);
        if (more){
            stageB(kc+1, nxt);
            if (!A_F32) stageA_async(kc+1, nxt);
            CP_COMMIT();
            if (A_F32) loadA_f32(kc+1, av);
        }
        const uint32_t aHi = sb + cur*SMBUF;
        const uint32_t aLo = aHi + 10240;
        const uint32_t bHi = aHi + 20480;
        const uint32_t bLo = aHi + 29184;
        #pragma unroll
        for (int ks=0; ks<2; ks++){
            // compile-time true for all ASRC != 0 (Kd multiple of 32 there)
            if (ASRC != 0 || kc*32 + ks*16 < Kd){
                uint32_t ah[2][4], al[2][4];
                #pragma unroll
                for (int mb=0; mb<2; mb++){
                    const uint32_t ao = (uint32_t)(warpm*32 + mb*16 + (lane & 15))*APITCH
                                      + ks*32 + ((lane >> 4)*16);
                    ldsm4(ah[mb], aHi + ao);
                    ldsm4(al[mb], aLo + ao);
                }
                #pragma unroll
                for (int np=0; np<4; np++){
                    const int n0 = warpn*64 + np*16;
                    const uint32_t bo = (uint32_t)(ks*16 + (lane & 15))*BPITCH
                                      + (uint32_t)n0*2 + ((lane >> 4)*16);
                    uint32_t bh[4], bl[4];
                    ldsm4t(bh, bHi + bo);
                    ldsm4t(bl, bLo + bo);
                    #pragma unroll
                    for (int mb=0; mb<2; mb++){
                        mma16816(d[mb][np*2  ], ah[mb], bh[0], bh[1]);
                        mma16816(d[mb][np*2  ], al[mb], bh[0], bh[1]);
                        mma16816(d[mb][np*2  ], ah[mb], bl[0], bl[1]);
                        mma16816(d[mb][np*2+1], ah[mb], bh[2], bh[3]);
                        mma16816(d[mb][np*2+1], al[mb], bh[2], bh[3]);
                        mma16816(d[mb][np*2+1], ah[mb], bl[2], bl[3]);
                    }
                }
            }
        }
        if (more){
            if (A_F32) storeA_f32(kc+1, nxt, av);
            CP_WAIT0();
        }
        __syncthreads();
    }

    #pragma unroll
    for (int mb=0; mb<2; mb++){
        #pragma unroll
        for (int nb=0; nb<8; nb++){
            const int m = brow + warpm*32 + mb*16 + (lane >> 2);
            const int n = bcol + warpn*64 + nb*8 + (lane & 3)*2;
            float b0 = 0.f, b1 = 0.f;
            if (bias){ b0 = bias[n]; b1 = bias[n+1]; }
            d[mb][nb][0] += b0; d[mb][nb][1] += b1;
            d[mb][nb][2] += b0; d[mb][nb][3] += b1;
            if (OUTSPLIT){
                split2_store(Chi + (size_t)m*Nd + n, Clo + (size_t)m*Nd + n,
                             d[mb][nb][0], d[mb][nb][1]);
                split2_store(Chi + (size_t)(m+8)*Nd + n, Clo + (size_t)(m+8)*Nd + n,
                             d[mb][nb][2], d[mb][nb][3]);
            } else {
                *reinterpret_cast<float2*>(C + (size_t)m*Nd + n) =
                    make_float2(d[mb][nb][0], d[mb][nb][1]);
                *reinterpret_cast<float2*>(C + (size_t)(m+8)*Nd + n) =
                    make_float2(d[mb][nb][2], d[mb][nb][3]);
            }
        }
    }

    if (STATS){
        float* sred = reinterpret_cast<float*>(smem + 2*SMBUF);
        sred[tid] = 0.f;
        __syncthreads();
        float s[16], q[16];
        #pragma unroll
        for (int i=0;i<16;i++){ s[i]=0.f; q[i]=0.f; }
        #pragma unroll
        for (int mb=0; mb<2; mb++)
            #pragma unroll
            for (int nb=0; nb<8; nb++){
                s[nb*2+0] += d[mb][nb][0] + d[mb][nb][2];
                s[nb*2+1] += d[mb][nb][1] + d[mb][nb][3];
                q[nb*2+0] += d[mb][nb][0]*d[mb][nb][0] + d[mb][nb][2]*d[mb][nb][2];
                q[nb*2+1] += d[mb][nb][1]*d[mb][nb][1] + d[mb][nb][3]*d[mb][nb][3];
            }
        #pragma unroll
        for (int off=4; off<32; off<<=1){
            #pragma unroll
            for (int i=0;i<16;i++){
                s[i] += __shfl_xor_sync(0xFFFFFFFFu, s[i], off);
                q[i] += __shfl_xor_sync(0xFFFFFFFFu, q[i], off);
            }
        }
        if (lane < 4){
            #pragma unroll
            for (int i=0;i<16;i++){
                const int col = warpn*64 + (i>>1)*8 + (lane & 3)*2 + (i & 1);
                atomicAdd(&sred[col], s[i]);
                atomicAdd(&sred[128+col], q[i]);
            }
        }
        __syncthreads();
        if (tid < 128){
            atomicAdd(&g_sum  [bcol + tid], sred[tid]);
            atomicAdd(&g_sumsq[bcol + tid], sred[128 + tid]);
        }
    }
}

// ================= spectral forward (256 blocks, red.add into fp32 HS) =================
#define SSMBUF 34816
__global__ void __launch_bounds__(256,2) spec5(float* __restrict__ HS)
{
    extern __shared__ __align__(16) uint8_t smem[];
    const uint32_t sb = smem_u32(smem);
    const int b   = blockIdx.z;
    const int seg = blockIdx.x;
    const __nv_bfloat16* Ahi = g_eihi + (size_t)b*V_*K_;
    const __nv_bfloat16* Alo = g_eilo + (size_t)b*V_*K_;
    const __nv_bfloat16* Bhi = g_hhi  + (size_t)b*V_*H_;
    const __nv_bfloat16* Blo = g_hlo  + (size_t)b*V_*H_;

    const int tid = threadIdx.x;
    const int lane = tid & 31, wid = tid >> 5;
    const int warpm = wid & 3, warpn = wid >> 2;
    const int vr = tid >> 3, cs = (tid & 7) * 16;
    const int v0 = seg * (V_/SPLITV);
    const int nch = V_/SPLITV/32;   // 16

    auto stage = [&](int vc, int buf){
        const int v = v0 + vc*32 + vr;
        const size_t soA = (size_t)v*K_ + cs;
        const size_t soB = (size_t)v*H_ + cs;
        const uint32_t base = sb + buf*SSMBUF + vr*BPITCH + cs*2;
        cpasync16(base,              Ahi + soA);
        cpasync16(base + 16,         Ahi + soA + 8);
        cpasync16(base + 8704,       Alo + soA);
        cpasync16(base + 8704 + 16,  Alo + soA + 8);
        cpasync16(base + 17408,      Bhi + soB);
        cpasync16(base + 17408 + 16, Bhi + soB + 8);
        cpasync16(base + 26112,      Blo + soB);
        cpasync16(base + 26112 + 16, Blo + soB + 8);
    };

    float d[2][8][4];
    #pragma unroll
    for (int i=0;i<2;i++)
        #pragma unroll
        for (int j=0;j<8;j++)
            #pragma unroll
            for (int q=0;q<4;q++) d[i][j][q] = 0.f;

    stage(0, 0);
    CP_COMMIT();
    CP_WAIT0();
    __syncthreads();

    for (int vc = 0; vc < nch; vc++){
        const int cur = vc & 1, nxt = cur ^ 1;
        const bool more = (vc + 1 < nch);
        if (more){ stage(vc+1, nxt); CP_COMMIT(); }

        const uint32_t aHi = sb + cur*SSMBUF;
        const uint32_t aLo = aHi + 8704;
        const uint32_t bHi = aHi + 17408;
        const uint32_t bLo = aHi + 26112;
        #pragma unroll
        for (int ks=0; ks<2; ks++){
            uint32_t ah[2][4], al[2][4];
            #pragma unroll
            for (int mb=0; mb<2; mb++){
                const uint32_t ao = (uint32_t)(ks*16 + (lane & 7) + ((lane >> 4)*8))*BPITCH
                                  + (uint32_t)(warpm*32 + mb*16)*2 + (((lane >> 3) & 1)*16);
                ldsm4t(ah[mb], aHi + ao);
                ldsm4t(al[mb], aLo + ao);
            }
            #pragma unroll
            for (int np=0; np<4; np++){
                const int n0 = warpn*64 + np*16;
                const uint32_t bo = (uint32_t)(ks*16 + (lane & 15))*BPITCH
                                  + (uint32_t)n0*2 + ((lane >> 4)*16);
                uint32_t bh[4], bl[4];
                ldsm4t(bh, bHi + bo);
                ldsm4t(bl, bLo + bo);
                #pragma unroll
                for (int mb=0; mb<2; mb++){
                    mma16816(d[mb][np*2  ], ah[mb], bh[0], bh[1]);
                    mma16816(d[mb][np*2  ], al[mb], bh[0], bh[1]);
                    mma16816(d[mb][np*2  ], ah[mb], bl[0], bl[1]);
                    mma16816(d[mb][np*2+1], ah[mb], bh[2], bh[3]);
                    mma16816(d[mb][np*2+1], al[mb], bh[2], bh[3]);
                    mma16816(d[mb][np*2+1], ah[mb], bl[2], bl[3]);
                }
            }
        }
        if (more) CP_WAIT0();
        __syncthreads();
    }

    float* Cb = HS + (size_t)b*K_*H_;
    #pragma unroll
    for (int mb=0; mb<2; mb++)
        #pragma unroll
        for (int nb=0; nb<8; nb++){
            const int m = warpm*32 + mb*16 + (lane >> 2);
            const int n = warpn*64 + nb*8 + (lane & 3)*2;
            red_add_v2(Cb + (size_t)m*H_ + n,     d[mb][nb][0], d[mb][nb][1]);
            red_add_v2(Cb + (size_t)(m+8)*H_ + n, d[mb][nb][2], d[mb][nb][3]);
        }
}

// finalize BN coeffs; zeroes stats for next accumulation
__global__ void finalize_bn(const float* __restrict__ g, const float* __restrict__ be, float Rinv){
    const int c = threadIdx.x;
    const float m   = g_sum[c]*Rinv;
    const float var = g_sumsq[c]*Rinv - m*m;
    const float sc  = g[c] * rsqrtf(var + EPSF);
    g_scale[c] = sc;
    g_shift[c] = be[c] - m*sc;
    g_sum[c] = 0.f;
    g_sumsq[c] = 0.f;
}

// ---------------- message + scatter-add ----------------
__global__ void msg_scatter(const float* __restrict__ Y2, const int* __restrict__ vid,
                            float* __restrict__ Hout)
{
    const int sub = threadIdx.x >> 5;
    const int c4  = (threadIdx.x & 31) * 4;
    const int e0  = blockIdx.x * 32 + sub * 8;
    const float s0=g_scale[c4],   s1=g_scale[c4+1],   s2=g_scale[c4+2],   s3=g_scale[c4+3];
    const float t0=g_shift[c4],   t1=g_shift[c4+1],   t2=g_shift[c4+2],   t3=g_shift[c4+3];
    const float u0=g_scale[128+c4],u1=g_scale[129+c4],u2=g_scale[130+c4],u3=g_scale[131+c4];
    const float w0=g_shift[128+c4],w1=g_shift[129+c4],w2=g_shift[130+c4],w3=g_shift[131+c4];
    #pragma unroll
    for (int i=0;i<8;i++){
        const int e = e0 + i;
        float4 f = *reinterpret_cast<const float4*>(Y2 + (size_t)e*256 + c4);
        float4 c = *reinterpret_cast<const float4*>(Y2 + (size_t)e*256 + 128 + c4);
        float m0 = (1.f/(1.f+__expf(-(f.x*s0+t0)))) * softplusf(c.x*u0+w0);
        float m1 = (1.f/(1.f+__expf(-(f.y*s1+t1)))) * softplusf(c.y*u1+w1);
        float m2 = (1.f/(1.f+__expf(-(f.z*s2+t2)))) * softplusf(c.z*u2+w2);
        float m3 = (1.f/(1.f+__expf(-(f.w*s3+t3)))) * softplusf(c.w*u3+w3);
        const int v = vid[e];
        red_add_v4(Hout + (size_t)v*128 + c4, m0, m1, m2, m3);
    }
}

// h += bn(Y); also emit split H
__global__ void h_update_split(float* __restrict__ H, const float* __restrict__ Y){
    const size_t i = (size_t)blockIdx.x*256 + threadIdx.x;
    const int c = (int)(i & 127);
    const float v = H[i] + Y[i]*g_scale[c] + g_shift[c];
    H[i] = v;
    __nv_bfloat16 hi, lo; split1(v, hi, lo);
    g_hhi[i] = hi; g_hlo[i] = lo;
}
__global__ void split_H(const float* __restrict__ H){
    const size_t i = (size_t)blockIdx.x*256 + threadIdx.x;
    __nv_bfloat16 hi, lo; split1(H[i], hi, lo);
    g_hhi[i] = hi; g_hlo[i] = lo;
}

// out[b] += mean_v( silu(bn(Yo)) . wo2 + bo2 )
__global__ void out_reduce(const float* __restrict__ Yo, const float* __restrict__ wo2,
                           const float* __restrict__ bo2, float* __restrict__ out)
{
    const int warp = threadIdx.x >> 5, lane = threadIdx.x & 31;
    const long n = (long)blockIdx.x*8 + warp;
    float s = 0.f;
    #pragma unroll
    for (int j=0;j<4;j++){
        const int h = lane + j*32;
        float x = Yo[(size_t)n*128 + h]*g_scale[h] + g_shift[h];
        x = siluf(x);
        s += x * wo2[h];
    }
    #pragma unroll
    for (int o=16;o>0;o>>=1) s += __shfl_xor_sync(0xFFFFFFFFu, s, o);
    if (lane == 0){
        const int b = (int)(n >> 11);
        atomicAdd(&out[b], (s + bo2[0]) * (1.f/(float)V_));
    }
}

// ---------------- launcher ----------------
extern "C" void kernel_launch(void* const* d_in, const int* in_sizes, int n_in,
                              void* d_out, int out_size)
{
    const float* chem = (const float*)d_in[0];
    const int*   vid  = (const int*  )d_in[1];
    const float* eigs = (const float*)d_in[2];
    const float* w1   = (const float*)d_in[3];
    const float* b1   = (const float*)d_in[4];
    const float* g1   = (const float*)d_in[5];
    const float* be1  = (const float*)d_in[6];
    const float* w2   = (const float*)d_in[7];
    const float* b2   = (const float*)d_in[8];
    const float* g2   = (const float*)d_in[9];
    const float* be2  = (const float*)d_in[10];
    const float* ptim = (const float*)d_in[11];
    const float* pw1  = (const float*)d_in[12];
    const float* pb1  = (const float*)d_in[13];
    const float* pg1  = (const float*)d_in[14];
    const float* pbe1 = (const float*)d_in[15];
    const float* pw2  = (const float*)d_in[16];
    const float* pb2  = (const float*)d_in[17];
    const float* pg2  = (const float*)d_in[18];
    const float* pbe2 = (const float*)d_in[19];
    const float* wo1  = (const float*)d_in[20];
    const float* bo1  = (const float*)d_in[21];
    const float* go1  = (const float*)d_in[22];
    const float* beo1 = (const float*)d_in[23];
    const float* wo2  = (const float*)d_in[24];
    const float* bo2  = (const float*)d_in[25];
    float* outp = (float*)d_out;

    void* p;
    float *pY1,*pY2,*pH,*pHS,*pYa,*pYb;
    __nv_bfloat16 *pw1hi,*pw1lo,*pw2hi,*pw2lo,*ppw1hi,*ppw1lo,*ppw2hi,*ppw2lo,*pwo1hi,*pwo1lo;
    __nv_bfloat16 *pevhi,*pevlo,*phhi,*phlo,*pThi,*pTlo;
    cudaGetSymbolAddress(&p, g_Y1); pY1=(float*)p;
    cudaGetSymbolAddress(&p, g_Y2); pY2=(float*)p;
    cudaGetSymbolAddress(&p, g_H ); pH =(float*)p;
    cudaGetSymbolAddress(&p, g_HS); pHS=(float*)p;
    cudaGetSymbolAddress(&p, g_Ya); pYa=(float*)p;
    cudaGetSymbolAddress(&p, g_Yb); pYb=(float*)p;
    cudaGetSymbolAddress(&p, w1s_hi); pw1hi=(__nv_bfloat16*)p;
    cudaGetSymbolAddress(&p, w1s_lo); pw1lo=(__nv_bfloat16*)p;
    cudaGetSymbolAddress(&p, w2s_hi); pw2hi=(__nv_bfloat16*)p;
    cudaGetSymbolAddress(&p, w2s_lo); pw2lo=(__nv_bfloat16*)p;
    cudaGetSymbolAddress(&p, pw1s_hi); ppw1hi=(__nv_bfloat16*)p;
    cudaGetSymbolAddress(&p, pw1s_lo); ppw1lo=(__nv_bfloat16*)p;
    cudaGetSymbolAddress(&p, pw2s_hi); ppw2hi=(__nv_bfloat16*)p;
    cudaGetSymbolAddress(&p, pw2s_lo); ppw2lo=(__nv_bfloat16*)p;
    cudaGetSymbolAddress(&p, wo1s_hi); pwo1hi=(__nv_bfloat16*)p;
    cudaGetSymbolAddress(&p, wo1s_lo); pwo1lo=(__nv_bfloat16*)p;
    cudaGetSymbolAddress(&p, g_evhi); pevhi=(__nv_bfloat16*)p;
    cudaGetSymbolAddress(&p, g_evlo); pevlo=(__nv_bfloat16*)p;
    cudaGetSymbolAddress(&p, g_hhi ); phhi=(__nv_bfloat16*)p;
    cudaGetSymbolAddress(&p, g_hlo ); phlo=(__nv_bfloat16*)p;
    cudaGetSymbolAddress(&p, g_Thi ); pThi=(__nv_bfloat16*)p;
    cudaGetSymbolAddress(&p, g_Tlo ); pTlo=(__nv_bfloat16*)p;

    const int GSM = 2*SMBUF + 1024;
    const int SSM = 2*SSMBUF;
    cudaFuncSetAttribute(gemm5<0,true ,false>, cudaFuncAttributeMaxDynamicSharedMemorySize, GSM);
    cudaFuncSetAttribute(gemm5<1,true ,false>, cudaFuncAttributeMaxDynamicSharedMemorySize, GSM);
    cudaFuncSetAttribute(gemm5<6,false,true >, cudaFuncAttributeMaxDynamicSharedMemorySize, GSM);
    cudaFuncSetAttribute(gemm5<5,true ,false>, cudaFuncAttributeMaxDynamicSharedMemorySize, GSM);
    cudaFuncSetAttribute(gemm5<3,true ,false>, cudaFuncAttributeMaxDynamicSharedMemorySize, GSM);
    cudaFuncSetAttribute(spec5, cudaFuncAttributeMaxDynamicSharedMemorySize, SSM);

    zero_kernel<<<1, 64>>>(outp, 64);
    zero_stats<<<1,256>>>();

    // ---- prep ----
    split_w1<<<64*128/256, 256>>>(w1);
    split_mat<<<(128*256+255)/256, 256>>>(w2, pw2hi, pw2lo, 128*256);
    split_mat<<<(3*256*128+255)/256, 256>>>(pw1, ppw1hi, ppw1lo, 3*256*128);
    split_mat<<<(3*128*128+255)/256, 256>>>(pw2, ppw2hi, ppw2lo, 3*128*128);
    split_mat<<<(128*128+255)/256, 256>>>(wo1, pwo1hi, pwo1lo, 128*128);
    split_eigs_k<<<(unsigned)(((size_t)B_*V_*K_)/256), 256>>>(eigs);

    // ---- chem MLP stage 1 (ks-skip saves 25% of its MMAs) ----
    gemm5<0,true,false><<<dim3(1, E_/128, 1), 256, GSM>>>(
        chem, nullptr, nullptr, nullptr, nullptr, pw1hi, pw1lo, nullptr, nullptr,
        b1, pY1, nullptr, nullptr, CF_, 128, CF_, 0, 0, 0, nullptr, nullptr, 0);
    finalize_bn<<<1,128>>>(g1, be1, 1.f/(float)E_);

    // ---- stage 2 (R7 shape: occupancy-2, x-split 2) ----
    gemm5<1,true,false><<<dim3(2, E_/128, 1), 256, GSM>>>(
        pY1, nullptr, nullptr, nullptr, nullptr, pw2hi, pw2lo, nullptr, nullptr,
        b2, pY2, nullptr, nullptr, 128, 256, 128, 0, 0, 0, nullptr, nullptr, 0);
    finalize_bn<<<1,256>>>(g2, be2, 1.f/(float)E_);

    // ---- message + segment_sum ----
    zero_kernel<<<(unsigned)(((size_t)N_*H_)/256), 256>>>(pH, (size_t)N_*H_);
    msg_scatter<<<E_/32, 128>>>(pY2, vid, pH);
    split_H<<<(unsigned)(((size_t)N_*H_)/256), 256>>>(pH);

    // ---- propagation layers ----
    for (int l = 0; l < L_; l++){
        zero_kernel<<<(B_*K_*H_+255)/256, 256>>>(pHS, (size_t)B_*K_*H_);
        spec5<<<dim3(SPLITV, 1, B_), 256, SSM>>>(pHS);
        // T[b] = (coeff .* HS[b]) @ W1b   (coeff fused into A loader)
        gemm5<6,false,true><<<dim3(1, 1, B_), 256, GSM>>>(
            pHS, nullptr, nullptr, nullptr, nullptr,
            ppw1hi + (size_t)l*256*128 + 128*128, ppw1lo + (size_t)l*256*128 + 128*128,
            nullptr, nullptr, nullptr, nullptr, pThi, pTlo,
            128, 128, 128, 0, 0, (size_t)K_*H_, eigs, ptim, l);
        // zMLP1: Ya = h @ W1a + evecs @ T[b] + pb1[l]
        gemm5<5,true,false><<<dim3(1, N_/128, 1), 256, GSM>>>(
            nullptr, phhi, phlo, pevhi, pevlo,
            ppw1hi + (size_t)l*256*128, ppw1lo + (size_t)l*256*128, pThi, pTlo,
            pb1 + l*H_, pYa, nullptr, nullptr, 256, 128, 128, 0, 0, 0, nullptr, nullptr, 0);
        finalize_bn<<<1,128>>>(pg1 + l*H_, pbe1 + l*H_, 1.f/(float)N_);
        // zMLP2: Yb = silu(bn(Ya)) @ pw2[l] + pb2[l]
        gemm5<1,true,false><<<dim3(1, N_/128, 1), 256, GSM>>>(
            pYa, nullptr, nullptr, nullptr, nullptr,
            ppw2hi + (size_t)l*128*128, ppw2lo + (size_t)l*128*128, nullptr, nullptr,
            pb2 + l*H_, pYb, nullptr, nullptr, 128, 128, 128, 0, 0, 0, nullptr, nullptr, 0);
        finalize_bn<<<1,128>>>(pg2 + l*H_, pbe2 + l*H_, 1.f/(float)N_);
        h_update_split<<<(unsigned)(((size_t)N_*H_)/256), 256>>>(pH, pYb);
    }

    // ---- output head ----
    gemm5<3,true,false><<<dim3(1, N_/128, 1), 256, GSM>>>(
        nullptr, phhi, phlo, nullptr, nullptr, pwo1hi, pwo1lo, nullptr, nullptr,
        bo1, pYa, nullptr, nullptr, 128, 128, 128, 0, 0, 0, nullptr, nullptr, 0);
    finalize_bn<<<1,128>>>(go1, beo1, 1.f/(float)N_);
    out_reduce<<<N_/8, 256>>>(pYa, wo2, bo2, outp);
}

// round 10
// speedup vs baseline: 1.1506x; 1.1188x over previous
#include <cuda_runtime.h>
#include <cuda_fp16.h>
#include <cstdint>

// ---------------- problem constants ----------------
#define B_   64
#define V_   2048
#define K_   128
#define H_   128
#define N_   (B_*V_)
#define E_   1048576
#define CF_  47
#define L_   3
#define EPSF 1e-5f
#define SPLITV 4

// ---------------- scratch ----------------
__device__ float g_Y1[(size_t)E_*H_];
__device__ float g_Y2[(size_t)E_*2*H_];
__device__ float g_H [(size_t)N_*H_];
__device__ float g_HS[(size_t)B_*K_*H_];
__device__ float g_Ya[(size_t)N_*H_];
__device__ float g_Yb[(size_t)N_*H_];
__device__ float g_sum[256], g_sumsq[256], g_scale[256], g_shift[256];
// pre-split fp16 operands: A-side need hi+lo, B-side hi only
__device__ __half w1s_hi[64*128];
__device__ __half w2s_hi[128*256];
__device__ __half pw1s_hi[3*256*128];
__device__ __half pw2s_hi[3*128*128];
__device__ __half wo1s_hi[128*128];
__device__ __half g_evhi[(size_t)B_*V_*K_], g_evlo[(size_t)B_*V_*K_];
__device__ __half g_eihi[(size_t)B_*V_*K_], g_eilo[(size_t)B_*V_*K_];
__device__ __half g_hhi [(size_t)N_*H_],    g_hlo [(size_t)N_*H_];
__device__ __half g_Thi [(size_t)B_*K_*H_];

// ---------------- helpers ----------------
__device__ __forceinline__ float siluf(float x){ return x * (1.f/(1.f+__expf(-x))); }
__device__ __forceinline__ float softplusf(float x){ return x > 20.f ? x : log1pf(__expf(x)); }
__device__ __forceinline__ void red_add_v4(float* a, float x, float y, float z, float w){
    asm volatile("red.global.add.v4.f32 [%0], {%1,%2,%3,%4};"
                 :: "l"(a), "f"(x), "f"(y), "f"(z), "f"(w) : "memory");
}
__device__ __forceinline__ void red_add_v2(float* a, float x, float y){
    asm volatile("red.global.add.v2.f32 [%0], {%1,%2};" :: "l"(a), "f"(x), "f"(y) : "memory");
}
__device__ __forceinline__ uint32_t smem_u32(const void* p){
    uint32_t a;
    asm("{ .reg .u64 t; cvta.to.shared.u64 t, %1; cvt.u32.u64 %0, t; }" : "=r"(a) : "l"(p));
    return a;
}
__device__ __forceinline__ void cpasync16(uint32_t s, const void* g){
    asm volatile("cp.async.ca.shared.global [%0], [%1], 16;" :: "r"(s), "l"(g));
}
#define CP_COMMIT() asm volatile("cp.async.commit_group;")
#define CP_WAIT0()  asm volatile("cp.async.wait_group 0;")

__device__ __forceinline__ void ldsm4(uint32_t* r, uint32_t addr){
    asm volatile("ldmatrix.sync.aligned.m8n8.x4.shared.b16 {%0,%1,%2,%3}, [%4];"
        : "=r"(r[0]),"=r"(r[1]),"=r"(r[2]),"=r"(r[3]) : "r"(addr));
}
__device__ __forceinline__ void ldsm4t(uint32_t* r, uint32_t addr){
    asm volatile("ldmatrix.sync.aligned.m8n8.x4.trans.shared.b16 {%0,%1,%2,%3}, [%4];"
        : "=r"(r[0]),"=r"(r[1]),"=r"(r[2]),"=r"(r[3]) : "r"(addr));
}
__device__ __forceinline__ void mma16816(float* d, const uint32_t* a, uint32_t b0, uint32_t b1){
    asm volatile("mma.sync.aligned.m16n8k16.row.col.f32.f16.f16.f32 "
        "{%0,%1,%2,%3}, {%4,%5,%6,%7}, {%8,%9}, {%0,%1,%2,%3};"
        : "+f"(d[0]),"+f"(d[1]),"+f"(d[2]),"+f"(d[3])
        : "r"(a[0]),"r"(a[1]),"r"(a[2]),"r"(a[3]), "r"(b0),"r"(b1));
}

// split fp32 -> fp16 hi/lo, 8 elements -> two uint4 (packed half2)
__device__ __forceinline__ void split8h(const float* f, uint4& hi, uint4& lo){
    unsigned h[4], l[4];
    #pragma unroll
    for (int p=0;p<4;p++){
        float2 a = make_float2(f[2*p], f[2*p+1]);
        __half2 hh = __float22half2_rn(a);
        float2 hf = __half22float2(hh);
        __half2 ll = __float22half2_rn(make_float2(a.x - hf.x, a.y - hf.y));
        h[p] = *reinterpret_cast<unsigned*>(&hh);
        l[p] = *reinterpret_cast<unsigned*>(&ll);
    }
    hi = make_uint4(h[0],h[1],h[2],h[3]);
    lo = make_uint4(l[0],l[1],l[2],l[3]);
}
__device__ __forceinline__ void split1h(float v, __half& hi, __half& lo){
    hi = __float2half_rn(v);
    lo = __float2half_rn(v - __half2float(hi));
}

__global__ void zero_kernel(float* __restrict__ p, size_t n){
    size_t i = (size_t)blockIdx.x*blockDim.x + threadIdx.x;
    if (i < n) p[i] = 0.f;
}
__global__ void zero_stats(){ g_sum[threadIdx.x]=0.f; g_sumsq[threadIdx.x]=0.f; }

// ---------------- prep: split kernels ----------------
__global__ void split_mat_hi(const float* __restrict__ src, __half* __restrict__ hi, size_t n){
    size_t i = (size_t)blockIdx.x*256 + threadIdx.x;
    if (i < n) hi[i] = __float2half_rn(src[i]);
}
__global__ void split_w1(const float* __restrict__ w1){
    int i = blockIdx.x*256 + threadIdx.x;
    int k = i >> 7, n = i & 127;
    float v = (k < CF_) ? w1[k*128 + n] : 0.f;
    w1s_hi[i] = __float2half_rn(v);
}
__global__ void split_eigs_k(const float* __restrict__ eigs){
    size_t i = (size_t)blockIdx.x*256 + threadIdx.x;
    size_t b = i >> 18, rem = i & 0x3FFFF;
    const float* base = eigs + (b*(size_t)(2*V_+1) + 1)*K_;
    __half h, l;
    split1h(base[rem], h, l);                 g_evhi[i]=h; g_evlo[i]=l;
    split1h(base[(size_t)V_*K_ + rem], h, l); g_eihi[i]=h; g_eilo[i]=l;
}

// ================= pipelined HMMA fp16 2-term GEMM =================
// D = Ah*Bh + Al*Bh (A split fp16, B hi-only fp16)
// ASRC 0: A fp32 plain, guarded scalar loads (GEMM1, Kd=47; skips all-zero k16 steps)
// ASRC 1: A fp32, silu(A*scale+shift)
// ASRC 3: A pre-split fp16
// ASRC 5: dual concat: kc<4 -> (h @ Bhi); kc>=4 -> (evecs[batch] @ B2hi[batch])
// ASRC 6: A fp32 * exp(-eig[row]*t[col])  (coeff-fused T-gemm)
#define APITCH 80
#define BPITCH 272
#define SMBUF  29184   // Ahi 10240 | Alo 10240 | Bhi 8704
template<int ASRC, bool STATS, bool OUTSPLIT>
__global__ void __launch_bounds__(256,2) gemm5(
    const float* __restrict__ Af,
    const __half* __restrict__ Ahi, const __half* __restrict__ Alo,
    const __half* __restrict__ A2hi, const __half* __restrict__ A2lo,
    const __half* __restrict__ Bhi, const __half* __restrict__ B2hi,
    const float* __restrict__ bias, float* __restrict__ C,
    __half* __restrict__ Chi,
    int Kd, int Nd, int lda,
    size_t sAs, size_t sBs, size_t sC,
    const float* __restrict__ eigsp, const float* __restrict__ ptp, int lidx)
{
    extern __shared__ __align__(16) uint8_t smem[];
    const uint32_t sb = smem_u32(smem);
    const int tid = threadIdx.x;
    const int lane = tid & 31, wid = tid >> 5;
    const int warpm = wid & 3, warpn = wid >> 2;
    const int brow = blockIdx.y * 128;
    const int bcol = blockIdx.x * 128;
    const int bz   = blockIdx.z;
    Ahi += sAs*bz; Alo += sAs*bz; Bhi += sBs*bz;
    if (ASRC == 6) Af += (size_t)K_*H_*bz;
    if (C)   C   += sC*bz;
    if (Chi) Chi += sC*bz;
    const int bb = brow >> 11;
    const size_t a2base = (size_t)bb*V_*K_ + (size_t)(brow & 2047)*K_;
    const size_t b2base = (size_t)bb*K_*H_;

    const int nch = (Kd + 31) >> 5;

    const int ar = tid >> 1, akh = (tid & 1) * 16;
    const int bkr = tid >> 3, bns = (tid & 7) * 16;

    auto stageB = [&](int kc, int buf){
        const __half* shi; size_t so;
        if (ASRC == 5 && kc >= 4){
            const int gk = (kc & 3)*32 + bkr;
            shi = B2hi + b2base;
            so = (size_t)gk*128 + bns;
        } else {
            const int gk = kc*32 + bkr;
            shi = Bhi;
            so = (size_t)gk*Nd + bcol + bns;
        }
        const uint32_t dst = sb + buf*SMBUF + 20480 + bkr*BPITCH + bns*2;
        cpasync16(dst,      shi + so);
        cpasync16(dst + 16, shi + so + 8);
    };
    auto stageA_async = [&](int kc, int buf){
        const __half *hi, *lo; size_t so;
        if (ASRC == 5){
            if (kc < 4){ hi = Ahi; lo = Alo; so = (size_t)(brow+ar)*128 + kc*32 + akh; }
            else { hi = A2hi + a2base; lo = A2lo + a2base;
                   so = (size_t)ar*K_ + (kc & 3)*32 + akh; }
        } else {
            hi = Ahi; lo = Alo;
            so = (size_t)(brow + ar)*lda + kc*32 + akh;
        }
        const uint32_t dst = sb + buf*SMBUF + ar*APITCH + akh*2;
        cpasync16(dst,              hi + so);
        cpasync16(dst + 16,         hi + so + 8);
        cpasync16(dst + 10240,      lo + so);
        cpasync16(dst + 10240 + 16, lo + so + 8);
    };
    auto loadA_f32 = [&](int kc, float* av){
        if (ASRC == 1 || ASRC == 6){
            const float* S = Af + (size_t)(brow+ar)*lda + kc*32 + akh;
            #pragma unroll
            for (int q=0;q<4;q++) *reinterpret_cast<float4*>(&av[q*4]) =
                *reinterpret_cast<const float4*>(S + q*4);
        } else {
            #pragma unroll
            for (int j=0;j<16;j++){
                const int k = kc*32 + akh + j;
                av[j] = (k < Kd) ? Af[(size_t)(brow+ar)*lda + k] : 0.f;
            }
        }
    };
    auto storeA_f32 = [&](int kc, int buf, float* av){
        if (ASRC == 1){
            #pragma unroll
            for (int j=0;j<16;j++){
                const int k = kc*32 + akh + j;
                av[j] = siluf(av[j]*g_scale[k] + g_shift[k]);
            }
        }
        if (ASRC == 6){
            const float eig_a = eigsp[(size_t)bz*(2*V_+1)*K_ + brow + ar];
            #pragma unroll
            for (int j=0;j<16;j++){
                const int k = kc*32 + akh + j;
                av[j] *= __expf(-eig_a * fmaxf(ptp[lidx*H_ + k], 1e-6f));
            }
        }
        uint4 h0,l0,h1,l1;
        split8h(&av[0], h0, l0);
        split8h(&av[8], h1, l1);
        uint8_t* base = smem + buf*SMBUF + ar*APITCH + akh*2;
        *reinterpret_cast<uint4*>(base)              = h0;
        *reinterpret_cast<uint4*>(base + 16)         = h1;
        *reinterpret_cast<uint4*>(base + 10240)      = l0;
        *reinterpret_cast<uint4*>(base + 10240 + 16) = l1;
    };

    constexpr bool A_F32 = (ASRC == 0) || (ASRC == 1) || (ASRC == 6);

    float d[2][8][4];
    #pragma unroll
    for (int i=0;i<2;i++)
        #pragma unroll
        for (int j=0;j<8;j++)
            #pragma unroll
            for (int q=0;q<4;q++) d[i][j][q] = 0.f;

    float av[16];
    stageB(0, 0);
    if (A_F32){ loadA_f32(0, av); storeA_f32(0, 0, av); }
    else       stageA_async(0, 0);
    CP_COMMIT();
    CP_WAIT0();
    __syncthreads();

    for (int kc = 0; kc < nch; kc++){
        const int cur = kc & 1, nxt = cur ^ 1;
        const bool more = (kc + 1 < nch);
        if (more){
            stageB(kc+1, nxt);
            if (!A_F32) stageA_async(kc+1, nxt);
            CP_COMMIT();
            if (A_F32) loadA_f32(kc+1, av);
        }
        const uint32_t aHi = sb + cur*SMBUF;
        const uint32_t aLo = aHi + 10240;
        const uint32_t bHi = aHi + 20480;
        #pragma unroll
        for (int ks=0; ks<2; ks++){
            // compile-time true for all ASRC != 0 (Kd multiple of 32 there)
            if (ASRC != 0 || kc*32 + ks*16 < Kd){
                uint32_t ah[2][4], al[2][4];
                #pragma unroll
                for (int mb=0; mb<2; mb++){
                    const uint32_t ao = (uint32_t)(warpm*32 + mb*16 + (lane & 15))*APITCH
                                      + ks*32 + ((lane >> 4)*16);
                    ldsm4(ah[mb], aHi + ao);
                    ldsm4(al[mb], aLo + ao);
                }
                #pragma unroll
                for (int np=0; np<4; np++){
                    const int n0 = warpn*64 + np*16;
                    const uint32_t bo = (uint32_t)(ks*16 + (lane & 15))*BPITCH
                                      + (uint32_t)n0*2 + ((lane >> 4)*16);
                    uint32_t bh[4];
                    ldsm4t(bh, bHi + bo);
                    #pragma unroll
                    for (int mb=0; mb<2; mb++){
                        mma16816(d[mb][np*2  ], ah[mb], bh[0], bh[1]);
                        mma16816(d[mb][np*2  ], al[mb], bh[0], bh[1]);
                        mma16816(d[mb][np*2+1], ah[mb], bh[2], bh[3]);
                        mma16816(d[mb][np*2+1], al[mb], bh[2], bh[3]);
                    }
                }
            }
        }
        if (more){
            if (A_F32) storeA_f32(kc+1, nxt, av);
            CP_WAIT0();
        }
        __syncthreads();
    }

    #pragma unroll
    for (int mb=0; mb<2; mb++){
        #pragma unroll
        for (int nb=0; nb<8; nb++){
            const int m = brow + warpm*32 + mb*16 + (lane >> 2);
            const int n = bcol + warpn*64 + nb*8 + (lane & 3)*2;
            float b0 = 0.f, b1 = 0.f;
            if (bias){ b0 = bias[n]; b1 = bias[n+1]; }
            d[mb][nb][0] += b0; d[mb][nb][1] += b1;
            d[mb][nb][2] += b0; d[mb][nb][3] += b1;
            if (OUTSPLIT){
                __half2 h2 = __float22half2_rn(make_float2(d[mb][nb][0], d[mb][nb][1]));
                *reinterpret_cast<__half2*>(Chi + (size_t)m*Nd + n) = h2;
                __half2 h3 = __float22half2_rn(make_float2(d[mb][nb][2], d[mb][nb][3]));
                *reinterpret_cast<__half2*>(Chi + (size_t)(m+8)*Nd + n) = h3;
            } else {
                *reinterpret_cast<float2*>(C + (size_t)m*Nd + n) =
                    make_float2(d[mb][nb][0], d[mb][nb][1]);
                *reinterpret_cast<float2*>(C + (size_t)(m+8)*Nd + n) =
                    make_float2(d[mb][nb][2], d[mb][nb][3]);
            }
        }
    }

    if (STATS){
        float* sred = reinterpret_cast<float*>(smem + 2*SMBUF);
        sred[tid] = 0.f;
        __syncthreads();
        float s[16], q[16];
        #pragma unroll
        for (int i=0;i<16;i++){ s[i]=0.f; q[i]=0.f; }
        #pragma unroll
        for (int mb=0; mb<2; mb++)
            #pragma unroll
            for (int nb=0; nb<8; nb++){
                s[nb*2+0] += d[mb][nb][0] + d[mb][nb][2];
                s[nb*2+1] += d[mb][nb][1] + d[mb][nb][3];
                q[nb*2+0] += d[mb][nb][0]*d[mb][nb][0] + d[mb][nb][2]*d[mb][nb][2];
                q[nb*2+1] += d[mb][nb][1]*d[mb][nb][1] + d[mb][nb][3]*d[mb][nb][3];
            }
        #pragma unroll
        for (int off=4; off<32; off<<=1){
            #pragma unroll
            for (int i=0;i<16;i++){
                s[i] += __shfl_xor_sync(0xFFFFFFFFu, s[i], off);
                q[i] += __shfl_xor_sync(0xFFFFFFFFu, q[i], off);
            }
        }
        if (lane < 4){
            #pragma unroll
            for (int i=0;i<16;i++){
                const int col = warpn*64 + (i>>1)*8 + (lane & 3)*2 + (i & 1);
                atomicAdd(&sred[col], s[i]);
                atomicAdd(&sred[128+col], q[i]);
            }
        }
        __syncthreads();
        if (tid < 128){
            atomicAdd(&g_sum  [bcol + tid], sred[tid]);
            atomicAdd(&g_sumsq[bcol + tid], sred[128 + tid]);
        }
    }
}

// ================= spectral forward (fp16 2-term, 256 blocks, red.add) =================
#define SSMBUF 26112   // Ahi 8704 | Alo 8704 | Bhi 8704
__global__ void __launch_bounds__(256,2) spec5(float* __restrict__ HS)
{
    extern __shared__ __align__(16) uint8_t smem[];
    const uint32_t sb = smem_u32(smem);
    const int b   = blockIdx.z;
    const int seg = blockIdx.x;
    const __half* Ahi = g_eihi + (size_t)b*V_*K_;
    const __half* Alo = g_eilo + (size_t)b*V_*K_;
    const __half* Bhi = g_hhi  + (size_t)b*V_*H_;

    const int tid = threadIdx.x;
    const int lane = tid & 31, wid = tid >> 5;
    const int warpm = wid & 3, warpn = wid >> 2;
    const int vr = tid >> 3, cs = (tid & 7) * 16;
    const int v0 = seg * (V_/SPLITV);
    const int nch = V_/SPLITV/32;   // 16

    auto stage = [&](int vc, int buf){
        const int v = v0 + vc*32 + vr;
        const size_t soA = (size_t)v*K_ + cs;
        const size_t soB = (size_t)v*H_ + cs;
        const uint32_t base = sb + buf*SSMBUF + vr*BPITCH + cs*2;
        cpasync16(base,              Ahi + soA);
        cpasync16(base + 16,         Ahi + soA + 8);
        cpasync16(base + 8704,       Alo + soA);
        cpasync16(base + 8704 + 16,  Alo + soA + 8);
        cpasync16(base + 17408,      Bhi + soB);
        cpasync16(base + 17408 + 16, Bhi + soB + 8);
    };

    float d[2][8][4];
    #pragma unroll
    for (int i=0;i<2;i++)
        #pragma unroll
        for (int j=0;j<8;j++)
            #pragma unroll
            for (int q=0;q<4;q++) d[i][j][q] = 0.f;

    stage(0, 0);
    CP_COMMIT();
    CP_WAIT0();
    __syncthreads();

    for (int vc = 0; vc < nch; vc++){
        const int cur = vc & 1, nxt = cur ^ 1;
        const bool more = (vc + 1 < nch);
        if (more){ stage(vc+1, nxt); CP_COMMIT(); }

        const uint32_t aHi = sb + cur*SSMBUF;
        const uint32_t aLo = aHi + 8704;
        const uint32_t bHi = aHi + 17408;
        #pragma unroll
        for (int ks=0; ks<2; ks++){
            uint32_t ah[2][4], al[2][4];
            #pragma unroll
            for (int mb=0; mb<2; mb++){
                const uint32_t ao = (uint32_t)(ks*16 + (lane & 7) + ((lane >> 4)*8))*BPITCH
                                  + (uint32_t)(warpm*32 + mb*16)*2 + (((lane >> 3) & 1)*16);
                ldsm4t(ah[mb], aHi + ao);
                ldsm4t(al[mb], aLo + ao);
            }
            #pragma unroll
            for (int np=0; np<4; np++){
                const int n0 = warpn*64 + np*16;
                const uint32_t bo = (uint32_t)(ks*16 + (lane & 15))*BPITCH
                                  + (uint32_t)n0*2 + ((lane >> 4)*16);
                uint32_t bh[4];
                ldsm4t(bh, bHi + bo);
                #pragma unroll
                for (int mb=0; mb<2; mb++){
                    mma16816(d[mb][np*2  ], ah[mb], bh[0], bh[1]);
                    mma16816(d[mb][np*2  ], al[mb], bh[0], bh[1]);
                    mma16816(d[mb][np*2+1], ah[mb], bh[2], bh[3]);
                    mma16816(d[mb][np*2+1], al[mb], bh[2], bh[3]);
                }
            }
        }
        if (more) CP_WAIT0();
        __syncthreads();
    }

    float* Cb = HS + (size_t)b*K_*H_;
    #pragma unroll
    for (int mb=0; mb<2; mb++)
        #pragma unroll
        for (int nb=0; nb<8; nb++){
            const int m = warpm*32 + mb*16 + (lane >> 2);
            const int n = warpn*64 + nb*8 + (lane & 3)*2;
            red_add_v2(Cb + (size_t)m*H_ + n,     d[mb][nb][0], d[mb][nb][1]);
            red_add_v2(Cb + (size_t)(m+8)*H_ + n, d[mb][nb][2], d[mb][nb][3]);
        }
}

// finalize BN coeffs; zeroes stats for next accumulation
__global__ void finalize_bn(const float* __restrict__ g, const float* __restrict__ be, float Rinv){
    const int c = threadIdx.x;
    const float m   = g_sum[c]*Rinv;
    const float var = g_sumsq[c]*Rinv - m*m;
    const float sc  = g[c] * rsqrtf(var + EPSF);
    g_scale[c] = sc;
    g_shift[c] = be[c] - m*sc;
    g_sum[c] = 0.f;
    g_sumsq[c] = 0.f;
}

// ---------------- message + scatter-add ----------------
__global__ void msg_scatter(const float* __restrict__ Y2, const int* __restrict__ vid,
                            float* __restrict__ Hout)
{
    const int sub = threadIdx.x >> 5;
    const int c4  = (threadIdx.x & 31) * 4;
    const int e0  = blockIdx.x * 32 + sub * 8;
    const float s0=g_scale[c4],   s1=g_scale[c4+1],   s2=g_scale[c4+2],   s3=g_scale[c4+3];
    const float t0=g_shift[c4],   t1=g_shift[c4+1],   t2=g_shift[c4+2],   t3=g_shift[c4+3];
    const float u0=g_scale[128+c4],u1=g_scale[129+c4],u2=g_scale[130+c4],u3=g_scale[131+c4];
    const float w0=g_shift[128+c4],w1=g_shift[129+c4],w2=g_shift[130+c4],w3=g_shift[131+c4];
    #pragma unroll
    for (int i=0;i<8;i++){
        const int e = e0 + i;
        float4 f = *reinterpret_cast<const float4*>(Y2 + (size_t)e*256 + c4);
        float4 c = *reinterpret_cast<const float4*>(Y2 + (size_t)e*256 + 128 + c4);
        float m0 = (1.f/(1.f+__expf(-(f.x*s0+t0)))) * softplusf(c.x*u0+w0);
        float m1 = (1.f/(1.f+__expf(-(f.y*s1+t1)))) * softplusf(c.y*u1+w1);
        float m2 = (1.f/(1.f+__expf(-(f.z*s2+t2)))) * softplusf(c.z*u2+w2);
        float m3 = (1.f/(1.f+__expf(-(f.w*s3+t3)))) * softplusf(c.w*u3+w3);
        const int v = vid[e];
        red_add_v4(Hout + (size_t)v*128 + c4, m0, m1, m2, m3);
    }
}

// h += bn(Y); also emit split H (fp16 hi/lo)
__global__ void h_update_split(float* __restrict__ H, const float* __restrict__ Y){
    const size_t i = (size_t)blockIdx.x*256 + threadIdx.x;
    const int c = (int)(i & 127);
    const float v = H[i] + Y[i]*g_scale[c] + g_shift[c];
    H[i] = v;
    __half hi, lo; split1h(v, hi, lo);
    g_hhi[i] = hi; g_hlo[i] = lo;
}
__global__ void split_H(const float* __restrict__ H){
    const size_t i = (size_t)blockIdx.x*256 + threadIdx.x;
    __half hi, lo; split1h(H[i], hi, lo);
    g_hhi[i] = hi; g_hlo[i] = lo;
}

// out[b] += mean_v( silu(bn(Yo)) . wo2 + bo2 )
__global__ void out_reduce(const float* __restrict__ Yo, const float* __restrict__ wo2,
                           const float* __restrict__ bo2, float* __restrict__ out)
{
    const int warp = threadIdx.x >> 5, lane = threadIdx.x & 31;
    const long n = (long)blockIdx.x*8 + warp;
    float s = 0.f;
    #pragma unroll
    for (int j=0;j<4;j++){
        const int h = lane + j*32;
        float x = Yo[(size_t)n*128 + h]*g_scale[h] + g_shift[h];
        x = siluf(x);
        s += x * wo2[h];
    }
    #pragma unroll
    for (int o=16;o>0;o>>=1) s += __shfl_xor_sync(0xFFFFFFFFu, s, o);
    if (lane == 0){
        const int b = (int)(n >> 11);
        atomicAdd(&out[b], (s + bo2[0]) * (1.f/(float)V_));
    }
}

// ---------------- launcher ----------------
extern "C" void kernel_launch(void* const* d_in, const int* in_sizes, int n_in,
                              void* d_out, int out_size)
{
    const float* chem = (const float*)d_in[0];
    const int*   vid  = (const int*  )d_in[1];
    const float* eigs = (const float*)d_in[2];
    const float* w1   = (const float*)d_in[3];
    const float* b1   = (const float*)d_in[4];
    const float* g1   = (const float*)d_in[5];
    const float* be1  = (const float*)d_in[6];
    const float* w2   = (const float*)d_in[7];
    const float* b2   = (const float*)d_in[8];
    const float* g2   = (const float*)d_in[9];
    const float* be2  = (const float*)d_in[10];
    const float* ptim = (const float*)d_in[11];
    const float* pw1  = (const float*)d_in[12];
    const float* pb1  = (const float*)d_in[13];
    const float* pg1  = (const float*)d_in[14];
    const float* pbe1 = (const float*)d_in[15];
    const float* pw2  = (const float*)d_in[16];
    const float* pb2  = (const float*)d_in[17];
    const float* pg2  = (const float*)d_in[18];
    const float* pbe2 = (const float*)d_in[19];
    const float* wo1  = (const float*)d_in[20];
    const float* bo1  = (const float*)d_in[21];
    const float* go1  = (const float*)d_in[22];
    const float* beo1 = (const float*)d_in[23];
    const float* wo2  = (const float*)d_in[24];
    const float* bo2  = (const float*)d_in[25];
    float* outp = (float*)d_out;

    void* p;
    float *pY1,*pY2,*pH,*pHS,*pYa,*pYb;
    __half *pw1hi,*pw2hi,*ppw1hi,*ppw2hi,*pwo1hi;
    __half *pevhi,*pevlo,*phhi,*phlo,*pThi;
    cudaGetSymbolAddress(&p, g_Y1); pY1=(float*)p;
    cudaGetSymbolAddress(&p, g_Y2); pY2=(float*)p;
    cudaGetSymbolAddress(&p, g_H ); pH =(float*)p;
    cudaGetSymbolAddress(&p, g_HS); pHS=(float*)p;
    cudaGetSymbolAddress(&p, g_Ya); pYa=(float*)p;
    cudaGetSymbolAddress(&p, g_Yb); pYb=(float*)p;
    cudaGetSymbolAddress(&p, w1s_hi); pw1hi=(__half*)p;
    cudaGetSymbolAddress(&p, w2s_hi); pw2hi=(__half*)p;
    cudaGetSymbolAddress(&p, pw1s_hi); ppw1hi=(__half*)p;
    cudaGetSymbolAddress(&p, pw2s_hi); ppw2hi=(__half*)p;
    cudaGetSymbolAddress(&p, wo1s_hi); pwo1hi=(__half*)p;
    cudaGetSymbolAddress(&p, g_evhi); pevhi=(__half*)p;
    cudaGetSymbolAddress(&p, g_evlo); pevlo=(__half*)p;
    cudaGetSymbolAddress(&p, g_hhi ); phhi=(__half*)p;
    cudaGetSymbolAddress(&p, g_hlo ); phlo=(__half*)p;
    cudaGetSymbolAddress(&p, g_Thi ); pThi=(__half*)p;

    const int GSM = 2*SMBUF + 1024;   // 59392
    const int SSM = 2*SSMBUF;         // 52224
    cudaFuncSetAttribute(gemm5<0,true ,false>, cudaFuncAttributeMaxDynamicSharedMemorySize, GSM);
    cudaFuncSetAttribute(gemm5<1,true ,false>, cudaFuncAttributeMaxDynamicSharedMemorySize, GSM);
    cudaFuncSetAttribute(gemm5<6,false,true >, cudaFuncAttributeMaxDynamicSharedMemorySize, GSM);
    cudaFuncSetAttribute(gemm5<5,true ,false>, cudaFuncAttributeMaxDynamicSharedMemorySize, GSM);
    cudaFuncSetAttribute(gemm5<3,true ,false>, cudaFuncAttributeMaxDynamicSharedMemorySize, GSM);
    cudaFuncSetAttribute(spec5, cudaFuncAttributeMaxDynamicSharedMemorySize, SSM);

    zero_kernel<<<1, 64>>>(outp, 64);
    zero_stats<<<1,256>>>();

    // ---- prep ----
    split_w1<<<64*128/256, 256>>>(w1);
    split_mat_hi<<<(128*256+255)/256, 256>>>(w2, pw2hi, 128*256);
    split_mat_hi<<<(3*256*128+255)/256, 256>>>(pw1, ppw1hi, 3*256*128);
    split_mat_hi<<<(3*128*128+255)/256, 256>>>(pw2, ppw2hi, 3*128*128);
    split_mat_hi<<<(128*128+255)/256, 256>>>(wo1, pwo1hi, 128*128);
    split_eigs_k<<<(unsigned)(((size_t)B_*V_*K_)/256), 256>>>(eigs);

    // ---- chem MLP stage 1 (ks-skip) ----
    gemm5<0,true,false><<<dim3(1, E_/128, 1), 256, GSM>>>(
        chem, nullptr, nullptr, nullptr, nullptr, pw1hi, nullptr,
        b1, pY1, nullptr, CF_, 128, CF_, 0, 0, 0, nullptr, nullptr, 0);
    finalize_bn<<<1,128>>>(g1, be1, 1.f/(float)E_);

    // ---- stage 2 ----
    gemm5<1,true,false><<<dim3(2, E_/128, 1), 256, GSM>>>(
        pY1, nullptr, nullptr, nullptr, nullptr, pw2hi, nullptr,
        b2, pY2, nullptr, 128, 256, 128, 0, 0, 0, nullptr, nullptr, 0);
    finalize_bn<<<1,256>>>(g2, be2, 1.f/(float)E_);

    // ---- message + segment_sum ----
    zero_kernel<<<(unsigned)(((size_t)N_*H_)/256), 256>>>(pH, (size_t)N_*H_);
    msg_scatter<<<E_/32, 128>>>(pY2, vid, pH);
    split_H<<<(unsigned)(((size_t)N_*H_)/256), 256>>>(pH);

    // ---- propagation layers ----
    for (int l = 0; l < L_; l++){
        zero_kernel<<<(B_*K_*H_+255)/256, 256>>>(pHS, (size_t)B_*K_*H_);
        spec5<<<dim3(SPLITV, 1, B_), 256, SSM>>>(pHS);
        // T[b] = (coeff .* HS[b]) @ W1b   (coeff fused into A loader; T hi-only out)
        gemm5<6,false,true><<<dim3(1, 1, B_), 256, GSM>>>(
            pHS, nullptr, nullptr, nullptr, nullptr,
            ppw1hi + (size_t)l*256*128 + 128*128, nullptr,
            nullptr, nullptr, pThi,
            128, 128, 128, 0, 0, (size_t)K_*H_, eigs, ptim, l);
        // zMLP1: Ya = h @ W1a + evecs @ T[b] + pb1[l]
        gemm5<5,true,false><<<dim3(1, N_/128, 1), 256, GSM>>>(
            nullptr, phhi, phlo, pevhi, pevlo,
            ppw1hi + (size_t)l*256*128, pThi,
            pb1 + l*H_, pYa, nullptr, 256, 128, 128, 0, 0, 0, nullptr, nullptr, 0);
        finalize_bn<<<1,128>>>(pg1 + l*H_, pbe1 + l*H_, 1.f/(float)N_);
        // zMLP2: Yb = silu(bn(Ya)) @ pw2[l] + pb2[l]
        gemm5<1,true,false><<<dim3(1, N_/128, 1), 256, GSM>>>(
            pYa, nullptr, nullptr, nullptr, nullptr,
            ppw2hi + (size_t)l*128*128, nullptr,
            pb2 + l*H_, pYb, nullptr, 128, 128, 128, 0, 0, 0, nullptr, nullptr, 0);
        finalize_bn<<<1,128>>>(pg2 + l*H_, pbe2 + l*H_, 1.f/(float)N_);
        h_update_split<<<(unsigned)(((size_t)N_*H_)/256), 256>>>(pH, pYb);
    }

    // ---- output head ----
    gemm5<3,true,false><<<dim3(1, N_/128, 1), 256, GSM>>>(
        nullptr, phhi, phlo, nullptr, nullptr, pwo1hi, nullptr,
        bo1, pYa, nullptr, 128, 128, 128, 0, 0, 0, nullptr, nullptr, 0);
    finalize_bn<<<1,128>>>(go1, beo1, 1.f/(float)N_);
    out_reduce<<<N_/8, 256>>>(pYa, wo2, bo2, outp);
}

// round 11
// speedup vs baseline: 1.2425x; 1.0799x over previous
#include <cuda_runtime.h>
#include <cuda_fp16.h>
#include <cstdint>

// ---------------- problem constants ----------------
#define B_   64
#define V_   2048
#define K_   128
#define H_   128
#define N_   (B_*V_)
#define E_   1048576
#define CF_  47
#define L_   3
#define EPSF 1e-5f
#define SPLITV 4

// ---------------- scratch ----------------
__device__ float g_Y1[(size_t)E_*H_];
__device__ float g_Y2[(size_t)E_*2*H_];
__device__ float g_H [(size_t)N_*H_];
__device__ float g_HS[(size_t)B_*K_*H_];
__device__ float g_Ya[(size_t)N_*H_];
__device__ float g_Yb[(size_t)N_*H_];
__device__ float g_sum[256], g_sumsq[256], g_scale[256], g_shift[256];
// fp16 hi-only operands
__device__ __half w1s_hi[64*128];
__device__ __half w2s_hi[128*256];
__device__ __half pw1s_hi[3*256*128];
__device__ __half pw2s_hi[3*128*128];
__device__ __half wo1s_hi[128*128];
__device__ __half g_evhi[(size_t)B_*V_*K_];
__device__ __half g_eihi[(size_t)B_*V_*K_];
__device__ __half g_hhi [(size_t)N_*H_];
__device__ __half g_Thi [(size_t)B_*K_*H_];

// ---------------- helpers ----------------
__device__ __forceinline__ float siluf(float x){ return x * (1.f/(1.f+__expf(-x))); }
__device__ __forceinline__ float softplusf(float x){ return x > 20.f ? x : log1pf(__expf(x)); }
__device__ __forceinline__ void red_add_v4(float* a, float x, float y, float z, float w){
    asm volatile("red.global.add.v4.f32 [%0], {%1,%2,%3,%4};"
                 :: "l"(a), "f"(x), "f"(y), "f"(z), "f"(w) : "memory");
}
__device__ __forceinline__ void red_add_v2(float* a, float x, float y){
    asm volatile("red.global.add.v2.f32 [%0], {%1,%2};" :: "l"(a), "f"(x), "f"(y) : "memory");
}
__device__ __forceinline__ uint32_t smem_u32(const void* p){
    uint32_t a;
    asm("{ .reg .u64 t; cvta.to.shared.u64 t, %1; cvt.u32.u64 %0, t; }" : "=r"(a) : "l"(p));
    return a;
}
__device__ __forceinline__ void cpasync16(uint32_t s, const void* g){
    asm volatile("cp.async.ca.shared.global [%0], [%1], 16;" :: "r"(s), "l"(g));
}
#define CP_COMMIT() asm volatile("cp.async.commit_group;")
#define CP_WAIT0()  asm volatile("cp.async.wait_group 0;")

__device__ __forceinline__ void ldsm4(uint32_t* r, uint32_t addr){
    asm volatile("ldmatrix.sync.aligned.m8n8.x4.shared.b16 {%0,%1,%2,%3}, [%4];"
        : "=r"(r[0]),"=r"(r[1]),"=r"(r[2]),"=r"(r[3]) : "r"(addr));
}
__device__ __forceinline__ void ldsm4t(uint32_t* r, uint32_t addr){
    asm volatile("ldmatrix.sync.aligned.m8n8.x4.trans.shared.b16 {%0,%1,%2,%3}, [%4];"
        : "=r"(r[0]),"=r"(r[1]),"=r"(r[2]),"=r"(r[3]) : "r"(addr));
}
__device__ __forceinline__ void mma16816(float* d, const uint32_t* a, uint32_t b0, uint32_t b1){
    asm volatile("mma.sync.aligned.m16n8k16.row.col.f32.f16.f16.f32 "
        "{%0,%1,%2,%3}, {%4,%5,%6,%7}, {%8,%9}, {%0,%1,%2,%3};"
        : "+f"(d[0]),"+f"(d[1]),"+f"(d[2]),"+f"(d[3])
        : "r"(a[0]),"r"(a[1]),"r"(a[2]),"r"(a[3]), "r"(b0),"r"(b1));
}

// convert 8 fp32 -> uint4 of packed half2 (hi only)
__device__ __forceinline__ uint4 cvt8h(const float* f){
    unsigned h[4];
    #pragma unroll
    for (int p=0;p<4;p++){
        __half2 hh = __float22half2_rn(make_float2(f[2*p], f[2*p+1]));
        h[p] = *reinterpret_cast<unsigned*>(&hh);
    }
    return make_uint4(h[0],h[1],h[2],h[3]);
}

__global__ void zero_kernel(float* __restrict__ p, size_t n){
    size_t i = (size_t)blockIdx.x*blockDim.x + threadIdx.x;
    if (i < n) p[i] = 0.f;
}
__global__ void zero_stats(){ g_sum[threadIdx.x]=0.f; g_sumsq[threadIdx.x]=0.f; }

// ---------------- prep: convert kernels ----------------
__global__ void split_mat_hi(const float* __restrict__ src, __half* __restrict__ hi, size_t n){
    size_t i = (size_t)blockIdx.x*256 + threadIdx.x;
    if (i < n) hi[i] = __float2half_rn(src[i]);
}
__global__ void split_w1(const float* __restrict__ w1){
    int i = blockIdx.x*256 + threadIdx.x;
    int k = i >> 7, n = i & 127;
    float v = (k < CF_) ? w1[k*128 + n] : 0.f;
    w1s_hi[i] = __float2half_rn(v);
}
__global__ void split_eigs_k(const float* __restrict__ eigs){
    size_t i = (size_t)blockIdx.x*256 + threadIdx.x;
    size_t b = i >> 18, rem = i & 0x3FFFF;
    const float* base = eigs + (b*(size_t)(2*V_+1) + 1)*K_;
    g_evhi[i] = __float2half_rn(base[rem]);
    g_eihi[i] = __float2half_rn(base[(size_t)V_*K_ + rem]);
}

// ================= pipelined HMMA fp16 1-term GEMM =================
// D = Ah*Bh, fp32 accum.
// ASRC 0: A fp32 plain, guarded scalar loads (GEMM1, Kd=47; skips all-zero k16 steps)
// ASRC 1: A fp32, silu(A*scale+shift)
// ASRC 3: A pre-converted fp16
// ASRC 5: dual concat: kc<4 -> (h @ Bhi); kc>=4 -> (evecs[batch] @ B2hi[batch])
// ASRC 6: A fp32 * exp(-eig[row]*t[col])  (coeff-fused T-gemm)
#define APITCH 80
#define BPITCH 272
#define SMBUF  18944   // Ahi 10240 | Bhi 8704
template<int ASRC, bool STATS, bool OUTHALF>
__global__ void __launch_bounds__(256,2) gemm5(
    const float* __restrict__ Af,
    const __half* __restrict__ Ahi, const __half* __restrict__ A2hi,
    const __half* __restrict__ Bhi, const __half* __restrict__ B2hi,
    const float* __restrict__ bias, float* __restrict__ C,
    __half* __restrict__ Chi,
    int Kd, int Nd, int lda,
    size_t sAs, size_t sBs, size_t sC,
    const float* __restrict__ eigsp, const float* __restrict__ ptp, int lidx)
{
    extern __shared__ __align__(16) uint8_t smem[];
    const uint32_t sb = smem_u32(smem);
    const int tid = threadIdx.x;
    const int lane = tid & 31, wid = tid >> 5;
    const int warpm = wid & 3, warpn = wid >> 2;
    const int brow = blockIdx.y * 128;
    const int bcol = blockIdx.x * 128;
    const int bz   = blockIdx.z;
    Ahi += sAs*bz; Bhi += sBs*bz;
    if (ASRC == 6) Af += (size_t)K_*H_*bz;
    if (C)   C   += sC*bz;
    if (Chi) Chi += sC*bz;
    const int bb = brow >> 11;
    const size_t a2base = (size_t)bb*V_*K_ + (size_t)(brow & 2047)*K_;
    const size_t b2base = (size_t)bb*K_*H_;

    const int nch = (Kd + 31) >> 5;

    const int ar = tid >> 1, akh = (tid & 1) * 16;
    const int bkr = tid >> 3, bns = (tid & 7) * 16;

    auto stageB = [&](int kc, int buf){
        const __half* shi; size_t so;
        if (ASRC == 5 && kc >= 4){
            const int gk = (kc & 3)*32 + bkr;
            shi = B2hi + b2base;
            so = (size_t)gk*128 + bns;
        } else {
            const int gk = kc*32 + bkr;
            shi = Bhi;
            so = (size_t)gk*Nd + bcol + bns;
        }
        const uint32_t dst = sb + buf*SMBUF + 10240 + bkr*BPITCH + bns*2;
        cpasync16(dst,      shi + so);
        cpasync16(dst + 16, shi + so + 8);
    };
    auto stageA_async = [&](int kc, int buf){
        const __half* hi; size_t so;
        if (ASRC == 5){
            if (kc < 4){ hi = Ahi; so = (size_t)(brow+ar)*128 + kc*32 + akh; }
            else { hi = A2hi + a2base; so = (size_t)ar*K_ + (kc & 3)*32 + akh; }
        } else {
            hi = Ahi;
            so = (size_t)(brow + ar)*lda + kc*32 + akh;
        }
        const uint32_t dst = sb + buf*SMBUF + ar*APITCH + akh*2;
        cpasync16(dst,      hi + so);
        cpasync16(dst + 16, hi + so + 8);
    };
    auto loadA_f32 = [&](int kc, float* av){
        if (ASRC == 1 || ASRC == 6){
            const float* S = Af + (size_t)(brow+ar)*lda + kc*32 + akh;
            #pragma unroll
            for (int q=0;q<4;q++) *reinterpret_cast<float4*>(&av[q*4]) =
                *reinterpret_cast<const float4*>(S + q*4);
        } else {
            #pragma unroll
            for (int j=0;j<16;j++){
                const int k = kc*32 + akh + j;
                av[j] = (k < Kd) ? Af[(size_t)(brow+ar)*lda + k] : 0.f;
            }
        }
    };
    auto storeA_f32 = [&](int kc, int buf, float* av){
        if (ASRC == 1){
            #pragma unroll
            for (int j=0;j<16;j++){
                const int k = kc*32 + akh + j;
                av[j] = siluf(av[j]*g_scale[k] + g_shift[k]);
            }
        }
        if (ASRC == 6){
            const float eig_a = eigsp[(size_t)bz*(2*V_+1)*K_ + brow + ar];
            #pragma unroll
            for (int j=0;j<16;j++){
                const int k = kc*32 + akh + j;
                av[j] *= __expf(-eig_a * fmaxf(ptp[lidx*H_ + k], 1e-6f));
            }
        }
        uint8_t* base = smem + buf*SMBUF + ar*APITCH + akh*2;
        *reinterpret_cast<uint4*>(base)      = cvt8h(&av[0]);
        *reinterpret_cast<uint4*>(base + 16) = cvt8h(&av[8]);
    };

    constexpr bool A_F32 = (ASRC == 0) || (ASRC == 1) || (ASRC == 6);

    float d[2][8][4];
    #pragma unroll
    for (int i=0;i<2;i++)
        #pragma unroll
        for (int j=0;j<8;j++)
            #pragma unroll
            for (int q=0;q<4;q++) d[i][j][q] = 0.f;

    float av[16];
    stageB(0, 0);
    if (A_F32){ loadA_f32(0, av); storeA_f32(0, 0, av); }
    else       stageA_async(0, 0);
    CP_COMMIT();
    CP_WAIT0();
    __syncthreads();

    for (int kc = 0; kc < nch; kc++){
        const int cur = kc & 1, nxt = cur ^ 1;
        const bool more = (kc + 1 < nch);
        if (more){
            stageB(kc+1, nxt);
            if (!A_F32) stageA_async(kc+1, nxt);
            CP_COMMIT();
            if (A_F32) loadA_f32(kc+1, av);
        }
        const uint32_t aHi = sb + cur*SMBUF;
        const uint32_t bHi = aHi + 10240;
        #pragma unroll
        for (int ks=0; ks<2; ks++){
            // compile-time true for all ASRC != 0 (Kd multiple of 32 there)
            if (ASRC != 0 || kc*32 + ks*16 < Kd){
                uint32_t ah[2][4];
                #pragma unroll
                for (int mb=0; mb<2; mb++){
                    const uint32_t ao = (uint32_t)(warpm*32 + mb*16 + (lane & 15))*APITCH
                                      + ks*32 + ((lane >> 4)*16);
                    ldsm4(ah[mb], aHi + ao);
                }
                #pragma unroll
                for (int np=0; np<4; np++){
                    const int n0 = warpn*64 + np*16;
                    const uint32_t bo = (uint32_t)(ks*16 + (lane & 15))*BPITCH
                                      + (uint32_t)n0*2 + ((lane >> 4)*16);
                    uint32_t bh[4];
                    ldsm4t(bh, bHi + bo);
                    #pragma unroll
                    for (int mb=0; mb<2; mb++){
                        mma16816(d[mb][np*2  ], ah[mb], bh[0], bh[1]);
                        mma16816(d[mb][np*2+1], ah[mb], bh[2], bh[3]);
                    }
                }
            }
        }
        if (more){
            if (A_F32) storeA_f32(kc+1, nxt, av);
            CP_WAIT0();
        }
        __syncthreads();
    }

    #pragma unroll
    for (int mb=0; mb<2; mb++){
        #pragma unroll
        for (int nb=0; nb<8; nb++){
            const int m = brow + warpm*32 + mb*16 + (lane >> 2);
            const int n = bcol + warpn*64 + nb*8 + (lane & 3)*2;
            float b0 = 0.f, b1 = 0.f;
            if (bias){ b0 = bias[n]; b1 = bias[n+1]; }
            d[mb][nb][0] += b0; d[mb][nb][1] += b1;
            d[mb][nb][2] += b0; d[mb][nb][3] += b1;
            if (OUTHALF){
                __half2 h2 = __float22half2_rn(make_float2(d[mb][nb][0], d[mb][nb][1]));
                *reinterpret_cast<__half2*>(Chi + (size_t)m*Nd + n) = h2;
                __half2 h3 = __float22half2_rn(make_float2(d[mb][nb][2], d[mb][nb][3]));
                *reinterpret_cast<__half2*>(Chi + (size_t)(m+8)*Nd + n) = h3;
            } else {
                *reinterpret_cast<float2*>(C + (size_t)m*Nd + n) =
                    make_float2(d[mb][nb][0], d[mb][nb][1]);
                *reinterpret_cast<float2*>(C + (size_t)(m+8)*Nd + n) =
                    make_float2(d[mb][nb][2], d[mb][nb][3]);
            }
        }
    }

    if (STATS){
        float* sred = reinterpret_cast<float*>(smem + 2*SMBUF);
        sred[tid] = 0.f;
        __syncthreads();
        float s[16], q[16];
        #pragma unroll
        for (int i=0;i<16;i++){ s[i]=0.f; q[i]=0.f; }
        #pragma unroll
        for (int mb=0; mb<2; mb++)
            #pragma unroll
            for (int nb=0; nb<8; nb++){
                s[nb*2+0] += d[mb][nb][0] + d[mb][nb][2];
                s[nb*2+1] += d[mb][nb][1] + d[mb][nb][3];
                q[nb*2+0] += d[mb][nb][0]*d[mb][nb][0] + d[mb][nb][2]*d[mb][nb][2];
                q[nb*2+1] += d[mb][nb][1]*d[mb][nb][1] + d[mb][nb][3]*d[mb][nb][3];
            }
        #pragma unroll
        for (int off=4; off<32; off<<=1){
            #pragma unroll
            for (int i=0;i<16;i++){
                s[i] += __shfl_xor_sync(0xFFFFFFFFu, s[i], off);
                q[i] += __shfl_xor_sync(0xFFFFFFFFu, q[i], off);
            }
        }
        if (lane < 4){
            #pragma unroll
            for (int i=0;i<16;i++){
                const int col = warpn*64 + (i>>1)*8 + (lane & 3)*2 + (i & 1);
                atomicAdd(&sred[col], s[i]);
                atomicAdd(&sred[128+col], q[i]);
            }
        }
        __syncthreads();
        if (tid < 128){
            atomicAdd(&g_sum  [bcol + tid], sred[tid]);
            atomicAdd(&g_sumsq[bcol + tid], sred[128 + tid]);
        }
    }
}

// ================= spectral forward (fp16 1-term, 256 blocks, red.add) =================
#define SSMBUF 17408   // Ahi 8704 | Bhi 8704
__global__ void __launch_bounds__(256,2) spec5(float* __restrict__ HS)
{
    extern __shared__ __align__(16) uint8_t smem[];
    const uint32_t sb = smem_u32(smem);
    const int b   = blockIdx.z;
    const int seg = blockIdx.x;
    const __half* Ahi = g_eihi + (size_t)b*V_*K_;
    const __half* Bhi = g_hhi  + (size_t)b*V_*H_;

    const int tid = threadIdx.x;
    const int lane = tid & 31, wid = tid >> 5;
    const int warpm = wid & 3, warpn = wid >> 2;
    const int vr = tid >> 3, cs = (tid & 7) * 16;
    const int v0 = seg * (V_/SPLITV);
    const int nch = V_/SPLITV/32;   // 16

    auto stage = [&](int vc, int buf){
        const int v = v0 + vc*32 + vr;
        const size_t soA = (size_t)v*K_ + cs;
        const size_t soB = (size_t)v*H_ + cs;
        const uint32_t base = sb + buf*SSMBUF + vr*BPITCH + cs*2;
        cpasync16(base,             Ahi + soA);
        cpasync16(base + 16,        Ahi + soA + 8);
        cpasync16(base + 8704,      Bhi + soB);
        cpasync16(base + 8704 + 16, Bhi + soB + 8);
    };

    float d[2][8][4];
    #pragma unroll
    for (int i=0;i<2;i++)
        #pragma unroll
        for (int j=0;j<8;j++)
            #pragma unroll
            for (int q=0;q<4;q++) d[i][j][q] = 0.f;

    stage(0, 0);
    CP_COMMIT();
    CP_WAIT0();
    __syncthreads();

    for (int vc = 0; vc < nch; vc++){
        const int cur = vc & 1, nxt = cur ^ 1;
        const bool more = (vc + 1 < nch);
        if (more){ stage(vc+1, nxt); CP_COMMIT(); }

        const uint32_t aHi = sb + cur*SSMBUF;
        const uint32_t bHi = aHi + 8704;
        #pragma unroll
        for (int ks=0; ks<2; ks++){
            uint32_t ah[2][4];
            #pragma unroll
            for (int mb=0; mb<2; mb++){
                const uint32_t ao = (uint32_t)(ks*16 + (lane & 7) + ((lane >> 4)*8))*BPITCH
                                  + (uint32_t)(warpm*32 + mb*16)*2 + (((lane >> 3) & 1)*16);
                ldsm4t(ah[mb], aHi + ao);
            }
            #pragma unroll
            for (int np=0; np<4; np++){
                const int n0 = warpn*64 + np*16;
                const uint32_t bo = (uint32_t)(ks*16 + (lane & 15))*BPITCH
                                  + (uint32_t)n0*2 + ((lane >> 4)*16);
                uint32_t bh[4];
                ldsm4t(bh, bHi + bo);
                #pragma unroll
                for (int mb=0; mb<2; mb++){
                    mma16816(d[mb][np*2  ], ah[mb], bh[0], bh[1]);
                    mma16816(d[mb][np*2+1], ah[mb], bh[2], bh[3]);
                }
            }
        }
        if (more) CP_WAIT0();
        __syncthreads();
    }

    float* Cb = HS + (size_t)b*K_*H_;
    #pragma unroll
    for (int mb=0; mb<2; mb++)
        #pragma unroll
        for (int nb=0; nb<8; nb++){
            const int m = warpm*32 + mb*16 + (lane >> 2);
            const int n = warpn*64 + nb*8 + (lane & 3)*2;
            red_add_v2(Cb + (size_t)m*H_ + n,     d[mb][nb][0], d[mb][nb][1]);
            red_add_v2(Cb + (size_t)(m+8)*H_ + n, d[mb][nb][2], d[mb][nb][3]);
        }
}

// finalize BN coeffs; zeroes stats for next accumulation
__global__ void finalize_bn(const float* __restrict__ g, const float* __restrict__ be, float Rinv){
    const int c = threadIdx.x;
    const float m   = g_sum[c]*Rinv;
    const float var = g_sumsq[c]*Rinv - m*m;
    const float sc  = g[c] * rsqrtf(var + EPSF);
    g_scale[c] = sc;
    g_shift[c] = be[c] - m*sc;
    g_sum[c] = 0.f;
    g_sumsq[c] = 0.f;
}

// ---------------- message + scatter-add ----------------
__global__ void msg_scatter(const float* __restrict__ Y2, const int* __restrict__ vid,
                            float* __restrict__ Hout)
{
    const int sub = threadIdx.x >> 5;
    const int c4  = (threadIdx.x & 31) * 4;
    const int e0  = blockIdx.x * 32 + sub * 8;
    const float s0=g_scale[c4],   s1=g_scale[c4+1],   s2=g_scale[c4+2],   s3=g_scale[c4+3];
    const float t0=g_shift[c4],   t1=g_shift[c4+1],   t2=g_shift[c4+2],   t3=g_shift[c4+3];
    const float u0=g_scale[128+c4],u1=g_scale[129+c4],u2=g_scale[130+c4],u3=g_scale[131+c4];
    const float w0=g_shift[128+c4],w1=g_shift[129+c4],w2=g_shift[130+c4],w3=g_shift[131+c4];
    #pragma unroll
    for (int i=0;i<8;i++){
        const int e = e0 + i;
        float4 f = *reinterpret_cast<const float4*>(Y2 + (size_t)e*256 + c4);
        float4 c = *reinterpret_cast<const float4*>(Y2 + (size_t)e*256 + 128 + c4);
        float m0 = (1.f/(1.f+__expf(-(f.x*s0+t0)))) * softplusf(c.x*u0+w0);
        float m1 = (1.f/(1.f+__expf(-(f.y*s1+t1)))) * softplusf(c.y*u1+w1);
        float m2 = (1.f/(1.f+__expf(-(f.z*s2+t2)))) * softplusf(c.z*u2+w2);
        float m3 = (1.f/(1.f+__expf(-(f.w*s3+t3)))) * softplusf(c.w*u3+w3);
        const int v = vid[e];
        red_add_v4(Hout + (size_t)v*128 + c4, m0, m1, m2, m3);
    }
}

// h += bn(Y); also emit fp16 H
__global__ void h_update_split(float* __restrict__ H, const float* __restrict__ Y){
    const size_t i = (size_t)blockIdx.x*256 + threadIdx.x;
    const int c = (int)(i & 127);
    const float v = H[i] + Y[i]*g_scale[c] + g_shift[c];
    H[i] = v;
    g_hhi[i] = __float2half_rn(v);
}
__global__ void split_H(const float* __restrict__ H){
    const size_t i = (size_t)blockIdx.x*256 + threadIdx.x;
    g_hhi[i] = __float2half_rn(H[i]);
}

// out[b] += mean_v( silu(bn(Yo)) . wo2 + bo2 )
__global__ void out_reduce(const float* __restrict__ Yo, const float* __restrict__ wo2,
                           const float* __restrict__ bo2, float* __restrict__ out)
{
    const int warp = threadIdx.x >> 5, lane = threadIdx.x & 31;
    const long n = (long)blockIdx.x*8 + warp;
    float s = 0.f;
    #pragma unroll
    for (int j=0;j<4;j++){
        const int h = lane + j*32;
        float x = Yo[(size_t)n*128 + h]*g_scale[h] + g_shift[h];
        x = siluf(x);
        s += x * wo2[h];
    }
    #pragma unroll
    for (int o=16;o>0;o>>=1) s += __shfl_xor_sync(0xFFFFFFFFu, s, o);
    if (lane == 0){
        const int b = (int)(n >> 11);
        atomicAdd(&out[b], (s + bo2[0]) * (1.f/(float)V_));
    }
}

// ---------------- launcher ----------------
extern "C" void kernel_launch(void* const* d_in, const int* in_sizes, int n_in,
                              void* d_out, int out_size)
{
    const float* chem = (const float*)d_in[0];
    const int*   vid  = (const int*  )d_in[1];
    const float* eigs = (const float*)d_in[2];
    const float* w1   = (const float*)d_in[3];
    const float* b1   = (const float*)d_in[4];
    const float* g1   = (const float*)d_in[5];
    const float* be1  = (const float*)d_in[6];
    const float* w2   = (const float*)d_in[7];
    const float* b2   = (const float*)d_in[8];
    const float* g2   = (const float*)d_in[9];
    const float* be2  = (const float*)d_in[10];
    const float* ptim = (const float*)d_in[11];
    const float* pw1  = (const float*)d_in[12];
    const float* pb1  = (const float*)d_in[13];
    const float* pg1  = (const float*)d_in[14];
    const float* pbe1 = (const float*)d_in[15];
    const float* pw2  = (const float*)d_in[16];
    const float* pb2  = (const float*)d_in[17];
    const float* pg2  = (const float*)d_in[18];
    const float* pbe2 = (const float*)d_in[19];
    const float* wo1  = (const float*)d_in[20];
    const float* bo1  = (const float*)d_in[21];
    const float* go1  = (const float*)d_in[22];
    const float* beo1 = (const float*)d_in[23];
    const float* wo2  = (const float*)d_in[24];
    const float* bo2  = (const float*)d_in[25];
    float* outp = (float*)d_out;

    void* p;
    float *pY1,*pY2,*pH,*pHS,*pYa,*pYb;
    __half *pw1hi,*pw2hi,*ppw1hi,*ppw2hi,*pwo1hi;
    __half *pevhi,*phhi,*pThi;
    cudaGetSymbolAddress(&p, g_Y1); pY1=(float*)p;
    cudaGetSymbolAddress(&p, g_Y2); pY2=(float*)p;
    cudaGetSymbolAddress(&p, g_H ); pH =(float*)p;
    cudaGetSymbolAddress(&p, g_HS); pHS=(float*)p;
    cudaGetSymbolAddress(&p, g_Ya); pYa=(float*)p;
    cudaGetSymbolAddress(&p, g_Yb); pYb=(float*)p;
    cudaGetSymbolAddress(&p, w1s_hi); pw1hi=(__half*)p;
    cudaGetSymbolAddress(&p, w2s_hi); pw2hi=(__half*)p;
    cudaGetSymbolAddress(&p, pw1s_hi); ppw1hi=(__half*)p;
    cudaGetSymbolAddress(&p, pw2s_hi); ppw2hi=(__half*)p;
    cudaGetSymbolAddress(&p, wo1s_hi); pwo1hi=(__half*)p;
    cudaGetSymbolAddress(&p, g_evhi); pevhi=(__half*)p;
    cudaGetSymbolAddress(&p, g_hhi ); phhi=(__half*)p;
    cudaGetSymbolAddress(&p, g_Thi ); pThi=(__half*)p;

    const int GSM = 2*SMBUF + 1024;   // 38912
    const int SSM = 2*SSMBUF;         // 34816
    cudaFuncSetAttribute(gemm5<0,true ,false>, cudaFuncAttributeMaxDynamicSharedMemorySize, GSM);
    cudaFuncSetAttribute(gemm5<1,true ,false>, cudaFuncAttributeMaxDynamicSharedMemorySize, GSM);
    cudaFuncSetAttribute(gemm5<6,false,true >, cudaFuncAttributeMaxDynamicSharedMemorySize, GSM);
    cudaFuncSetAttribute(gemm5<5,true ,false>, cudaFuncAttributeMaxDynamicSharedMemorySize, GSM);
    cudaFuncSetAttribute(gemm5<3,true ,false>, cudaFuncAttributeMaxDynamicSharedMemorySize, GSM);
    cudaFuncSetAttribute(spec5, cudaFuncAttributeMaxDynamicSharedMemorySize, SSM);

    zero_kernel<<<1, 64>>>(outp, 64);
    zero_stats<<<1,256>>>();

    // ---- prep ----
    split_w1<<<64*128/256, 256>>>(w1);
    split_mat_hi<<<(128*256+255)/256, 256>>>(w2, pw2hi, 128*256);
    split_mat_hi<<<(3*256*128+255)/256, 256>>>(pw1, ppw1hi, 3*256*128);
    split_mat_hi<<<(3*128*128+255)/256, 256>>>(pw2, ppw2hi, 3*128*128);
    split_mat_hi<<<(128*128+255)/256, 256>>>(wo1, pwo1hi, 128*128);
    split_eigs_k<<<(unsigned)(((size_t)B_*V_*K_)/256), 256>>>(eigs);

    // ---- chem MLP stage 1 (ks-skip) ----
    gemm5<0,true,false><<<dim3(1, E_/128, 1), 256, GSM>>>(
        chem, nullptr, nullptr, pw1hi, nullptr,
        b1, pY1, nullptr, CF_, 128, CF_, 0, 0, 0, nullptr, nullptr, 0);
    finalize_bn<<<1,128>>>(g1, be1, 1.f/(float)E_);

    // ---- stage 2 ----
    gemm5<1,true,false><<<dim3(2, E_/128, 1), 256, GSM>>>(
        pY1, nullptr, nullptr, pw2hi, nullptr,
        b2, pY2, nullptr, 128, 256, 128, 0, 0, 0, nullptr, nullptr, 0);
    finalize_bn<<<1,256>>>(g2, be2, 1.f/(float)E_);

    // ---- message + segment_sum ----
    zero_kernel<<<(unsigned)(((size_t)N_*H_)/256), 256>>>(pH, (size_t)N_*H_);
    msg_scatter<<<E_/32, 128>>>(pY2, vid, pH);
    split_H<<<(unsigned)(((size_t)N_*H_)/256), 256>>>(pH);

    // ---- propagation layers ----
    for (int l = 0; l < L_; l++){
        zero_kernel<<<(B_*K_*H_+255)/256, 256>>>(pHS, (size_t)B_*K_*H_);
        spec5<<<dim3(SPLITV, 1, B_), 256, SSM>>>(pHS);
        // T[b] = (coeff .* HS[b]) @ W1b   (coeff fused into A loader; T fp16 out)
        gemm5<6,false,true><<<dim3(1, 1, B_), 256, GSM>>>(
            pHS, nullptr, nullptr,
            ppw1hi + (size_t)l*256*128 + 128*128, nullptr,
            nullptr, nullptr, pThi,
            128, 128, 128, 0, 0, (size_t)K_*H_, eigs, ptim, l);
        // zMLP1: Ya = h @ W1a + evecs @ T[b] + pb1[l]
        gemm5<5,true,false><<<dim3(1, N_/128, 1), 256, GSM>>>(
            nullptr, phhi, pevhi,
            ppw1hi + (size_t)l*256*128, pThi,
            pb1 + l*H_, pYa, nullptr, 256, 128, 128, 0, 0, 0, nullptr, nullptr, 0);
        finalize_bn<<<1,128>>>(pg1 + l*H_, pbe1 + l*H_, 1.f/(float)N_);
        // zMLP2: Yb = silu(bn(Ya)) @ pw2[l] + pb2[l]
        gemm5<1,true,false><<<dim3(1, N_/128, 1), 256, GSM>>>(
            pYa, nullptr, nullptr,
            ppw2hi + (size_t)l*128*128, nullptr,
            pb2 + l*H_, pYb, nullptr, 128, 128, 128, 0, 0, 0, nullptr, nullptr, 0);
        finalize_bn<<<1,128>>>(pg2 + l*H_, pbe2 + l*H_, 1.f/(float)N_);
        h_update_split<<<(unsigned)(((size_t)N_*H_)/256), 256>>>(pH, pYb);
    }

    // ---- output head ----
    gemm5<3,true,false><<<dim3(1, N_/128, 1), 256, GSM>>>(
        nullptr, phhi, nullptr, pwo1hi, nullptr,
        bo1, pYa, nullptr, 128, 128, 128, 0, 0, 0, nullptr, nullptr, 0);
    finalize_bn<<<1,128>>>(go1, beo1, 1.f/(float)N_);
    out_reduce<<<N_/8, 256>>>(pYa, wo2, bo2, outp);
}

// round 12
// speedup vs baseline: 1.2799x; 1.0301x over previous
#include <cuda_runtime.h>
#include <cuda_fp16.h>
#include <cstdint>

// ---------------- problem constants ----------------
#define B_   64
#define V_   2048
#define K_   128
#define H_   128
#define N_   (B_*V_)
#define E_   1048576
#define CF_  47
#define L_   3
#define EPSF 1e-5f
#define SPLITV 4

// ---------------- scratch ----------------
__device__ __half g_Y1h[(size_t)E_*H_];      // 256 MB
__device__ __half g_Y2h[(size_t)E_*2*H_];    // 512 MB
__device__ float g_H [(size_t)N_*H_];
__device__ float g_HS[(size_t)B_*K_*H_];
__device__ float g_Ya[(size_t)N_*H_];
__device__ float g_Yb[(size_t)N_*H_];
__device__ float g_sum[256], g_sumsq[256], g_scale[256], g_shift[256];
// fp16 operands
__device__ __half w1s_hi[64*128];
__device__ __half w2s_hi[128*256];
__device__ __half pw1s_hi[3*256*128];
__device__ __half pw2s_hi[3*128*128];
__device__ __half wo1s_hi[128*128];
__device__ __half g_evhi[(size_t)B_*V_*K_];
__device__ __half g_eihi[(size_t)B_*V_*K_];
__device__ __half g_hhi [(size_t)N_*H_];
__device__ __half g_Thi [(size_t)B_*K_*H_];

// ---------------- helpers ----------------
__device__ __forceinline__ float siluf(float x){ return x * (1.f/(1.f+__expf(-x))); }
__device__ __forceinline__ float softplusf(float x){ return x > 20.f ? x : log1pf(__expf(x)); }
__device__ __forceinline__ void red_add_v4(float* a, float x, float y, float z, float w){
    asm volatile("red.global.add.v4.f32 [%0], {%1,%2,%3,%4};"
                 :: "l"(a), "f"(x), "f"(y), "f"(z), "f"(w) : "memory");
}
__device__ __forceinline__ void red_add_v2(float* a, float x, float y){
    asm volatile("red.global.add.v2.f32 [%0], {%1,%2};" :: "l"(a), "f"(x), "f"(y) : "memory");
}
__device__ __forceinline__ uint32_t smem_u32(const void* p){
    uint32_t a;
    asm("{ .reg .u64 t; cvta.to.shared.u64 t, %1; cvt.u32.u64 %0, t; }" : "=r"(a) : "l"(p));
    return a;
}
__device__ __forceinline__ void cpasync16(uint32_t s, const void* g){
    asm volatile("cp.async.ca.shared.global [%0], [%1], 16;" :: "r"(s), "l"(g));
}
#define CP_COMMIT() asm volatile("cp.async.commit_group;")
#define CP_WAIT0()  asm volatile("cp.async.wait_group 0;")

__device__ __forceinline__ void ldsm4(uint32_t* r, uint32_t addr){
    asm volatile("ldmatrix.sync.aligned.m8n8.x4.shared.b16 {%0,%1,%2,%3}, [%4];"
        : "=r"(r[0]),"=r"(r[1]),"=r"(r[2]),"=r"(r[3]) : "r"(addr));
}
__device__ __forceinline__ void ldsm4t(uint32_t* r, uint32_t addr){
    asm volatile("ldmatrix.sync.aligned.m8n8.x4.trans.shared.b16 {%0,%1,%2,%3}, [%4];"
        : "=r"(r[0]),"=r"(r[1]),"=r"(r[2]),"=r"(r[3]) : "r"(addr));
}
__device__ __forceinline__ void mma16816(float* d, const uint32_t* a, uint32_t b0, uint32_t b1){
    asm volatile("mma.sync.aligned.m16n8k16.row.col.f32.f16.f16.f32 "
        "{%0,%1,%2,%3}, {%4,%5,%6,%7}, {%8,%9}, {%0,%1,%2,%3};"
        : "+f"(d[0]),"+f"(d[1]),"+f"(d[2]),"+f"(d[3])
        : "r"(a[0]),"r"(a[1]),"r"(a[2]),"r"(a[3]), "r"(b0),"r"(b1));
}

__device__ __forceinline__ uint4 cvt8h(const float* f){
    unsigned h[4];
    #pragma unroll
    for (int p=0;p<4;p++){
        __half2 hh = __float22half2_rn(make_float2(f[2*p], f[2*p+1]));
        h[p] = *reinterpret_cast<unsigned*>(&hh);
    }
    return make_uint4(h[0],h[1],h[2],h[3]);
}
__device__ __forceinline__ void unpack8h(uint4 u, float* f){
    const unsigned v[4] = {u.x, u.y, u.z, u.w};
    #pragma unroll
    for (int p=0;p<4;p++){
        float2 a = __half22float2(*reinterpret_cast<const __half2*>(&v[p]));
        f[2*p] = a.x; f[2*p+1] = a.y;
    }
}

__global__ void zero_kernel(float* __restrict__ p, size_t n){
    size_t i = (size_t)blockIdx.x*blockDim.x + threadIdx.x;
    if (i < n) p[i] = 0.f;
}
__global__ void zero_stats(){ g_sum[threadIdx.x]=0.f; g_sumsq[threadIdx.x]=0.f; }

// ---------------- prep: convert kernels ----------------
__global__ void split_mat_hi(const float* __restrict__ src, __half* __restrict__ hi, size_t n){
    size_t i = (size_t)blockIdx.x*256 + threadIdx.x;
    if (i < n) hi[i] = __float2half_rn(src[i]);
}
__global__ void split_w1(const float* __restrict__ w1){
    int i = blockIdx.x*256 + threadIdx.x;
    int k = i >> 7, n = i & 127;
    float v = (k < CF_) ? w1[k*128 + n] : 0.f;
    w1s_hi[i] = __float2half_rn(v);
}
__global__ void split_eigs_k(const float* __restrict__ eigs){
    size_t i = (size_t)blockIdx.x*256 + threadIdx.x;
    size_t b = i >> 18, rem = i & 0x3FFFF;
    const float* base = eigs + (b*(size_t)(2*V_+1) + 1)*K_;
    g_evhi[i] = __float2half_rn(base[rem]);
    g_eihi[i] = __float2half_rn(base[(size_t)V_*K_ + rem]);
}

// ================= pipelined HMMA fp16 GEMM =================
// D = Ah*Bh, fp32 accum.
// ASRC 0: A fp32 plain, guarded scalar loads (GEMM1, Kd=47; skips all-zero k16 steps)
// ASRC 1: A fp32, silu(A*scale+shift)
// ASRC 2: A fp16 (Ahalf), silu(A*scale+shift) on the fly
// ASRC 3: A pre-converted fp16 (cp.async)
// ASRC 5: dual concat: kc<4 -> (h @ Bhi); kc>=4 -> (evecs[batch] @ B2hi[batch])
// ASRC 6: A fp32 * exp(-eig[row]*t[col])  (coeff-fused T-gemm)
#define APITCH 80
#define BPITCH 272
#define SMBUF  18944   // Ahi 10240 | Bhi 8704
template<int ASRC, bool STATS, bool OUTHALF>
__global__ void __launch_bounds__(256,2) gemm5(
    const float* __restrict__ Af, const __half* __restrict__ Afh,
    const __half* __restrict__ Ahi, const __half* __restrict__ A2hi,
    const __half* __restrict__ Bhi, const __half* __restrict__ B2hi,
    const float* __restrict__ bias, float* __restrict__ C,
    __half* __restrict__ Chi,
    int Kd, int Nd, int lda,
    size_t sAs, size_t sBs, size_t sC,
    const float* __restrict__ eigsp, const float* __restrict__ ptp, int lidx)
{
    extern __shared__ __align__(16) uint8_t smem[];
    const uint32_t sb = smem_u32(smem);
    const int tid = threadIdx.x;
    const int lane = tid & 31, wid = tid >> 5;
    const int warpm = wid & 3, warpn = wid >> 2;
    const int brow = blockIdx.y * 128;
    const int bcol = blockIdx.x * 128;
    const int bz   = blockIdx.z;
    Ahi += sAs*bz; Bhi += sBs*bz;
    if (ASRC == 6) Af += (size_t)K_*H_*bz;
    if (C)   C   += sC*bz;
    if (Chi) Chi += sC*bz;
    const int bb = brow >> 11;
    const size_t a2base = (size_t)bb*V_*K_ + (size_t)(brow & 2047)*K_;
    const size_t b2base = (size_t)bb*K_*H_;

    const int nch = (Kd + 31) >> 5;

    const int ar = tid >> 1, akh = (tid & 1) * 16;
    const int bkr = tid >> 3, bns = (tid & 7) * 16;

    auto stageB = [&](int kc, int buf){
        const __half* shi; size_t so;
        if (ASRC == 5 && kc >= 4){
            const int gk = (kc & 3)*32 + bkr;
            shi = B2hi + b2base;
            so = (size_t)gk*128 + bns;
        } else {
            const int gk = kc*32 + bkr;
            shi = Bhi;
            so = (size_t)gk*Nd + bcol + bns;
        }
        const uint32_t dst = sb + buf*SMBUF + 10240 + bkr*BPITCH + bns*2;
        cpasync16(dst,      shi + so);
        cpasync16(dst + 16, shi + so + 8);
    };
    auto stageA_async = [&](int kc, int buf){
        const __half* hi; size_t so;
        if (ASRC == 5){
            if (kc < 4){ hi = Ahi; so = (size_t)(brow+ar)*128 + kc*32 + akh; }
            else { hi = A2hi + a2base; so = (size_t)ar*K_ + (kc & 3)*32 + akh; }
        } else {
            hi = Ahi;
            so = (size_t)(brow + ar)*lda + kc*32 + akh;
        }
        const uint32_t dst = sb + buf*SMBUF + ar*APITCH + akh*2;
        cpasync16(dst,      hi + so);
        cpasync16(dst + 16, hi + so + 8);
    };
    auto loadA_f32 = [&](int kc, float* av){
        if (ASRC == 2){
            const __half* S = Afh + (size_t)(brow+ar)*lda + kc*32 + akh;
            unpack8h(*reinterpret_cast<const uint4*>(S),     &av[0]);
            unpack8h(*reinterpret_cast<const uint4*>(S + 8), &av[8]);
        } else if (ASRC == 1 || ASRC == 6){
            const float* S = Af + (size_t)(brow+ar)*lda + kc*32 + akh;
            #pragma unroll
            for (int q=0;q<4;q++) *reinterpret_cast<float4*>(&av[q*4]) =
                *reinterpret_cast<const float4*>(S + q*4);
        } else {
            #pragma unroll
            for (int j=0;j<16;j++){
                const int k = kc*32 + akh + j;
                av[j] = (k < Kd) ? Af[(size_t)(brow+ar)*lda + k] : 0.f;
            }
        }
    };
    auto storeA_f32 = [&](int kc, int buf, float* av){
        if (ASRC == 1 || ASRC == 2){
            #pragma unroll
            for (int j=0;j<16;j++){
                const int k = kc*32 + akh + j;
                av[j] = siluf(av[j]*g_scale[k] + g_shift[k]);
            }
        }
        if (ASRC == 6){
            const float eig_a = eigsp[(size_t)bz*(2*V_+1)*K_ + brow + ar];
            #pragma unroll
            for (int j=0;j<16;j++){
                const int k = kc*32 + akh + j;
                av[j] *= __expf(-eig_a * fmaxf(ptp[lidx*H_ + k], 1e-6f));
            }
        }
        uint8_t* base = smem + buf*SMBUF + ar*APITCH + akh*2;
        *reinterpret_cast<uint4*>(base)      = cvt8h(&av[0]);
        *reinterpret_cast<uint4*>(base + 16) = cvt8h(&av[8]);
    };

    constexpr bool A_F32 = (ASRC == 0) || (ASRC == 1) || (ASRC == 2) || (ASRC == 6);

    float d[2][8][4];
    #pragma unroll
    for (int i=0;i<2;i++)
        #pragma unroll
        for (int j=0;j<8;j++)
            #pragma unroll
            for (int q=0;q<4;q++) d[i][j][q] = 0.f;

    float av[16];
    stageB(0, 0);
    if (A_F32){ loadA_f32(0, av); storeA_f32(0, 0, av); }
    else       stageA_async(0, 0);
    CP_COMMIT();
    CP_WAIT0();
    __syncthreads();

    for (int kc = 0; kc < nch; kc++){
        const int cur = kc & 1, nxt = cur ^ 1;
        const bool more = (kc + 1 < nch);
        if (more){
            stageB(kc+1, nxt);
            if (!A_F32) stageA_async(kc+1, nxt);
            CP_COMMIT();
            if (A_F32) loadA_f32(kc+1, av);
        }
        const uint32_t aHi = sb + cur*SMBUF;
        const uint32_t bHi = aHi + 10240;
        #pragma unroll
        for (int ks=0; ks<2; ks++){
            if (ASRC != 0 || kc*32 + ks*16 < Kd){
                uint32_t ah[2][4];
                #pragma unroll
                for (int mb=0; mb<2; mb++){
                    const uint32_t ao = (uint32_t)(warpm*32 + mb*16 + (lane & 15))*APITCH
                                      + ks*32 + ((lane >> 4)*16);
                    ldsm4(ah[mb], aHi + ao);
                }
                #pragma unroll
                for (int np=0; np<4; np++){
                    const int n0 = warpn*64 + np*16;
                    const uint32_t bo = (uint32_t)(ks*16 + (lane & 15))*BPITCH
                                      + (uint32_t)n0*2 + ((lane >> 4)*16);
                    uint32_t bh[4];
                    ldsm4t(bh, bHi + bo);
                    #pragma unroll
                    for (int mb=0; mb<2; mb++){
                        mma16816(d[mb][np*2  ], ah[mb], bh[0], bh[1]);
                        mma16816(d[mb][np*2+1], ah[mb], bh[2], bh[3]);
                    }
                }
            }
        }
        if (more){
            if (A_F32) storeA_f32(kc+1, nxt, av);
            CP_WAIT0();
        }
        __syncthreads();
    }

    #pragma unroll
    for (int mb=0; mb<2; mb++){
        #pragma unroll
        for (int nb=0; nb<8; nb++){
            const int m = brow + warpm*32 + mb*16 + (lane >> 2);
            const int n = bcol + warpn*64 + nb*8 + (lane & 3)*2;
            float b0 = 0.f, b1 = 0.f;
            if (bias){ b0 = bias[n]; b1 = bias[n+1]; }
            d[mb][nb][0] += b0; d[mb][nb][1] += b1;
            d[mb][nb][2] += b0; d[mb][nb][3] += b1;
            if (OUTHALF){
                __half2 h2 = __float22half2_rn(make_float2(d[mb][nb][0], d[mb][nb][1]));
                *reinterpret_cast<__half2*>(Chi + (size_t)m*Nd + n) = h2;
                __half2 h3 = __float22half2_rn(make_float2(d[mb][nb][2], d[mb][nb][3]));
                *reinterpret_cast<__half2*>(Chi + (size_t)(m+8)*Nd + n) = h3;
            } else {
                *reinterpret_cast<float2*>(C + (size_t)m*Nd + n) =
                    make_float2(d[mb][nb][0], d[mb][nb][1]);
                *reinterpret_cast<float2*>(C + (size_t)(m+8)*Nd + n) =
                    make_float2(d[mb][nb][2], d[mb][nb][3]);
            }
        }
    }

    if (STATS){
        float* sred = reinterpret_cast<float*>(smem + 2*SMBUF);
        sred[tid] = 0.f;
        __syncthreads();
        float s[16], q[16];
        #pragma unroll
        for (int i=0;i<16;i++){ s[i]=0.f; q[i]=0.f; }
        #pragma unroll
        for (int mb=0; mb<2; mb++)
            #pragma unroll
            for (int nb=0; nb<8; nb++){
                s[nb*2+0] += d[mb][nb][0] + d[mb][nb][2];
                s[nb*2+1] += d[mb][nb][1] + d[mb][nb][3];
                q[nb*2+0] += d[mb][nb][0]*d[mb][nb][0] + d[mb][nb][2]*d[mb][nb][2];
                q[nb*2+1] += d[mb][nb][1]*d[mb][nb][1] + d[mb][nb][3]*d[mb][nb][3];
            }
        #pragma unroll
        for (int off=4; off<32; off<<=1){
            #pragma unroll
            for (int i=0;i<16;i++){
                s[i] += __shfl_xor_sync(0xFFFFFFFFu, s[i], off);
                q[i] += __shfl_xor_sync(0xFFFFFFFFu, q[i], off);
            }
        }
        if (lane < 4){
            #pragma unroll
            for (int i=0;i<16;i++){
                const int col = warpn*64 + (i>>1)*8 + (lane & 3)*2 + (i & 1);
                atomicAdd(&sred[col], s[i]);
                atomicAdd(&sred[128+col], q[i]);
            }
        }
        __syncthreads();
        if (tid < 128){
            atomicAdd(&g_sum  [bcol + tid], sred[tid]);
            atomicAdd(&g_sumsq[bcol + tid], sred[128 + tid]);
        }
    }
}

// ================= spectral forward (fp16 1-term, 256 blocks, red.add) =================
#define SSMBUF 17408   // Ahi 8704 | Bhi 8704
__global__ void __launch_bounds__(256,2) spec5(float* __restrict__ HS)
{
    extern __shared__ __align__(16) uint8_t smem[];
    const uint32_t sb = smem_u32(smem);
    const int b   = blockIdx.z;
    const int seg = blockIdx.x;
    const __half* Ahi = g_eihi + (size_t)b*V_*K_;
    const __half* Bhi = g_hhi  + (size_t)b*V_*H_;

    const int tid = threadIdx.x;
    const int lane = tid & 31, wid = tid >> 5;
    const int warpm = wid & 3, warpn = wid >> 2;
    const int vr = tid >> 3, cs = (tid & 7) * 16;
    const int v0 = seg * (V_/SPLITV);
    const int nch = V_/SPLITV/32;   // 16

    auto stage = [&](int vc, int buf){
        const int v = v0 + vc*32 + vr;
        const size_t soA = (size_t)v*K_ + cs;
        const size_t soB = (size_t)v*H_ + cs;
        const uint32_t base = sb + buf*SSMBUF + vr*BPITCH + cs*2;
        cpasync16(base,             Ahi + soA);
        cpasync16(base + 16,        Ahi + soA + 8);
        cpasync16(base + 8704,      Bhi + soB);
        cpasync16(base + 8704 + 16, Bhi + soB + 8);
    };

    float d[2][8][4];
    #pragma unroll
    for (int i=0;i<2;i++)
        #pragma unroll
        for (int j=0;j<8;j++)
            #pragma unroll
            for (int q=0;q<4;q++) d[i][j][q] = 0.f;

    stage(0, 0);
    CP_COMMIT();
    CP_WAIT0();
    __syncthreads();

    for (int vc = 0; vc < nch; vc++){
        const int cur = vc & 1, nxt = cur ^ 1;
        const bool more = (vc + 1 < nch);
        if (more){ stage(vc+1, nxt); CP_COMMIT(); }

        const uint32_t aHi = sb + cur*SSMBUF;
        const uint32_t bHi = aHi + 8704;
        #pragma unroll
        for (int ks=0; ks<2; ks++){
            uint32_t ah[2][4];
            #pragma unroll
            for (int mb=0; mb<2; mb++){
                const uint32_t ao = (uint32_t)(ks*16 + (lane & 7) + ((lane >> 4)*8))*BPITCH
                                  + (uint32_t)(warpm*32 + mb*16)*2 + (((lane >> 3) & 1)*16);
                ldsm4t(ah[mb], aHi + ao);
            }
            #pragma unroll
            for (int np=0; np<4; np++){
                const int n0 = warpn*64 + np*16;
                const uint32_t bo = (uint32_t)(ks*16 + (lane & 15))*BPITCH
                                  + (uint32_t)n0*2 + ((lane >> 4)*16);
                uint32_t bh[4];
                ldsm4t(bh, bHi + bo);
                #pragma unroll
                for (int mb=0; mb<2; mb++){
                    mma16816(d[mb][np*2  ], ah[mb], bh[0], bh[1]);
                    mma16816(d[mb][np*2+1], ah[mb], bh[2], bh[3]);
                }
            }
        }
        if (more) CP_WAIT0();
        __syncthreads();
    }

    float* Cb = HS + (size_t)b*K_*H_;
    #pragma unroll
    for (int mb=0; mb<2; mb++)
        #pragma unroll
        for (int nb=0; nb<8; nb++){
            const int m = warpm*32 + mb*16 + (lane >> 2);
            const int n = warpn*64 + nb*8 + (lane & 3)*2;
            red_add_v2(Cb + (size_t)m*H_ + n,     d[mb][nb][0], d[mb][nb][1]);
            red_add_v2(Cb + (size_t)(m+8)*H_ + n, d[mb][nb][2], d[mb][nb][3]);
        }
}

// finalize BN coeffs; zeroes stats for next accumulation
__global__ void finalize_bn(const float* __restrict__ g, const float* __restrict__ be, float Rinv){
    const int c = threadIdx.x;
    const float m   = g_sum[c]*Rinv;
    const float var = g_sumsq[c]*Rinv - m*m;
    const float sc  = g[c] * rsqrtf(var + EPSF);
    g_scale[c] = sc;
    g_shift[c] = be[c] - m*sc;
    g_sum[c] = 0.f;
    g_sumsq[c] = 0.f;
}

// ---------------- message + scatter-add (fp16 Y2) ----------------
__global__ void msg_scatter(const __half* __restrict__ Y2h, const int* __restrict__ vid,
                            float* __restrict__ Hout)
{
    const int sub = threadIdx.x >> 5;
    const int c4  = (threadIdx.x & 31) * 4;
    const int e0  = blockIdx.x * 32 + sub * 8;
    const float s0=g_scale[c4],   s1=g_scale[c4+1],   s2=g_scale[c4+2],   s3=g_scale[c4+3];
    const float t0=g_shift[c4],   t1=g_shift[c4+1],   t2=g_shift[c4+2],   t3=g_shift[c4+3];
    const float u0=g_scale[128+c4],u1=g_scale[129+c4],u2=g_scale[130+c4],u3=g_scale[131+c4];
    const float w0=g_shift[128+c4],w1=g_shift[129+c4],w2=g_shift[130+c4],w3=g_shift[131+c4];
    #pragma unroll
    for (int i=0;i<8;i++){
        const int e = e0 + i;
        uint2 fu = *reinterpret_cast<const uint2*>(Y2h + (size_t)e*256 + c4);
        uint2 cu = *reinterpret_cast<const uint2*>(Y2h + (size_t)e*256 + 128 + c4);
        float2 fa = __half22float2(*reinterpret_cast<const __half2*>(&fu.x));
        float2 fb = __half22float2(*reinterpret_cast<const __half2*>(&fu.y));
        float2 ca = __half22float2(*reinterpret_cast<const __half2*>(&cu.x));
        float2 cb = __half22float2(*reinterpret_cast<const __half2*>(&cu.y));
        float m0 = (1.f/(1.f+__expf(-(fa.x*s0+t0)))) * softplusf(ca.x*u0+w0);
        float m1 = (1.f/(1.f+__expf(-(fa.y*s1+t1)))) * softplusf(ca.y*u1+w1);
        float m2 = (1.f/(1.f+__expf(-(fb.x*s2+t2)))) * softplusf(cb.x*u2+w2);
        float m3 = (1.f/(1.f+__expf(-(fb.y*s3+t3)))) * softplusf(cb.y*u3+w3);
        const int v = vid[e];
        red_add_v4(Hout + (size_t)v*128 + c4, m0, m1, m2, m3);
    }
}

// h += bn(Y); also emit fp16 H
__global__ void h_update_split(float* __restrict__ H, const float* __restrict__ Y){
    const size_t i = (size_t)blockIdx.x*256 + threadIdx.x;
    const int c = (int)(i & 127);
    const float v = H[i] + Y[i]*g_scale[c] + g_shift[c];
    H[i] = v;
    g_hhi[i] = __float2half_rn(v);
}
__global__ void split_H(const float* __restrict__ H){
    const size_t i = (size_t)blockIdx.x*256 + threadIdx.x;
    g_hhi[i] = __float2half_rn(H[i]);
}

// out[b] += mean_v( silu(bn(Yo)) . wo2 + bo2 )
__global__ void out_reduce(const float* __restrict__ Yo, const float* __restrict__ wo2,
                           const float* __restrict__ bo2, float* __restrict__ out)
{
    const int warp = threadIdx.x >> 5, lane = threadIdx.x & 31;
    const long n = (long)blockIdx.x*8 + warp;
    float s = 0.f;
    #pragma unroll
    for (int j=0;j<4;j++){
        const int h = lane + j*32;
        float x = Yo[(size_t)n*128 + h]*g_scale[h] + g_shift[h];
        x = siluf(x);
        s += x * wo2[h];
    }
    #pragma unroll
    for (int o=16;o>0;o>>=1) s += __shfl_xor_sync(0xFFFFFFFFu, s, o);
    if (lane == 0){
        const int b = (int)(n >> 11);
        atomicAdd(&out[b], (s + bo2[0]) * (1.f/(float)V_));
    }
}

// ---------------- launcher ----------------
extern "C" void kernel_launch(void* const* d_in, const int* in_sizes, int n_in,
                              void* d_out, int out_size)
{
    const float* chem = (const float*)d_in[0];
    const int*   vid  = (const int*  )d_in[1];
    const float* eigs = (const float*)d_in[2];
    const float* w1   = (const float*)d_in[3];
    const float* b1   = (const float*)d_in[4];
    const float* g1   = (const float*)d_in[5];
    const float* be1  = (const float*)d_in[6];
    const float* w2   = (const float*)d_in[7];
    const float* b2   = (const float*)d_in[8];
    const float* g2   = (const float*)d_in[9];
    const float* be2  = (const float*)d_in[10];
    const float* ptim = (const float*)d_in[11];
    const float* pw1  = (const float*)d_in[12];
    const float* pb1  = (const float*)d_in[13];
    const float* pg1  = (const float*)d_in[14];
    const float* pbe1 = (const float*)d_in[15];
    const float* pw2  = (const float*)d_in[16];
    const float* pb2  = (const float*)d_in[17];
    const float* pg2  = (const float*)d_in[18];
    const float* pbe2 = (const float*)d_in[19];
    const float* wo1  = (const float*)d_in[20];
    const float* bo1  = (const float*)d_in[21];
    const float* go1  = (const float*)d_in[22];
    const float* beo1 = (const float*)d_in[23];
    const float* wo2  = (const float*)d_in[24];
    const float* bo2  = (const float*)d_in[25];
    float* outp = (float*)d_out;

    void* p;
    float *pH,*pHS,*pYa,*pYb;
    __half *pY1h,*pY2h;
    __half *pw1hi,*pw2hi,*ppw1hi,*ppw2hi,*pwo1hi;
    __half *pevhi,*phhi,*pThi;
    cudaGetSymbolAddress(&p, g_Y1h); pY1h=(__half*)p;
    cudaGetSymbolAddress(&p, g_Y2h); pY2h=(__half*)p;
    cudaGetSymbolAddress(&p, g_H ); pH =(float*)p;
    cudaGetSymbolAddress(&p, g_HS); pHS=(float*)p;
    cudaGetSymbolAddress(&p, g_Ya); pYa=(float*)p;
    cudaGetSymbolAddress(&p, g_Yb); pYb=(float*)p;
    cudaGetSymbolAddress(&p, w1s_hi); pw1hi=(__half*)p;
    cudaGetSymbolAddress(&p, w2s_hi); pw2hi=(__half*)p;
    cudaGetSymbolAddress(&p, pw1s_hi); ppw1hi=(__half*)p;
    cudaGetSymbolAddress(&p, pw2s_hi); ppw2hi=(__half*)p;
    cudaGetSymbolAddress(&p, wo1s_hi); pwo1hi=(__half*)p;
    cudaGetSymbolAddress(&p, g_evhi); pevhi=(__half*)p;
    cudaGetSymbolAddress(&p, g_hhi ); phhi=(__half*)p;
    cudaGetSymbolAddress(&p, g_Thi ); pThi=(__half*)p;

    const int GSM = 2*SMBUF + 1024;   // 38912
    const int SSM = 2*SSMBUF;         // 34816
    cudaFuncSetAttribute(gemm5<0,true ,true >, cudaFuncAttributeMaxDynamicSharedMemorySize, GSM);
    cudaFuncSetAttribute(gemm5<2,true ,true >, cudaFuncAttributeMaxDynamicSharedMemorySize, GSM);
    cudaFuncSetAttribute(gemm5<1,true ,false>, cudaFuncAttributeMaxDynamicSharedMemorySize, GSM);
    cudaFuncSetAttribute(gemm5<6,false,true >, cudaFuncAttributeMaxDynamicSharedMemorySize, GSM);
    cudaFuncSetAttribute(gemm5<5,true ,false>, cudaFuncAttributeMaxDynamicSharedMemorySize, GSM);
    cudaFuncSetAttribute(gemm5<3,true ,false>, cudaFuncAttributeMaxDynamicSharedMemorySize, GSM);
    cudaFuncSetAttribute(spec5, cudaFuncAttributeMaxDynamicSharedMemorySize, SSM);

    zero_kernel<<<1, 64>>>(outp, 64);
    zero_stats<<<1,256>>>();

    // ---- prep ----
    split_w1<<<64*128/256, 256>>>(w1);
    split_mat_hi<<<(128*256+255)/256, 256>>>(w2, pw2hi, 128*256);
    split_mat_hi<<<(3*256*128+255)/256, 256>>>(pw1, ppw1hi, 3*256*128);
    split_mat_hi<<<(3*128*128+255)/256, 256>>>(pw2, ppw2hi, 3*128*128);
    split_mat_hi<<<(128*128+255)/256, 256>>>(wo1, pwo1hi, 128*128);
    split_eigs_k<<<(unsigned)(((size_t)B_*V_*K_)/256), 256>>>(eigs);

    // ---- chem MLP stage 1 (ks-skip, fp16 out) ----
    gemm5<0,true,true><<<dim3(1, E_/128, 1), 256, GSM>>>(
        chem, nullptr, nullptr, nullptr, pw1hi, nullptr,
        b1, nullptr, pY1h, CF_, 128, CF_, 0, 0, 0, nullptr, nullptr, 0);
    finalize_bn<<<1,128>>>(g1, be1, 1.f/(float)E_);

    // ---- stage 2 (fp16 in, silu(bn) fused, fp16 out) ----
    gemm5<2,true,true><<<dim3(2, E_/128, 1), 256, GSM>>>(
        nullptr, pY1h, nullptr, nullptr, pw2hi, nullptr,
        b2, nullptr, pY2h, 128, 256, 128, 0, 0, 0, nullptr, nullptr, 0);
    finalize_bn<<<1,256>>>(g2, be2, 1.f/(float)E_);

    // ---- message + segment_sum ----
    zero_kernel<<<(unsigned)(((size_t)N_*H_)/256), 256>>>(pH, (size_t)N_*H_);
    msg_scatter<<<E_/32, 128>>>(pY2h, vid, pH);
    split_H<<<(unsigned)(((size_t)N_*H_)/256), 256>>>(pH);

    // ---- propagation layers ----
    for (int l = 0; l < L_; l++){
        zero_kernel<<<(B_*K_*H_+255)/256, 256>>>(pHS, (size_t)B_*K_*H_);
        spec5<<<dim3(SPLITV, 1, B_), 256, SSM>>>(pHS);
        // T[b] = (coeff .* HS[b]) @ W1b   (coeff fused; T fp16 out)
        gemm5<6,false,true><<<dim3(1, 1, B_), 256, GSM>>>(
            pHS, nullptr, nullptr, nullptr,
            ppw1hi + (size_t)l*256*128 + 128*128, nullptr,
            nullptr, nullptr, pThi,
            128, 128, 128, 0, 0, (size_t)K_*H_, eigs, ptim, l);
        // zMLP1: Ya = h @ W1a + evecs @ T[b] + pb1[l]
        gemm5<5,true,false><<<dim3(1, N_/128, 1), 256, GSM>>>(
            nullptr, nullptr, phhi, pevhi,
            ppw1hi + (size_t)l*256*128, pThi,
            pb1 + l*H_, pYa, nullptr, 256, 128, 128, 0, 0, 0, nullptr, nullptr, 0);
        finalize_bn<<<1,128>>>(pg1 + l*H_, pbe1 + l*H_, 1.f/(float)N_);
        // zMLP2: Yb = silu(bn(Ya)) @ pw2[l] + pb2[l]
        gemm5<1,true,false><<<dim3(1, N_/128, 1), 256, GSM>>>(
            pYa, nullptr, nullptr, nullptr,
            ppw2hi + (size_t)l*128*128, nullptr,
            pb2 + l*H_, pYb, nullptr, 128, 128, 128, 0, 0, 0, nullptr, nullptr, 0);
        finalize_bn<<<1,128>>>(pg2 + l*H_, pbe2 + l*H_, 1.f/(float)N_);
        h_update_split<<<(unsigned)(((size_t)N_*H_)/256), 256>>>(pH, pYb);
    }

    // ---- output head ----
    gemm5<3,true,false><<<dim3(1, N_/128, 1), 256, GSM>>>(
        nullptr, nullptr, phhi, nullptr, pwo1hi, nullptr,
        bo1, pYa, nullptr, 128, 128, 128, 0, 0, 0, nullptr, nullptr, 0);
    finalize_bn<<<1,128>>>(go1, beo1, 1.f/(float)N_);
    out_reduce<<<N_/8, 256>>>(pYa, wo2, bo2, outp);
}

// round 13
// speedup vs baseline: 1.2873x; 1.0058x over previous
#include <cuda_runtime.h>
#include <cuda_fp16.h>
#include <cstdint>

// ---------------- problem constants ----------------
#define B_   64
#define V_   2048
#define K_   128
#define H_   128
#define N_   (B_*V_)
#define E_   1048576
#define CF_  47
#define L_   3
#define EPSF 1e-5f
#define SPLITV 4

// ---------------- scratch ----------------
__device__ __half g_Y1h[(size_t)E_*H_];      // 256 MB
__device__ __half g_Y2h[(size_t)E_*2*H_];    // 512 MB
__device__ float g_H  [(size_t)N_*H_];
__device__ float g_HSp[(size_t)SPLITV*B_*K_*H_];   // 16 MB partials
__device__ __half g_Yah[(size_t)N_*H_];
__device__ __half g_Ybh[(size_t)N_*H_];
__device__ float g_Yo [(size_t)N_*H_];
__device__ float g_sum[256], g_sumsq[256], g_scale[256], g_shift[256];
// fp16 operands
__device__ __half w1s_hi[64*128];
__device__ __half w2s_hi[128*256];
__device__ __half pw1s_hi[3*256*128];
__device__ __half pw2s_hi[3*128*128];
__device__ __half wo1s_hi[128*128];
__device__ __half g_evhi[(size_t)B_*V_*K_];
__device__ __half g_eihi[(size_t)B_*V_*K_];
__device__ __half g_hhi [(size_t)N_*H_];
__device__ __half g_Thi [(size_t)B_*K_*H_];

// ---------------- helpers ----------------
__device__ __forceinline__ float siluf(float x){ return x * (1.f/(1.f+__expf(-x))); }
__device__ __forceinline__ float softplusf(float x){ return x > 20.f ? x : log1pf(__expf(x)); }
__device__ __forceinline__ void red_add_v4(float* a, float x, float y, float z, float w){
    asm volatile("red.global.add.v4.f32 [%0], {%1,%2,%3,%4};"
                 :: "l"(a), "f"(x), "f"(y), "f"(z), "f"(w) : "memory");
}
__device__ __forceinline__ uint32_t smem_u32(const void* p){
    uint32_t a;
    asm("{ .reg .u64 t; cvta.to.shared.u64 t, %1; cvt.u32.u64 %0, t; }" : "=r"(a) : "l"(p));
    return a;
}
__device__ __forceinline__ void cpasync16(uint32_t s, const void* g){
    asm volatile("cp.async.ca.shared.global [%0], [%1], 16;" :: "r"(s), "l"(g));
}
#define CP_COMMIT() asm volatile("cp.async.commit_group;")
#define CP_WAIT0()  asm volatile("cp.async.wait_group 0;")

__device__ __forceinline__ void ldsm4(uint32_t* r, uint32_t addr){
    asm volatile("ldmatrix.sync.aligned.m8n8.x4.shared.b16 {%0,%1,%2,%3}, [%4];"
        : "=r"(r[0]),"=r"(r[1]),"=r"(r[2]),"=r"(r[3]) : "r"(addr));
}
__device__ __forceinline__ void ldsm4t(uint32_t* r, uint32_t addr){
    asm volatile("ldmatrix.sync.aligned.m8n8.x4.trans.shared.b16 {%0,%1,%2,%3}, [%4];"
        : "=r"(r[0]),"=r"(r[1]),"=r"(r[2]),"=r"(r[3]) : "r"(addr));
}
__device__ __forceinline__ void mma16816(float* d, const uint32_t* a, uint32_t b0, uint32_t b1){
    asm volatile("mma.sync.aligned.m16n8k16.row.col.f32.f16.f16.f32 "
        "{%0,%1,%2,%3}, {%4,%5,%6,%7}, {%8,%9}, {%0,%1,%2,%3};"
        : "+f"(d[0]),"+f"(d[1]),"+f"(d[2]),"+f"(d[3])
        : "r"(a[0]),"r"(a[1]),"r"(a[2]),"r"(a[3]), "r"(b0),"r"(b1));
}

__device__ __forceinline__ uint4 cvt8h(const float* f){
    unsigned h[4];
    #pragma unroll
    for (int p=0;p<4;p++){
        __half2 hh = __float22half2_rn(make_float2(f[2*p], f[2*p+1]));
        h[p] = *reinterpret_cast<unsigned*>(&hh);
    }
    return make_uint4(h[0],h[1],h[2],h[3]);
}
__device__ __forceinline__ void unpack8h(uint4 u, float* f){
    const unsigned v[4] = {u.x, u.y, u.z, u.w};
    #pragma unroll
    for (int p=0;p<4;p++){
        float2 a = __half22float2(*reinterpret_cast<const __half2*>(&v[p]));
        f[2*p] = a.x; f[2*p+1] = a.y;
    }
}

__global__ void zero_kernel(float* __restrict__ p, size_t n){
    size_t i = (size_t)blockIdx.x*blockDim.x + threadIdx.x;
    if (i < n) p[i] = 0.f;
}
__global__ void zero_stats(){ g_sum[threadIdx.x]=0.f; g_sumsq[threadIdx.x]=0.f; }

// ---------------- prep: convert kernels ----------------
__global__ void split_mat_hi(const float* __restrict__ src, __half* __restrict__ hi, size_t n){
    size_t i = (size_t)blockIdx.x*256 + threadIdx.x;
    if (i < n) hi[i] = __float2half_rn(src[i]);
}
__global__ void split_w1(const float* __restrict__ w1){
    int i = blockIdx.x*256 + threadIdx.x;
    int k = i >> 7, n = i & 127;
    float v = (k < CF_) ? w1[k*128 + n] : 0.f;
    w1s_hi[i] = __float2half_rn(v);
}
__global__ void split_eigs_k(const float* __restrict__ eigs){
    size_t i = (size_t)blockIdx.x*256 + threadIdx.x;
    size_t b = i >> 18, rem = i & 0x3FFFF;
    const float* base = eigs + (b*(size_t)(2*V_+1) + 1)*K_;
    g_evhi[i] = __float2half_rn(base[rem]);
    g_eihi[i] = __float2half_rn(base[(size_t)V_*K_ + rem]);
}

// ================= pipelined HMMA fp16 GEMM =================
// D = Ah*Bh, fp32 accum.
// ASRC 0: A fp32 plain, guarded scalar loads (GEMM1, Kd=47; skips all-zero k16 steps)
// ASRC 1: A fp32, silu(A*scale+shift)
// ASRC 2: A fp16 (Afh), silu(A*scale+shift) on the fly
// ASRC 3: A pre-converted fp16 (cp.async)
// ASRC 5: dual concat: kc<4 -> (h @ Bhi); kc>=4 -> (evecs[batch] @ B2hi[batch])
// ASRC 6: A = sum of SPLITV fp32 partials (stride B*K*H) * exp(-eig[row]*t[col])
#define APITCH 80
#define BPITCH 272
#define SMBUF  18944   // Ahi 10240 | Bhi 8704
template<int ASRC, bool STATS, bool OUTHALF>
__global__ void __launch_bounds__(256,2) gemm5(
    const float* __restrict__ Af, const __half* __restrict__ Afh,
    const __half* __restrict__ Ahi, const __half* __restrict__ A2hi,
    const __half* __restrict__ Bhi, const __half* __restrict__ B2hi,
    const float* __restrict__ bias, float* __restrict__ C,
    __half* __restrict__ Chi,
    int Kd, int Nd, int lda,
    size_t sAs, size_t sBs, size_t sC,
    const float* __restrict__ eigsp, const float* __restrict__ ptp, int lidx)
{
    extern __shared__ __align__(16) uint8_t smem[];
    const uint32_t sb = smem_u32(smem);
    const int tid = threadIdx.x;
    const int lane = tid & 31, wid = tid >> 5;
    const int warpm = wid & 3, warpn = wid >> 2;
    const int brow = blockIdx.y * 128;
    const int bcol = blockIdx.x * 128;
    const int bz   = blockIdx.z;
    Ahi += sAs*bz; Bhi += sBs*bz;
    if (ASRC == 6) Af += (size_t)K_*H_*bz;
    if (C)   C   += sC*bz;
    if (Chi) Chi += sC*bz;
    const int bb = brow >> 11;
    const size_t a2base = (size_t)bb*V_*K_ + (size_t)(brow & 2047)*K_;
    const size_t b2base = (size_t)bb*K_*H_;

    const int nch = (Kd + 31) >> 5;

    const int ar = tid >> 1, akh = (tid & 1) * 16;
    const int bkr = tid >> 3, bns = (tid & 7) * 16;

    auto stageB = [&](int kc, int buf){
        const __half* shi; size_t so;
        if (ASRC == 5 && kc >= 4){
            const int gk = (kc & 3)*32 + bkr;
            shi = B2hi + b2base;
            so = (size_t)gk*128 + bns;
        } else {
            const int gk = kc*32 + bkr;
            shi = Bhi;
            so = (size_t)gk*Nd + bcol + bns;
        }
        const uint32_t dst = sb + buf*SMBUF + 10240 + bkr*BPITCH + bns*2;
        cpasync16(dst,      shi + so);
        cpasync16(dst + 16, shi + so + 8);
    };
    auto stageA_async = [&](int kc, int buf){
        const __half* hi; size_t so;
        if (ASRC == 5){
            if (kc < 4){ hi = Ahi; so = (size_t)(brow+ar)*128 + kc*32 + akh; }
            else { hi = A2hi + a2base; so = (size_t)ar*K_ + (kc & 3)*32 + akh; }
        } else {
            hi = Ahi;
            so = (size_t)(brow + ar)*lda + kc*32 + akh;
        }
        const uint32_t dst = sb + buf*SMBUF + ar*APITCH + akh*2;
        cpasync16(dst,      hi + so);
        cpasync16(dst + 16, hi + so + 8);
    };
    auto loadA_f32 = [&](int kc, float* av){
        if (ASRC == 2){
            const __half* S = Afh + (size_t)(brow+ar)*lda + kc*32 + akh;
            unpack8h(*reinterpret_cast<const uint4*>(S),     &av[0]);
            unpack8h(*reinterpret_cast<const uint4*>(S + 8), &av[8]);
        } else if (ASRC == 6){
            const float* S = Af + (size_t)(brow+ar)*lda + kc*32 + akh;
            const size_t P = (size_t)B_*K_*H_;
            #pragma unroll
            for (int q=0;q<4;q++){
                float4 v0 = *reinterpret_cast<const float4*>(S + q*4);
                float4 v1 = *reinterpret_cast<const float4*>(S + P + q*4);
                float4 v2 = *reinterpret_cast<const float4*>(S + 2*P + q*4);
                float4 v3 = *reinterpret_cast<const float4*>(S + 3*P + q*4);
                av[q*4+0] = v0.x + v1.x + v2.x + v3.x;
                av[q*4+1] = v0.y + v1.y + v2.y + v3.y;
                av[q*4+2] = v0.z + v1.z + v2.z + v3.z;
                av[q*4+3] = v0.w + v1.w + v2.w + v3.w;
            }
        } else if (ASRC == 1){
            const float* S = Af + (size_t)(brow+ar)*lda + kc*32 + akh;
            #pragma unroll
            for (int q=0;q<4;q++) *reinterpret_cast<float4*>(&av[q*4]) =
                *reinterpret_cast<const float4*>(S + q*4);
        } else {
            #pragma unroll
            for (int j=0;j<16;j++){
                const int k = kc*32 + akh + j;
                av[j] = (k < Kd) ? Af[(size_t)(brow+ar)*lda + k] : 0.f;
            }
        }
    };
    auto storeA_f32 = [&](int kc, int buf, float* av){
        if (ASRC == 1 || ASRC == 2){
            #pragma unroll
            for (int j=0;j<16;j++){
                const int k = kc*32 + akh + j;
                av[j] = siluf(av[j]*g_scale[k] + g_shift[k]);
            }
        }
        if (ASRC == 6){
            const float eig_a = eigsp[(size_t)bz*(2*V_+1)*K_ + brow + ar];
            #pragma unroll
            for (int j=0;j<16;j++){
                const int k = kc*32 + akh + j;
                av[j] *= __expf(-eig_a * fmaxf(ptp[lidx*H_ + k], 1e-6f));
            }
        }
        uint8_t* base = smem + buf*SMBUF + ar*APITCH + akh*2;
        *reinterpret_cast<uint4*>(base)      = cvt8h(&av[0]);
        *reinterpret_cast<uint4*>(base + 16) = cvt8h(&av[8]);
    };

    constexpr bool A_F32 = (ASRC == 0) || (ASRC == 1) || (ASRC == 2) || (ASRC == 6);

    float d[2][8][4];
    #pragma unroll
    for (int i=0;i<2;i++)
        #pragma unroll
        for (int j=0;j<8;j++)
            #pragma unroll
            for (int q=0;q<4;q++) d[i][j][q] = 0.f;

    float av[16];
    stageB(0, 0);
    if (A_F32){ loadA_f32(0, av); storeA_f32(0, 0, av); }
    else       stageA_async(0, 0);
    CP_COMMIT();
    CP_WAIT0();
    __syncthreads();

    for (int kc = 0; kc < nch; kc++){
        const int cur = kc & 1, nxt = cur ^ 1;
        const bool more = (kc + 1 < nch);
        if (more){
            stageB(kc+1, nxt);
            if (!A_F32) stageA_async(kc+1, nxt);
            CP_COMMIT();
            if (A_F32) loadA_f32(kc+1, av);
        }
        const uint32_t aHi = sb + cur*SMBUF;
        const uint32_t bHi = aHi + 10240;
        #pragma unroll
        for (int ks=0; ks<2; ks++){
            if (ASRC != 0 || kc*32 + ks*16 < Kd){
                uint32_t ah[2][4];
                #pragma unroll
                for (int mb=0; mb<2; mb++){
                    const uint32_t ao = (uint32_t)(warpm*32 + mb*16 + (lane & 15))*APITCH
                                      + ks*32 + ((lane >> 4)*16);
                    ldsm4(ah[mb], aHi + ao);
                }
                #pragma unroll
                for (int np=0; np<4; np++){
                    const int n0 = warpn*64 + np*16;
                    const uint32_t bo = (uint32_t)(ks*16 + (lane & 15))*BPITCH
                                      + (uint32_t)n0*2 + ((lane >> 4)*16);
                    uint32_t bh[4];
                    ldsm4t(bh, bHi + bo);
                    #pragma unroll
                    for (int mb=0; mb<2; mb++){
                        mma16816(d[mb][np*2  ], ah[mb], bh[0], bh[1]);
                        mma16816(d[mb][np*2+1], ah[mb], bh[2], bh[3]);
                    }
                }
            }
        }
        if (more){
            if (A_F32) storeA_f32(kc+1, nxt, av);
            CP_WAIT0();
        }
        __syncthreads();
    }

    #pragma unroll
    for (int mb=0; mb<2; mb++){
        #pragma unroll
        for (int nb=0; nb<8; nb++){
            const int m = brow + warpm*32 + mb*16 + (lane >> 2);
            const int n = bcol + warpn*64 + nb*8 + (lane & 3)*2;
            float b0 = 0.f, b1 = 0.f;
            if (bias){ b0 = bias[n]; b1 = bias[n+1]; }
            d[mb][nb][0] += b0; d[mb][nb][1] += b1;
            d[mb][nb][2] += b0; d[mb][nb][3] += b1;
            if (OUTHALF){
                __half2 h2 = __float22half2_rn(make_float2(d[mb][nb][0], d[mb][nb][1]));
                *reinterpret_cast<__half2*>(Chi + (size_t)m*Nd + n) = h2;
                __half2 h3 = __float22half2_rn(make_float2(d[mb][nb][2], d[mb][nb][3]));
                *reinterpret_cast<__half2*>(Chi + (size_t)(m+8)*Nd + n) = h3;
            } else {
                *reinterpret_cast<float2*>(C + (size_t)m*Nd + n) =
                    make_float2(d[mb][nb][0], d[mb][nb][1]);
                *reinterpret_cast<float2*>(C + (size_t)(m+8)*Nd + n) =
                    make_float2(d[mb][nb][2], d[mb][nb][3]);
            }
        }
    }

    if (STATS){
        float* sred = reinterpret_cast<float*>(smem + 2*SMBUF);
        sred[tid] = 0.f;
        __syncthreads();
        float s[16], q[16];
        #pragma unroll
        for (int i=0;i<16;i++){ s[i]=0.f; q[i]=0.f; }
        #pragma unroll
        for (int mb=0; mb<2; mb++)
            #pragma unroll
            for (int nb=0; nb<8; nb++){
                s[nb*2+0] += d[mb][nb][0] + d[mb][nb][2];
                s[nb*2+1] += d[mb][nb][1] + d[mb][nb][3];
                q[nb*2+0] += d[mb][nb][0]*d[mb][nb][0] + d[mb][nb][2]*d[mb][nb][2];
                q[nb*2+1] += d[mb][nb][1]*d[mb][nb][1] + d[mb][nb][3]*d[mb][nb][3];
            }
        #pragma unroll
        for (int off=4; off<32; off<<=1){
            #pragma unroll
            for (int i=0;i<16;i++){
                s[i] += __shfl_xor_sync(0xFFFFFFFFu, s[i], off);
                q[i] += __shfl_xor_sync(0xFFFFFFFFu, q[i], off);
            }
        }
        if (lane < 4){
            #pragma unroll
            for (int i=0;i<16;i++){
                const int col = warpn*64 + (i>>1)*8 + (lane & 3)*2 + (i & 1);
                atomicAdd(&sred[col], s[i]);
                atomicAdd(&sred[128+col], q[i]);
            }
        }
        __syncthreads();
        if (tid < 128){
            atomicAdd(&g_sum  [bcol + tid], sred[tid]);
            atomicAdd(&g_sumsq[bcol + tid], sred[128 + tid]);
        }
    }
}

// ================= spectral forward (fp16, per-seg partial buffers, plain stores) =================
#define SSMBUF 17408   // Ahi 8704 | Bhi 8704
__global__ void __launch_bounds__(256,2) spec5(float* __restrict__ HSp)
{
    extern __shared__ __align__(16) uint8_t smem[];
    const uint32_t sb = smem_u32(smem);
    const int b   = blockIdx.z;
    const int seg = blockIdx.x;
    const __half* Ahi = g_eihi + (size_t)b*V_*K_;
    const __half* Bhi = g_hhi  + (size_t)b*V_*H_;

    const int tid = threadIdx.x;
    const int lane = tid & 31, wid = tid >> 5;
    const int warpm = wid & 3, warpn = wid >> 2;
    const int vr = tid >> 3, cs = (tid & 7) * 16;
    const int v0 = seg * (V_/SPLITV);
    const int nch = V_/SPLITV/32;   // 16

    auto stage = [&](int vc, int buf){
        const int v = v0 + vc*32 + vr;
        const size_t soA = (size_t)v*K_ + cs;
        const size_t soB = (size_t)v*H_ + cs;
        const uint32_t base = sb + buf*SSMBUF + vr*BPITCH + cs*2;
        cpasync16(base,             Ahi + soA);
        cpasync16(base + 16,        Ahi + soA + 8);
        cpasync16(base + 8704,      Bhi + soB);
        cpasync16(base + 8704 + 16, Bhi + soB + 8);
    };

    float d[2][8][4];
    #pragma unroll
    for (int i=0;i<2;i++)
        #pragma unroll
        for (int j=0;j<8;j++)
            #pragma unroll
            for (int q=0;q<4;q++) d[i][j][q] = 0.f;

    stage(0, 0);
    CP_COMMIT();
    CP_WAIT0();
    __syncthreads();

    for (int vc = 0; vc < nch; vc++){
        const int cur = vc & 1, nxt = cur ^ 1;
        const bool more = (vc + 1 < nch);
        if (more){ stage(vc+1, nxt); CP_COMMIT(); }

        const uint32_t aHi = sb + cur*SSMBUF;
        const uint32_t bHi = aHi + 8704;
        #pragma unroll
        for (int ks=0; ks<2; ks++){
            uint32_t ah[2][4];
            #pragma unroll
            for (int mb=0; mb<2; mb++){
                const uint32_t ao = (uint32_t)(ks*16 + (lane & 7) + ((lane >> 4)*8))*BPITCH
                                  + (uint32_t)(warpm*32 + mb*16)*2 + (((lane >> 3) & 1)*16);
                ldsm4t(ah[mb], aHi + ao);
            }
            #pragma unroll
            for (int np=0; np<4; np++){
                const int n0 = warpn*64 + np*16;
                const uint32_t bo = (uint32_t)(ks*16 + (lane & 15))*BPITCH
                                  + (uint32_t)n0*2 + ((lane >> 4)*16);
                uint32_t bh[4];
                ldsm4t(bh, bHi + bo);
                #pragma unroll
                for (int mb=0; mb<2; mb++){
                    mma16816(d[mb][np*2  ], ah[mb], bh[0], bh[1]);
                    mma16816(d[mb][np*2+1], ah[mb], bh[2], bh[3]);
                }
            }
        }
        if (more) CP_WAIT0();
        __syncthreads();
    }

    float* Cb = HSp + (size_t)seg*B_*K_*H_ + (size_t)b*K_*H_;
    #pragma unroll
    for (int mb=0; mb<2; mb++)
        #pragma unroll
        for (int nb=0; nb<8; nb++){
            const int m = warpm*32 + mb*16 + (lane >> 2);
            const int n = warpn*64 + nb*8 + (lane & 3)*2;
            *reinterpret_cast<float2*>(Cb + (size_t)m*H_ + n) =
                make_float2(d[mb][nb][0], d[mb][nb][1]);
            *reinterpret_cast<float2*>(Cb + (size_t)(m+8)*H_ + n) =
                make_float2(d[mb][nb][2], d[mb][nb][3]);
        }
}

// finalize BN coeffs; zeroes stats for next accumulation
__global__ void finalize_bn(const float* __restrict__ g, const float* __restrict__ be, float Rinv){
    const int c = threadIdx.x;
    const float m   = g_sum[c]*Rinv;
    const float var = g_sumsq[c]*Rinv - m*m;
    const float sc  = g[c] * rsqrtf(var + EPSF);
    g_scale[c] = sc;
    g_shift[c] = be[c] - m*sc;
    g_sum[c] = 0.f;
    g_sumsq[c] = 0.f;
}

// ---------------- message + scatter-add (fp16 Y2) ----------------
__global__ void msg_scatter(const __half* __restrict__ Y2h, const int* __restrict__ vid,
                            float* __restrict__ Hout)
{
    const int sub = threadIdx.x >> 5;
    const int c4  = (threadIdx.x & 31) * 4;
    const int e0  = blockIdx.x * 32 + sub * 8;
    const float s0=g_scale[c4],   s1=g_scale[c4+1],   s2=g_scale[c4+2],   s3=g_scale[c4+3];
    const float t0=g_shift[c4],   t1=g_shift[c4+1],   t2=g_shift[c4+2],   t3=g_shift[c4+3];
    const float u0=g_scale[128+c4],u1=g_scale[129+c4],u2=g_scale[130+c4],u3=g_scale[131+c4];
    const float w0=g_shift[128+c4],w1=g_shift[129+c4],w2=g_shift[130+c4],w3=g_shift[131+c4];
    #pragma unroll
    for (int i=0;i<8;i++){
        const int e = e0 + i;
        uint2 fu = *reinterpret_cast<const uint2*>(Y2h + (size_t)e*256 + c4);
        uint2 cu = *reinterpret_cast<const uint2*>(Y2h + (size_t)e*256 + 128 + c4);
        float2 fa = __half22float2(*reinterpret_cast<const __half2*>(&fu.x));
        float2 fb = __half22float2(*reinterpret_cast<const __half2*>(&fu.y));
        float2 ca = __half22float2(*reinterpret_cast<const __half2*>(&cu.x));
        float2 cb = __half22float2(*reinterpret_cast<const __half2*>(&cu.y));
        float m0 = (1.f/(1.f+__expf(-(fa.x*s0+t0)))) * softplusf(ca.x*u0+w0);
        float m1 = (1.f/(1.f+__expf(-(fa.y*s1+t1)))) * softplusf(ca.y*u1+w1);
        float m2 = (1.f/(1.f+__expf(-(fb.x*s2+t2)))) * softplusf(cb.x*u2+w2);
        float m3 = (1.f/(1.f+__expf(-(fb.y*s3+t3)))) * softplusf(cb.y*u3+w3);
        const int v = vid[e];
        red_add_v4(Hout + (size_t)v*128 + c4, m0, m1, m2, m3);
    }
}

// h += bn(Ybh); also emit fp16 H
__global__ void h_update_split(float* __restrict__ H, const __half* __restrict__ Ybh){
    const size_t i = (size_t)blockIdx.x*256 + threadIdx.x;
    const int c = (int)(i & 127);
    const float v = H[i] + __half2float(Ybh[i])*g_scale[c] + g_shift[c];
    H[i] = v;
    g_hhi[i] = __float2half_rn(v);
}
__global__ void split_H(const float* __restrict__ H){
    const size_t i = (size_t)blockIdx.x*256 + threadIdx.x;
    g_hhi[i] = __float2half_rn(H[i]);
}

// out[b] += mean_v( silu(bn(Yo)) . wo2 + bo2 )
__global__ void out_reduce(const float* __restrict__ Yo, const float* __restrict__ wo2,
                           const float* __restrict__ bo2, float* __restrict__ out)
{
    const int warp = threadIdx.x >> 5, lane = threadIdx.x & 31;
    const long n = (long)blockIdx.x*8 + warp;
    float s = 0.f;
    #pragma unroll
    for (int j=0;j<4;j++){
        const int h = lane + j*32;
        float x = Yo[(size_t)n*128 + h]*g_scale[h] + g_shift[h];
        x = siluf(x);
        s += x * wo2[h];
    }
    #pragma unroll
    for (int o=16;o>0;o>>=1) s += __shfl_xor_sync(0xFFFFFFFFu, s, o);
    if (lane == 0){
        const int b = (int)(n >> 11);
        atomicAdd(&out[b], (s + bo2[0]) * (1.f/(float)V_));
    }
}

// ---------------- launcher ----------------
extern "C" void kernel_launch(void* const* d_in, const int* in_sizes, int n_in,
                              void* d_out, int out_size)
{
    const float* chem = (const float*)d_in[0];
    const int*   vid  = (const int*  )d_in[1];
    const float* eigs = (const float*)d_in[2];
    const float* w1   = (const float*)d_in[3];
    const float* b1   = (const float*)d_in[4];
    const float* g1   = (const float*)d_in[5];
    const float* be1  = (const float*)d_in[6];
    const float* w2   = (const float*)d_in[7];
    const float* b2   = (const float*)d_in[8];
    const float* g2   = (const float*)d_in[9];
    const float* be2  = (const float*)d_in[10];
    const float* ptim = (const float*)d_in[11];
    const float* pw1  = (const float*)d_in[12];
    const float* pb1  = (const float*)d_in[13];
    const float* pg1  = (const float*)d_in[14];
    const float* pbe1 = (const float*)d_in[15];
    const float* pw2  = (const float*)d_in[16];
    const float* pb2  = (const float*)d_in[17];
    const float* pg2  = (const float*)d_in[18];
    const float* pbe2 = (const float*)d_in[19];
    const float* wo1  = (const float*)d_in[20];
    const float* bo1  = (const float*)d_in[21];
    const float* go1  = (const float*)d_in[22];
    const float* beo1 = (const float*)d_in[23];
    const float* wo2  = (const float*)d_in[24];
    const float* bo2  = (const float*)d_in[25];
    float* outp = (float*)d_out;

    void* p;
    float *pH,*pHSp,*pYo;
    __half *pY1h,*pY2h,*pYah,*pYbh;
    __half *pw1hi,*pw2hi,*ppw1hi,*ppw2hi,*pwo1hi;
    __half *pevhi,*phhi,*pThi;
    cudaGetSymbolAddress(&p, g_Y1h); pY1h=(__half*)p;
    cudaGetSymbolAddress(&p, g_Y2h); pY2h=(__half*)p;
    cudaGetSymbolAddress(&p, g_H );  pH  =(float*)p;
    cudaGetSymbolAddress(&p, g_HSp); pHSp=(float*)p;
    cudaGetSymbolAddress(&p, g_Yah); pYah=(__half*)p;
    cudaGetSymbolAddress(&p, g_Ybh); pYbh=(__half*)p;
    cudaGetSymbolAddress(&p, g_Yo);  pYo =(float*)p;
    cudaGetSymbolAddress(&p, w1s_hi); pw1hi=(__half*)p;
    cudaGetSymbolAddress(&p, w2s_hi); pw2hi=(__half*)p;
    cudaGetSymbolAddress(&p, pw1s_hi); ppw1hi=(__half*)p;
    cudaGetSymbolAddress(&p, pw2s_hi); ppw2hi=(__half*)p;
    cudaGetSymbolAddress(&p, wo1s_hi); pwo1hi=(__half*)p;
    cudaGetSymbolAddress(&p, g_evhi); pevhi=(__half*)p;
    cudaGetSymbolAddress(&p, g_hhi ); phhi=(__half*)p;
    cudaGetSymbolAddress(&p, g_Thi ); pThi=(__half*)p;

    const int GSM = 2*SMBUF + 1024;   // 38912
    const int SSM = 2*SSMBUF;         // 34816
    cudaFuncSetAttribute(gemm5<0,true ,true >, cudaFuncAttributeMaxDynamicSharedMemorySize, GSM);
    cudaFuncSetAttribute(gemm5<2,true ,true >, cudaFuncAttributeMaxDynamicSharedMemorySize, GSM);
    cudaFuncSetAttribute(gemm5<6,false,true >, cudaFuncAttributeMaxDynamicSharedMemorySize, GSM);
    cudaFuncSetAttribute(gemm5<5,true ,true >, cudaFuncAttributeMaxDynamicSharedMemorySize, GSM);
    cudaFuncSetAttribute(gemm5<3,true ,false>, cudaFuncAttributeMaxDynamicSharedMemorySize, GSM);
    cudaFuncSetAttribute(spec5, cudaFuncAttributeMaxDynamicSharedMemorySize, SSM);

    zero_kernel<<<1, 64>>>(outp, 64);
    zero_stats<<<1,256>>>();

    // ---- prep ----
    split_w1<<<64*128/256, 256>>>(w1);
    split_mat_hi<<<(128*256+255)/256, 256>>>(w2, pw2hi, 128*256);
    split_mat_hi<<<(3*256*128+255)/256, 256>>>(pw1, ppw1hi, 3*256*128);
    split_mat_hi<<<(3*128*128+255)/256, 256>>>(pw2, ppw2hi, 3*128*128);
    split_mat_hi<<<(128*128+255)/256, 256>>>(wo1, pwo1hi, 128*128);
    split_eigs_k<<<(unsigned)(((size_t)B_*V_*K_)/256), 256>>>(eigs);

    // ---- chem MLP stage 1 (ks-skip, fp16 out) ----
    gemm5<0,true,true><<<dim3(1, E_/128, 1), 256, GSM>>>(
        chem, nullptr, nullptr, nullptr, pw1hi, nullptr,
        b1, nullptr, pY1h, CF_, 128, CF_, 0, 0, 0, nullptr, nullptr, 0);
    finalize_bn<<<1,128>>>(g1, be1, 1.f/(float)E_);

    // ---- stage 2 (fp16 in, silu(bn) fused, fp16 out) ----
    gemm5<2,true,true><<<dim3(2, E_/128, 1), 256, GSM>>>(
        nullptr, pY1h, nullptr, nullptr, pw2hi, nullptr,
        b2, nullptr, pY2h, 128, 256, 128, 0, 0, 0, nullptr, nullptr, 0);
    finalize_bn<<<1,256>>>(g2, be2, 1.f/(float)E_);

    // ---- message + segment_sum ----
    zero_kernel<<<(unsigned)(((size_t)N_*H_)/256), 256>>>(pH, (size_t)N_*H_);
    msg_scatter<<<E_/32, 128>>>(pY2h, vid, pH);
    split_H<<<(unsigned)(((size_t)N_*H_)/256), 256>>>(pH);

    // ---- propagation layers ----
    for (int l = 0; l < L_; l++){
        // HS partials (plain stores, no zero/atomics)
        spec5<<<dim3(SPLITV, 1, B_), 256, SSM>>>(pHSp);
        // T[b] = (coeff .* sum(HSp)) @ W1b   (partials summed + coeff in A loader)
        gemm5<6,false,true><<<dim3(1, 1, B_), 256, GSM>>>(
            pHSp, nullptr, nullptr, nullptr,
            ppw1hi + (size_t)l*256*128 + 128*128, nullptr,
            nullptr, nullptr, pThi,
            128, 128, 128, 0, 0, (size_t)K_*H_, eigs, ptim, l);
        // zMLP1: Ya(h16) = h @ W1a + evecs @ T[b] + pb1[l]
        gemm5<5,true,true><<<dim3(1, N_/128, 1), 256, GSM>>>(
            nullptr, nullptr, phhi, pevhi,
            ppw1hi + (size_t)l*256*128, pThi,
            pb1 + l*H_, nullptr, pYah, 256, 128, 128, 0, 0, 0, nullptr, nullptr, 0);
        finalize_bn<<<1,128>>>(pg1 + l*H_, pbe1 + l*H_, 1.f/(float)N_);
        // zMLP2: Yb(h16) = silu(bn(Ya)) @ pw2[l] + pb2[l]
        gemm5<2,true,true><<<dim3(1, N_/128, 1), 256, GSM>>>(
            nullptr, pYah, nullptr, nullptr,
            ppw2hi + (size_t)l*128*128, nullptr,
            pb2 + l*H_, nullptr, pYbh, 128, 128, 128, 0, 0, 0, nullptr, nullptr, 0);
        finalize_bn<<<1,128>>>(pg2 + l*H_, pbe2 + l*H_, 1.f/(float)N_);
        h_update_split<<<(unsigned)(((size_t)N_*H_)/256), 256>>>(pH, pYbh);
    }

    // ---- output head ----
    gemm5<3,true,false><<<dim3(1, N_/128, 1), 256, GSM>>>(
        nullptr, nullptr, phhi, nullptr, pwo1hi, nullptr,
        bo1, pYo, nullptr, 128, 128, 128, 0, 0, 0, nullptr, nullptr, 0);
    finalize_bn<<<1,128>>>(go1, beo1, 1.f/(float)N_);
    out_reduce<<<N_/8, 256>>>(pYo, wo2, bo2, outp);
}